// round 6
// baseline (speedup 1.0000x reference)
#include <cuda_runtime.h>
#include <cuda_bf16.h>
#include <cstdint>

#define BATCH 8
#define NTOK  16384
#define NK    256
#define SCALE 0.125f

// ---------------- scratch (allocation-free rule) ----------------
__device__ float    g_w3[32 * 8448];
__device__ float    g_k[BATCH * 64 * NK];    // [b][d][p] fp32
__device__ float    g_v[BATCH * NK * 64];    // [b][p][c] fp32
__device__ uint32_t g_mh[BATCH * 8192];      // M bf16-hi pairs: [c][p/2]
__device__ uint32_t g_ml[BATCH * 8192];      // M bf16-lo
__device__ uint32_t g_vh[BATCH * 8192];      // V' bf16-hi pairs: [p][e/2]
__device__ uint32_t g_vl[BATCH * 8192];      // V' bf16-lo

// ---------------- helpers ----------------
__device__ __forceinline__ uint32_t smem_u32(const void* p) {
    uint32_t a;
    asm("{ .reg .u64 t; cvta.to.shared.u64 t, %1; cvt.u32.u64 %0, t; }" : "=r"(a) : "l"(p));
    return a;
}
__device__ __forceinline__ void split_pair(float a, float b, uint32_t& hp, uint32_t& lp) {
    __nv_bfloat16 ah = __float2bfloat16(a);
    __nv_bfloat16 bh = __float2bfloat16(b);
    __nv_bfloat16 al = __float2bfloat16(a - __bfloat162float(ah));
    __nv_bfloat16 bl = __float2bfloat16(b - __bfloat162float(bh));
    hp = ((uint32_t)__bfloat16_as_ushort(bh) << 16) | (uint32_t)__bfloat16_as_ushort(ah);
    lp = ((uint32_t)__bfloat16_as_ushort(bl) << 16) | (uint32_t)__bfloat16_as_ushort(al);
}

#define LDSM4(r, addr) \
    asm volatile("ldmatrix.sync.aligned.m8n8.x4.shared.b16 {%0,%1,%2,%3}, [%4];" \
        : "=r"((r)[0]), "=r"((r)[1]), "=r"((r)[2]), "=r"((r)[3]) : "r"(addr))
#define LDSM4T(r, addr) \
    asm volatile("ldmatrix.sync.aligned.m8n8.x4.trans.shared.b16 {%0,%1,%2,%3}, [%4];" \
        : "=r"((r)[0]), "=r"((r)[1]), "=r"((r)[2]), "=r"((r)[3]) : "r"(addr))
#define MMA_BF16(d, a, b0, b1) \
    asm volatile("mma.sync.aligned.m16n8k16.row.col.f32.bf16.bf16.f32 " \
        "{%0,%1,%2,%3}, {%4,%5,%6,%7}, {%8,%9}, {%0,%1,%2,%3};" \
        : "+f"((d)[0]), "+f"((d)[1]), "+f"((d)[2]), "+f"((d)[3]) \
        : "r"((a)[0]), "r"((a)[1]), "r"((a)[2]), "r"((a)[3]), "r"(b0), "r"(b1))

__device__ __forceinline__ void cp16(uint32_t s, const void* g) {
    asm volatile("cp.async.cg.shared.global [%0], [%1], 16;" :: "r"(s), "l"(g));
}
#define CP_COMMIT() asm volatile("cp.async.commit_group;" ::: "memory")
#define CP_WAIT1()  asm volatile("cp.async.wait_group 1;" ::: "memory")
#define CP_WAIT0()  asm volatile("cp.async.wait_group 0;" ::: "memory")

// ---------------------------------------------------------------------------
// Kernel 0: weight reshuffle for prep (unchanged)
// ---------------------------------------------------------------------------
__global__ void k_transpose_w(const float* __restrict__ srw) {
    int d = blockIdx.x * 512 + threadIdx.x;
    int stage = d / 8448;
    int r = d - stage * 8448;
    int o = r / 132;
    int r2 = r - o * 132;
    float v = 0.f;
    if (r2 < 128) {
        int kw = r2 >> 4, ii = r2 & 15;
        int ic = stage >> 3, kh = stage & 7;
        v = srw[o * 4096 + (ic * 16 + ii) * 64 + kh * 8 + kw];
    }
    g_w3[d] = v;
}

// ---------------------------------------------------------------------------
// Kernel 1: sr-conv + LayerNorm + KV projection. cp.async double-buffered.
// Dyn smem floats: ws[2][8448] @0, xs[2][2048] @16896. 83968 bytes.
// ---------------------------------------------------------------------------
__global__ void __launch_bounds__(512) k_prep(
    const float* __restrict__ x, const float* __restrict__ srb,
    const float* __restrict__ lng, const float* __restrict__ lnb,
    const float* __restrict__ Wkv)
{
    extern __shared__ float dsm[];
    int ph = blockIdx.x, b = blockIdx.y;
    int t = threadIdx.x;
    int o = t & 63, pwg = t >> 6;
    uint32_t sb = smem_u32(dsm);

    // issue async loads for one stage into buffer bi
    auto issue = [&](int stage, int bi) {
        int ic = stage >> 3, kh = stage & 7;
        uint32_t wsdst = sb + bi * 33792;
        const float4* wsrc = (const float4*)g_w3 + stage * 2112;
        for (int i = t; i < 2112; i += 512)
            cp16(wsdst + i * 16, wsrc + i);
        uint32_t xsdst = sb + 67584 + bi * 8192;
        int w = t >> 2, j = t & 3;
        int row = (ph * 8 + kh) * 128 + w;
        cp16(xsdst + t * 16, (const float4*)x + (size_t)(b * NTOK + row) * 16 + ic * 4 + j);
    };

    float a0 = 0.f, a1 = 0.f;
    issue(0, 0);
    CP_COMMIT();
    for (int s = 0; s < 32; s++) {
        if (s + 1 < 32) { issue(s + 1, (s + 1) & 1); CP_COMMIT(); CP_WAIT1(); }
        else CP_WAIT0();
        __syncthreads();
        const float4* wsb  = (const float4*)(dsm + (s & 1) * 8448) + o * 33;
        const float4* xs4s = (const float4*)(dsm + 16896 + (s & 1) * 2048);
        #pragma unroll
        for (int kw = 0; kw < 8; kw++) {
            #pragma unroll
            for (int ii4 = 0; ii4 < 4; ii4++) {
                float4 w  = wsb[kw * 4 + ii4];
                float4 xa = xs4s[(pwg * 8 + kw) * 4 + ii4];
                float4 xb = xs4s[((pwg + 8) * 8 + kw) * 4 + ii4];
                a0 = fmaf(w.x, xa.x, a0); a0 = fmaf(w.y, xa.y, a0);
                a0 = fmaf(w.z, xa.z, a0); a0 = fmaf(w.w, xa.w, a0);
                a1 = fmaf(w.x, xb.x, a1); a1 = fmaf(w.y, xb.y, a1);
                a1 = fmaf(w.z, xb.z, a1); a1 = fmaf(w.w, xb.w, a1);
            }
        }
        __syncthreads();
    }

    float* co = dsm;
    float* ln = dsm + 1024;
    float bo = srb[o];
    co[pwg * 64 + o]       = a0 + bo;
    co[(pwg + 8) * 64 + o] = a1 + bo;
    __syncthreads();

    int warp = t >> 5, lane = t & 31;
    {
        float v0 = co[warp * 64 + lane];
        float v1 = co[warp * 64 + lane + 32];
        float s = v0 + v1, sq = v0 * v0 + v1 * v1;
        #pragma unroll
        for (int off = 16; off; off >>= 1) {
            s  += __shfl_xor_sync(0xffffffffu, s, off);
            sq += __shfl_xor_sync(0xffffffffu, sq, off);
        }
        float mean = s * (1.f / 64.f);
        float var  = sq * (1.f / 64.f) - mean * mean;
        float rs = rsqrtf(var + 1e-5f);
        ln[warp * 64 + lane]      = (v0 - mean) * rs * lng[lane]      + lnb[lane];
        ln[warp * 64 + lane + 32] = (v1 - mean) * rs * lng[lane + 32] + lnb[lane + 32];
    }
    __syncthreads();

    int c = t & 127, pg = t >> 7;
    float acc[4] = {0.f, 0.f, 0.f, 0.f};
    for (int i = 0; i < 64; i++) {
        float wv = Wkv[i * 128 + c];
        #pragma unroll
        for (int m = 0; m < 4; m++)
            acc[m] = fmaf(ln[(pg * 4 + m) * 64 + i], wv, acc[m]);
    }
    #pragma unroll
    for (int m = 0; m < 4; m++) {
        int p = ph * 16 + pg * 4 + m;
        if (c < 64) g_k[(b * 64 + c) * NK + p]        = acc[m];
        else        g_v[(b * NK + p) * 64 + (c - 64)] = acc[m];
    }
}

// ---------------------------------------------------------------------------
// Kernel 1.5: fold projections -> bf16 hi/lo pair-packed operands.
// grid (8 b, 2 z, 4 slices), 512 threads.
// ---------------------------------------------------------------------------
__global__ void __launch_bounds__(512) k_fold(
    const float* __restrict__ Wq, const float* __restrict__ Wp)
{
    extern __shared__ float fs[];
    int b = blockIdx.x, z = blockIdx.y, sl = blockIdx.z;
    int t = threadIdx.x;

    if (z == 0) {
        float* wq = fs;           // [64 c][64 d]
        float* ks = fs + 4096;    // [64 d][256 p]
        for (int i = t; i < 1024; i += 512) ((float4*)wq)[i] = ((const float4*)Wq)[i];
        const float4* gk4 = (const float4*)g_k + b * 4096;
        for (int i = t; i < 4096; i += 512) ((float4*)ks)[i] = gk4[i];
        __syncthreads();
        uint32_t* mh = g_mh + b * 8192;
        uint32_t* ml = g_ml + b * 8192;
        for (int idx = sl * 2048 + t; idx < (sl + 1) * 2048; idx += 512) {
            int c = idx >> 7, pp = idx & 127;
            float m0 = 0.f, m1 = 0.f;
            for (int d = 0; d < 64; d++) {
                float w = wq[c * 64 + d];
                m0 = fmaf(w, ks[d * 256 + 2 * pp],     m0);
                m1 = fmaf(w, ks[d * 256 + 2 * pp + 1], m1);
            }
            m0 *= SCALE; m1 *= SCALE;
            uint32_t hp, lp; split_pair(m0, m1, hp, lp);
            mh[idx] = hp; ml[idx] = lp;
        }
    } else {
        float* wp = fs;           // [64 c][64 e]
        float* vs = fs + 4096;    // [256 p][65]
        for (int i = t; i < 1024; i += 512) ((float4*)wp)[i] = ((const float4*)Wp)[i];
        const float* gv = g_v + b * 16384;
        for (int i = t; i < 16384; i += 512) { int p = i >> 6, c = i & 63; vs[p * 65 + c] = gv[i]; }
        __syncthreads();
        uint32_t* vh = g_vh + b * 8192;
        uint32_t* vl = g_vl + b * 8192;
        for (int idx = sl * 2048 + t; idx < (sl + 1) * 2048; idx += 512) {
            int p = idx >> 5, ee = idx & 31;
            float a0 = 0.f, a1 = 0.f;
            for (int c = 0; c < 64; c++) {
                float v = vs[p * 65 + c];
                a0 = fmaf(v, wp[c * 64 + 2 * ee],     a0);
                a1 = fmaf(v, wp[c * 64 + 2 * ee + 1], a1);
            }
            uint32_t hp, lp; split_pair(a0, a1, hp, lp);
            vh[idx] = hp; vl[idx] = lp;
        }
    }
}

// ---------------------------------------------------------------------------
// Kernel 2: HMMA attention. 128 queries/CTA, grid (128, 8), 1024 threads.
// SMEM byte map identical to R4.
// ---------------------------------------------------------------------------
#define SA1 144
#define SB1 528
#define SE  528
#define SB2 144
#define A1H_ 0
#define A1L_ 18432
#define B1H_ 36864
#define B1L_ 70656
#define EH_  0
#define EL_  67584
#define B2H_ 135168
#define B2L_ 172032
#define PSUM_ 208896
#define SMEM_ASK 210944

__global__ void __launch_bounds__(1024, 1) k_attn_mma(
    const float* __restrict__ x, const float* __restrict__ bp,
    float* __restrict__ out)
{
    extern __shared__ char sm[];
    uint32_t sb = smem_u32(sm);
    int t = threadIdx.x;
    int L = t & 31, w = t >> 5;
    int qt = blockIdx.x, b = blockIdx.y;
    int q0 = qt * 128;

    // ---- copy B1 (M) and B2 (V') hi/lo into padded smem ----
    {
        const uint4* mh = (const uint4*)(g_mh + b * 8192);
        const uint4* ml = (const uint4*)(g_ml + b * 8192);
        const uint4* vh = (const uint4*)(g_vh + b * 8192);
        const uint4* vl = (const uint4*)(g_vl + b * 8192);
        uint4* b1h = (uint4*)(sm + B1H_);
        uint4* b1l = (uint4*)(sm + B1L_);
        uint4* b2h = (uint4*)(sm + B2H_);
        uint4* b2l = (uint4*)(sm + B2L_);
        for (int i = t; i < 2048; i += 1024) {
            int r1 = i >> 5, c1 = i & 31;
            b1h[r1 * 33 + c1] = mh[i];
            b1l[r1 * 33 + c1] = ml[i];
            int r2 = i >> 3, c2 = i & 7;
            b2h[r2 * 9 + c2] = vh[i];
            b2l[r2 * 9 + c2] = vl[i];
        }
    }
    // ---- A1: x tile fp32 -> bf16 hi/lo, rows stride 144B ----
    {
        int q = t >> 3, seg = t & 7;
        const float4* xg = (const float4*)(x + ((size_t)b * NTOK + q0 + q) * 64 + seg * 8);
        uint32_t* ah = (uint32_t*)(sm + A1H_);
        uint32_t* al = (uint32_t*)(sm + A1L_);
        #pragma unroll
        for (int j = 0; j < 2; j++) {
            float4 v = xg[j];
            int wb = q * 36 + seg * 4 + 2 * j;
            uint32_t hp, lp;
            split_pair(v.x, v.y, hp, lp);
            ah[wb] = hp; al[wb] = lp;
            split_pair(v.z, v.w, hp, lp);
            ah[wb + 1] = hp; al[wb + 1] = lp;
        }
    }
    __syncthreads();

    int wr = w >> 2, wc = w & 3;
    int m0 = wr * 16;

    // ================= GEMM1: S[128,256] = x @ M (3-term bf16) =================
    // warp tile 16x64 (8 row-groups x 4 col-groups)
    float acc[8][4];
    #pragma unroll
    for (int j = 0; j < 8; j++)
        #pragma unroll
        for (int k = 0; k < 4; k++) acc[j][k] = 0.f;

    {
        int n0 = wc * 64;
        uint32_t a_lane = (uint32_t)((L & 15) * SA1 + (L >> 4) * 16);
        uint32_t b_lane = (uint32_t)(((L & 7) + 8 * ((L >> 3) & 1)) * SB1 + (L >> 4) * 16);
        const int aoffs[3] = {A1H_, A1L_, A1H_};
        const int boffs[3] = {B1H_, B1H_, B1L_};
        #pragma unroll
        for (int term = 0; term < 3; term++) {
            uint32_t abase = sb + aoffs[term] + m0 * SA1 + a_lane;
            uint32_t bbase = sb + boffs[term] + n0 * 2 + b_lane;
            #pragma unroll
            for (int kc = 0; kc < 4; kc++) {
                uint32_t af[4];
                LDSM4(af, abase + kc * 32);
                uint32_t bf[4][4];
                #pragma unroll
                for (int j = 0; j < 4; j++)
                    LDSM4T(bf[j], bbase + kc * 16 * SB1 + j * 32);
                #pragma unroll
                for (int j = 0; j < 4; j++) {
                    MMA_BF16(acc[2 * j],     af, bf[j][0], bf[j][1]);
                    MMA_BF16(acc[2 * j + 1], af, bf[j][2], bf[j][3]);
                }
            }
        }
    }
    __syncthreads();   // GEMM1 reads done before E overwrites the region

    // ================= exp + row sums + store E (bf16 hi/lo) =================
    {
        int n0 = wc * 64;
        int r0 = m0 + (L >> 2);
        float rs0 = 0.f, rs1 = 0.f;
        #pragma unroll
        for (int j = 0; j < 8; j++) {
            float e0 = __expf(acc[j][0]);
            float e1 = __expf(acc[j][1]);
            float e2 = __expf(acc[j][2]);
            float e3 = __expf(acc[j][3]);
            rs0 += e0 + e1;
            rs1 += e2 + e3;
            int cb = (n0 + j * 8 + 2 * (L & 3)) * 2;
            uint32_t hp, lp;
            split_pair(e0, e1, hp, lp);
            *(uint32_t*)(sm + EH_ + r0 * SE + cb) = hp;
            *(uint32_t*)(sm + EL_ + r0 * SE + cb) = lp;
            split_pair(e2, e3, hp, lp);
            *(uint32_t*)(sm + EH_ + (r0 + 8) * SE + cb) = hp;
            *(uint32_t*)(sm + EL_ + (r0 + 8) * SE + cb) = lp;
        }
        rs0 += __shfl_xor_sync(0xffffffffu, rs0, 1);
        rs0 += __shfl_xor_sync(0xffffffffu, rs0, 2);
        rs1 += __shfl_xor_sync(0xffffffffu, rs1, 1);
        rs1 += __shfl_xor_sync(0xffffffffu, rs1, 2);
        if ((L & 3) == 0) {
            float* ps = (float*)(sm + PSUM_);
            ps[r0 * 4 + wc]       = rs0;
            ps[(r0 + 8) * 4 + wc] = rs1;
        }
    }
    __syncthreads();

    // ================= GEMM2: ctx[128,64] = E @ V' (3-term bf16) ===============
    // warp tile 16x16 (8 row-groups x 4 col-groups)
    float acc2[2][4];
    #pragma unroll
    for (int j = 0; j < 2; j++)
        #pragma unroll
        for (int k = 0; k < 4; k++) acc2[j][k] = 0.f;

    {
        int n2 = wc * 16;
        uint32_t a_lane = (uint32_t)((L & 15) * SE + (L >> 4) * 16);
        uint32_t b_lane = (uint32_t)(((L & 7) + 8 * ((L >> 3) & 1)) * SB2 + (L >> 4) * 16);
        const int aoffs[3] = {EH_, EL_, EH_};
        const int boffs[3] = {B2H_, B2H_, B2L_};
        #pragma unroll
        for (int term = 0; term < 3; term++) {
            uint32_t abase = sb + aoffs[term] + m0 * SE + a_lane;
            uint32_t bbase = sb + boffs[term] + n2 * 2 + b_lane;
            #pragma unroll
            for (int kc = 0; kc < 16; kc++) {
                uint32_t af[4];
                LDSM4(af, abase + kc * 32);
                uint32_t bf[4];
                LDSM4T(bf, bbase + kc * 16 * SB2);
                MMA_BF16(acc2[0], af, bf[0], bf[1]);
                MMA_BF16(acc2[1], af, bf[2], bf[3]);
            }
        }
    }

    // ================= epilogue: /rowsum + bias + store =================
    {
        int n2 = wc * 16;
        const float* ps = (const float*)(sm + PSUM_);
        int r0 = m0 + (L >> 2);
        #pragma unroll
        for (int h = 0; h < 2; h++) {
            int row = r0 + 8 * h;
            float4 p4 = *(const float4*)(ps + row * 4);
            float inv = 1.f / (p4.x + p4.y + p4.z + p4.w);
            float* og = out + ((size_t)(b * NTOK) + q0 + row) * 64;
            #pragma unroll
            for (int jj = 0; jj < 2; jj++) {
                int c = n2 + jj * 8 + 2 * (L & 3);
                float2 bb = *(const float2*)(bp + c);
                float2 o;
                o.x = acc2[jj][2 * h]     * inv + bb.x;
                o.y = acc2[jj][2 * h + 1] * inv + bb.y;
                *(float2*)(og + c) = o;
            }
        }
    }
}

// ---------------------------------------------------------------------------
extern "C" void kernel_launch(void* const* d_in, const int* in_sizes, int n_in,
                              void* d_out, int out_size) {
    const float* x   = (const float*)d_in[0];
    const float* Wq  = (const float*)d_in[1];
    const float* Wkv = (const float*)d_in[2];
    const float* Wp  = (const float*)d_in[3];
    const float* bp  = (const float*)d_in[4];
    const float* srw = (const float*)d_in[5];
    const float* srb = (const float*)d_in[6];
    const float* lng = (const float*)d_in[7];
    const float* lnb = (const float*)d_in[8];
    float* out = (float*)d_out;

    cudaFuncSetAttribute(k_prep, cudaFuncAttributeMaxDynamicSharedMemorySize, 83968);
    cudaFuncSetAttribute(k_fold, cudaFuncAttributeMaxDynamicSharedMemorySize, 82944);
    cudaFuncSetAttribute(k_attn_mma, cudaFuncAttributeMaxDynamicSharedMemorySize, SMEM_ASK);

    k_transpose_w<<<528, 512>>>(srw);
    k_prep<<<dim3(16, 8), 512, 83968>>>(x, srb, lng, lnb, Wkv);
    k_fold<<<dim3(8, 2, 4), 512, 82944>>>(Wq, Wp);
    k_attn_mma<<<dim3(128, 8), 1024, SMEM_ASK>>>(x, bp, out);
}

// round 7
// speedup vs baseline: 2.1519x; 2.1519x over previous
#include <cuda_runtime.h>
#include <cuda_bf16.h>
#include <cstdint>

#define BATCH 8
#define NTOK  16384
#define NK    256
#define SCALE 0.125f

// ---------------- scratch (allocation-free rule) ----------------
__device__ float    g_w3[32 * 8448];
__device__ float    g_k[BATCH * 64 * NK];    // [b][d][p] fp32
__device__ float    g_v[BATCH * NK * 64];    // [b][p][c] fp32
__device__ uint32_t g_mh[BATCH * 8192];      // M bf16-hi pairs: [c][p/2]
__device__ uint32_t g_ml[BATCH * 8192];      // M bf16-lo
__device__ uint32_t g_vh[BATCH * 8192];      // V' bf16-hi pairs: [p][e/2]
__device__ float    g_vsum[BATCH * 64];      // fp32 column sums of V'

// ---------------- helpers ----------------
__device__ __forceinline__ uint32_t smem_u32(const void* p) {
    uint32_t a;
    asm("{ .reg .u64 t; cvta.to.shared.u64 t, %1; cvt.u32.u64 %0, t; }" : "=r"(a) : "l"(p));
    return a;
}
__device__ __forceinline__ void split_pair(float a, float b, uint32_t& hp, uint32_t& lp) {
    __nv_bfloat16 ah = __float2bfloat16(a);
    __nv_bfloat16 bh = __float2bfloat16(b);
    __nv_bfloat16 al = __float2bfloat16(a - __bfloat162float(ah));
    __nv_bfloat16 bl = __float2bfloat16(b - __bfloat162float(bh));
    hp = ((uint32_t)__bfloat16_as_ushort(bh) << 16) | (uint32_t)__bfloat16_as_ushort(ah);
    lp = ((uint32_t)__bfloat16_as_ushort(bl) << 16) | (uint32_t)__bfloat16_as_ushort(al);
}
__device__ __forceinline__ uint32_t pack_bf16(float a, float b) {
    __nv_bfloat16 ah = __float2bfloat16(a);
    __nv_bfloat16 bh = __float2bfloat16(b);
    return ((uint32_t)__bfloat16_as_ushort(bh) << 16) | (uint32_t)__bfloat16_as_ushort(ah);
}

#define LDSM4(r, addr) \
    asm volatile("ldmatrix.sync.aligned.m8n8.x4.shared.b16 {%0,%1,%2,%3}, [%4];" \
        : "=r"((r)[0]), "=r"((r)[1]), "=r"((r)[2]), "=r"((r)[3]) : "r"(addr))
#define LDSM4T(r, addr) \
    asm volatile("ldmatrix.sync.aligned.m8n8.x4.trans.shared.b16 {%0,%1,%2,%3}, [%4];" \
        : "=r"((r)[0]), "=r"((r)[1]), "=r"((r)[2]), "=r"((r)[3]) : "r"(addr))
#define MMA_BF16(d, a, b0, b1) \
    asm volatile("mma.sync.aligned.m16n8k16.row.col.f32.bf16.bf16.f32 " \
        "{%0,%1,%2,%3}, {%4,%5,%6,%7}, {%8,%9}, {%0,%1,%2,%3};" \
        : "+f"((d)[0]), "+f"((d)[1]), "+f"((d)[2]), "+f"((d)[3]) \
        : "r"((a)[0]), "r"((a)[1]), "r"((a)[2]), "r"((a)[3]), "r"(b0), "r"(b1))

__device__ __forceinline__ void cp16(uint32_t s, const void* g) {
    asm volatile("cp.async.cg.shared.global [%0], [%1], 16;" :: "r"(s), "l"(g));
}
#define CP_COMMIT() asm volatile("cp.async.commit_group;" ::: "memory")
#define CP_WAIT1()  asm volatile("cp.async.wait_group 1;" ::: "memory")
#define CP_WAIT0()  asm volatile("cp.async.wait_group 0;" ::: "memory")

// ---------------------------------------------------------------------------
// Kernel 0: weight reshuffle for prep; also zero g_vsum (block 0)
// ---------------------------------------------------------------------------
__global__ void k_transpose_w(const float* __restrict__ srw) {
    int d = blockIdx.x * 512 + threadIdx.x;
    if (d < BATCH * 64) g_vsum[d] = 0.f;
    int stage = d / 8448;
    int r = d - stage * 8448;
    int o = r / 132;
    int r2 = r - o * 132;
    float v = 0.f;
    if (r2 < 128) {
        int kw = r2 >> 4, ii = r2 & 15;
        int ic = stage >> 3, kh = stage & 7;
        v = srw[o * 4096 + (ic * 16 + ii) * 64 + kh * 8 + kw];
    }
    g_w3[d] = v;
}

// ---------------------------------------------------------------------------
// Kernel 1: sr-conv + LayerNorm + KV projection. cp.async double-buffered.
// ---------------------------------------------------------------------------
__global__ void __launch_bounds__(512) k_prep(
    const float* __restrict__ x, const float* __restrict__ srb,
    const float* __restrict__ lng, const float* __restrict__ lnb,
    const float* __restrict__ Wkv)
{
    extern __shared__ float dsm[];
    int ph = blockIdx.x, b = blockIdx.y;
    int t = threadIdx.x;
    int o = t & 63, pwg = t >> 6;
    uint32_t sb = smem_u32(dsm);

    auto issue = [&](int stage, int bi) {
        int ic = stage >> 3, kh = stage & 7;
        uint32_t wsdst = sb + bi * 33792;
        const float4* wsrc = (const float4*)g_w3 + stage * 2112;
        for (int i = t; i < 2112; i += 512)
            cp16(wsdst + i * 16, wsrc + i);
        uint32_t xsdst = sb + 67584 + bi * 8192;
        int w = t >> 2, j = t & 3;
        int row = (ph * 8 + kh) * 128 + w;
        cp16(xsdst + t * 16, (const float4*)x + (size_t)(b * NTOK + row) * 16 + ic * 4 + j);
    };

    float a0 = 0.f, a1 = 0.f;
    issue(0, 0);
    CP_COMMIT();
    for (int s = 0; s < 32; s++) {
        if (s + 1 < 32) { issue(s + 1, (s + 1) & 1); CP_COMMIT(); CP_WAIT1(); }
        else CP_WAIT0();
        __syncthreads();
        const float4* wsb  = (const float4*)(dsm + (s & 1) * 8448) + o * 33;
        const float4* xs4s = (const float4*)(dsm + 16896 + (s & 1) * 2048);
        #pragma unroll
        for (int kw = 0; kw < 8; kw++) {
            #pragma unroll
            for (int ii4 = 0; ii4 < 4; ii4++) {
                float4 w  = wsb[kw * 4 + ii4];
                float4 xa = xs4s[(pwg * 8 + kw) * 4 + ii4];
                float4 xb = xs4s[((pwg + 8) * 8 + kw) * 4 + ii4];
                a0 = fmaf(w.x, xa.x, a0); a0 = fmaf(w.y, xa.y, a0);
                a0 = fmaf(w.z, xa.z, a0); a0 = fmaf(w.w, xa.w, a0);
                a1 = fmaf(w.x, xb.x, a1); a1 = fmaf(w.y, xb.y, a1);
                a1 = fmaf(w.z, xb.z, a1); a1 = fmaf(w.w, xb.w, a1);
            }
        }
        __syncthreads();
    }

    float* co = dsm;
    float* ln = dsm + 1024;
    float bo = srb[o];
    co[pwg * 64 + o]       = a0 + bo;
    co[(pwg + 8) * 64 + o] = a1 + bo;
    __syncthreads();

    int warp = t >> 5, lane = t & 31;
    {
        float v0 = co[warp * 64 + lane];
        float v1 = co[warp * 64 + lane + 32];
        float s = v0 + v1, sq = v0 * v0 + v1 * v1;
        #pragma unroll
        for (int off = 16; off; off >>= 1) {
            s  += __shfl_xor_sync(0xffffffffu, s, off);
            sq += __shfl_xor_sync(0xffffffffu, sq, off);
        }
        float mean = s * (1.f / 64.f);
        float var  = sq * (1.f / 64.f) - mean * mean;
        float rs = rsqrtf(var + 1e-5f);
        ln[warp * 64 + lane]      = (v0 - mean) * rs * lng[lane]      + lnb[lane];
        ln[warp * 64 + lane + 32] = (v1 - mean) * rs * lng[lane + 32] + lnb[lane + 32];
    }
    __syncthreads();

    int c = t & 127, pg = t >> 7;
    float acc[4] = {0.f, 0.f, 0.f, 0.f};
    for (int i = 0; i < 64; i++) {
        float wv = Wkv[i * 128 + c];
        #pragma unroll
        for (int m = 0; m < 4; m++)
            acc[m] = fmaf(ln[(pg * 4 + m) * 64 + i], wv, acc[m]);
    }
    #pragma unroll
    for (int m = 0; m < 4; m++) {
        int p = ph * 16 + pg * 4 + m;
        if (c < 64) g_k[(b * 64 + c) * NK + p]        = acc[m];
        else        g_v[(b * NK + p) * 64 + (c - 64)] = acc[m];
    }
}

// ---------------------------------------------------------------------------
// Kernel 1.5: fold projections -> bf16 operands; V' colsum fp32 atomics.
// grid (8 b, 2 z, 4 slices), 512 threads.
// ---------------------------------------------------------------------------
__global__ void __launch_bounds__(512) k_fold(
    const float* __restrict__ Wq, const float* __restrict__ Wp)
{
    extern __shared__ float fs[];
    int b = blockIdx.x, z = blockIdx.y, sl = blockIdx.z;
    int t = threadIdx.x;

    if (z == 0) {
        float* wq = fs;           // [64 c][64 d]
        float* ks = fs + 4096;    // [64 d][256 p]
        for (int i = t; i < 1024; i += 512) ((float4*)wq)[i] = ((const float4*)Wq)[i];
        const float4* gk4 = (const float4*)g_k + b * 4096;
        for (int i = t; i < 4096; i += 512) ((float4*)ks)[i] = gk4[i];
        __syncthreads();
        uint32_t* mh = g_mh + b * 8192;
        uint32_t* ml = g_ml + b * 8192;
        for (int idx = sl * 2048 + t; idx < (sl + 1) * 2048; idx += 512) {
            int c = idx >> 7, pp = idx & 127;
            float m0 = 0.f, m1 = 0.f;
            for (int d = 0; d < 64; d++) {
                float w = wq[c * 64 + d];
                m0 = fmaf(w, ks[d * 256 + 2 * pp],     m0);
                m1 = fmaf(w, ks[d * 256 + 2 * pp + 1], m1);
            }
            m0 *= SCALE; m1 *= SCALE;
            uint32_t hp, lp; split_pair(m0, m1, hp, lp);
            mh[idx] = hp; ml[idx] = lp;
        }
    } else {
        float* wp = fs;           // [64 c][64 e]
        float* vs = fs + 4096;    // [256 p][65]
        for (int i = t; i < 1024; i += 512) ((float4*)wp)[i] = ((const float4*)Wp)[i];
        const float* gv = g_v + b * 16384;
        for (int i = t; i < 16384; i += 512) { int p = i >> 6, c = i & 63; vs[p * 65 + c] = gv[i]; }
        __syncthreads();
        uint32_t* vh = g_vh + b * 8192;
        for (int idx = sl * 2048 + t; idx < (sl + 1) * 2048; idx += 512) {
            int p = idx >> 5, ee = idx & 31;
            float a0 = 0.f, a1 = 0.f;
            for (int c = 0; c < 64; c++) {
                float v = vs[p * 65 + c];
                a0 = fmaf(v, wp[c * 64 + 2 * ee],     a0);
                a1 = fmaf(v, wp[c * 64 + 2 * ee + 1], a1);
            }
            vh[idx] = pack_bf16(a0, a1);
            atomicAdd(&g_vsum[b * 64 + 2 * ee],     a0);
            atomicAdd(&g_vsum[b * 64 + 2 * ee + 1], a1);
        }
    }
}

// ---------------------------------------------------------------------------
// Kernel 2: HMMA attention with centered-E GEMM2. 512 threads, grid (128, 8).
// SMEM map:
//   phase1: A1h@0(18432) A1l@18432 B1h@36864(33792) B1l@70656(33792)
//   phase2: E(=exp(s)-1, bf16)@0 (128*528=67584)  [aliases A1 + B1h only]
//   B2h@104448 (36864)   PSUM@141312 (2048)  -> total 143360
// ---------------------------------------------------------------------------
#define SA1 144
#define SB1 528
#define SE  528
#define SB2 144
#define A1H_ 0
#define A1L_ 18432
#define B1H_ 36864
#define B1L_ 70656
#define EH_  0
#define B2H_ 104448
#define PSUM_ 141312
#define SMEM_ASK 143360

__global__ void __launch_bounds__(512, 1) k_attn_mma(
    const float* __restrict__ x, const float* __restrict__ bp,
    float* __restrict__ out)
{
    extern __shared__ char sm[];
    uint32_t sb = smem_u32(sm);
    int t = threadIdx.x;
    int L = t & 31, w = t >> 5;
    int qt = blockIdx.x, b = blockIdx.y;
    int q0 = qt * 128;

    // ---- copy B1 (M hi/lo) and B2 (V' hi) into padded smem ----
    {
        const uint4* mh = (const uint4*)(g_mh + b * 8192);
        const uint4* ml = (const uint4*)(g_ml + b * 8192);
        const uint4* vh = (const uint4*)(g_vh + b * 8192);
        uint4* b1h = (uint4*)(sm + B1H_);
        uint4* b1l = (uint4*)(sm + B1L_);
        uint4* b2h = (uint4*)(sm + B2H_);
        for (int i = t; i < 2048; i += 512) {
            int r1 = i >> 5, c1 = i & 31;
            b1h[r1 * 33 + c1] = mh[i];
            b1l[r1 * 33 + c1] = ml[i];
            int r2 = i >> 3, c2 = i & 7;
            b2h[r2 * 9 + c2] = vh[i];
        }
    }
    // ---- A1: x tile fp32 -> bf16 hi/lo, rows stride 144B ----
    {
        int q = t >> 2, seg = t & 3;
        const float4* xg = (const float4*)(x + ((size_t)b * NTOK + q0 + q) * 64 + seg * 16);
        uint32_t* ah = (uint32_t*)(sm + A1H_);
        uint32_t* al = (uint32_t*)(sm + A1L_);
        int wb = q * 36 + seg * 8;
        #pragma unroll
        for (int j = 0; j < 4; j++) {
            float4 v = xg[j];
            uint32_t hp, lp;
            split_pair(v.x, v.y, hp, lp);
            ah[wb + 2 * j] = hp; al[wb + 2 * j] = lp;
            split_pair(v.z, v.w, hp, lp);
            ah[wb + 2 * j + 1] = hp; al[wb + 2 * j + 1] = lp;
        }
    }
    __syncthreads();

    int wr = w >> 2, wc = w & 3;
    int m0 = wr * 32;

    // ================= GEMM1: S[128,256] = x @ M (3-term bf16) =================
    float acc[2][8][4];
    #pragma unroll
    for (int i = 0; i < 2; i++)
        #pragma unroll
        for (int j = 0; j < 8; j++)
            #pragma unroll
            for (int k = 0; k < 4; k++) acc[i][j][k] = 0.f;

    {
        int n0 = wc * 64;
        uint32_t a_lane = (uint32_t)((L & 15) * SA1 + (L >> 4) * 16);
        uint32_t b_lane = (uint32_t)(((L & 7) + 8 * ((L >> 3) & 1)) * SB1 + (L >> 4) * 16);
        const int aoffs[3] = {A1H_, A1L_, A1H_};
        const int boffs[3] = {B1H_, B1H_, B1L_};
        #pragma unroll
        for (int term = 0; term < 3; term++) {
            uint32_t abase = sb + aoffs[term] + m0 * SA1 + a_lane;
            uint32_t bbase = sb + boffs[term] + n0 * 2 + b_lane;
            #pragma unroll
            for (int kc = 0; kc < 4; kc++) {
                uint32_t af[2][4];
                LDSM4(af[0], abase + kc * 32);
                LDSM4(af[1], abase + 16 * SA1 + kc * 32);
                uint32_t bf[4][4];
                #pragma unroll
                for (int j = 0; j < 4; j++)
                    LDSM4T(bf[j], bbase + kc * 16 * SB1 + j * 32);
                #pragma unroll
                for (int i = 0; i < 2; i++)
                    #pragma unroll
                    for (int j = 0; j < 4; j++) {
                        MMA_BF16(acc[i][2 * j],     af[i], bf[j][0], bf[j][1]);
                        MMA_BF16(acc[i][2 * j + 1], af[i], bf[j][2], bf[j][3]);
                    }
            }
        }
    }
    __syncthreads();   // GEMM1 reads done before E overwrites the region

    // ============ exp + row sums + store (E-1) as single bf16 ============
    {
        int n0 = wc * 64;
        float rs[4] = {0.f, 0.f, 0.f, 0.f};
        #pragma unroll
        for (int i = 0; i < 2; i++) {
            int r0 = m0 + i * 16 + (L >> 2);
            #pragma unroll
            for (int j = 0; j < 8; j++) {
                float e0 = __expf(acc[i][j][0]);
                float e1 = __expf(acc[i][j][1]);
                float e2 = __expf(acc[i][j][2]);
                float e3 = __expf(acc[i][j][3]);
                rs[i * 2]     += e0 + e1;
                rs[i * 2 + 1] += e2 + e3;
                int cb = (n0 + j * 8 + 2 * (L & 3)) * 2;
                *(uint32_t*)(sm + EH_ + r0 * SE + cb)       = pack_bf16(e0 - 1.f, e1 - 1.f);
                *(uint32_t*)(sm + EH_ + (r0 + 8) * SE + cb) = pack_bf16(e2 - 1.f, e3 - 1.f);
            }
        }
        #pragma unroll
        for (int k = 0; k < 4; k++) {
            rs[k] += __shfl_xor_sync(0xffffffffu, rs[k], 1);
            rs[k] += __shfl_xor_sync(0xffffffffu, rs[k], 2);
        }
        if ((L & 3) == 0) {
            float* ps = (float*)(sm + PSUM_);
            #pragma unroll
            for (int i = 0; i < 2; i++)
                #pragma unroll
                for (int h = 0; h < 2; h++) {
                    int row = m0 + i * 16 + 8 * h + (L >> 2);
                    ps[row * 4 + wc] = rs[i * 2 + h];
                }
        }
    }
    __syncthreads();

    // ========= GEMM2: D2[128,64] = (E-1) @ V'hi (single term) =========
    float acc2[2][2][4];
    #pragma unroll
    for (int i = 0; i < 2; i++)
        #pragma unroll
        for (int j = 0; j < 2; j++)
            #pragma unroll
            for (int k = 0; k < 4; k++) acc2[i][j][k] = 0.f;

    {
        int n2 = wc * 16;
        uint32_t a_lane = (uint32_t)((L & 15) * SE + (L >> 4) * 16);
        uint32_t b_lane = (uint32_t)(((L & 7) + 8 * ((L >> 3) & 1)) * SB2 + (L >> 4) * 16);
        uint32_t abase = sb + EH_ + m0 * SE + a_lane;
        uint32_t bbase = sb + B2H_ + n2 * 2 + b_lane;
        #pragma unroll
        for (int kc = 0; kc < 16; kc++) {
            uint32_t af[2][4];
            LDSM4(af[0], abase + kc * 32);
            LDSM4(af[1], abase + 16 * SE + kc * 32);
            uint32_t bf[4];
            LDSM4T(bf, bbase + kc * 16 * SB2);
            MMA_BF16(acc2[0][0], af[0], bf[0], bf[1]);
            MMA_BF16(acc2[0][1], af[0], bf[2], bf[3]);
            MMA_BF16(acc2[1][0], af[1], bf[0], bf[1]);
            MMA_BF16(acc2[1][1], af[1], bf[2], bf[3]);
        }
    }

    // ===== epilogue: out = (D2 + Svsum)/rowsum + bias =====
    {
        int n2 = wc * 16;
        const float* ps = (const float*)(sm + PSUM_);
        const float* sv = g_vsum + b * 64;
        #pragma unroll
        for (int i = 0; i < 2; i++)
            #pragma unroll
            for (int h = 0; h < 2; h++) {
                int row = m0 + i * 16 + 8 * h + (L >> 2);
                float4 p4 = *(const float4*)(ps + row * 4);
                float inv = 1.f / (p4.x + p4.y + p4.z + p4.w);
                float* og = out + ((size_t)(b * NTOK) + q0 + row) * 64;
                #pragma unroll
                for (int jj = 0; jj < 2; jj++) {
                    int c = n2 + jj * 8 + 2 * (L & 3);
                    float2 bb = *(const float2*)(bp + c);
                    float2 ss = *(const float2*)(sv + c);
                    float2 o;
                    o.x = (acc2[i][jj][2 * h]     + ss.x) * inv + bb.x;
                    o.y = (acc2[i][jj][2 * h + 1] + ss.y) * inv + bb.y;
                    *(float2*)(og + c) = o;
                }
            }
    }
}

// ---------------------------------------------------------------------------
extern "C" void kernel_launch(void* const* d_in, const int* in_sizes, int n_in,
                              void* d_out, int out_size) {
    const float* x   = (const float*)d_in[0];
    const float* Wq  = (const float*)d_in[1];
    const float* Wkv = (const float*)d_in[2];
    const float* Wp  = (const float*)d_in[3];
    const float* bp  = (const float*)d_in[4];
    const float* srw = (const float*)d_in[5];
    const float* srb = (const float*)d_in[6];
    const float* lng = (const float*)d_in[7];
    const float* lnb = (const float*)d_in[8];
    float* out = (float*)d_out;

    cudaFuncSetAttribute(k_prep, cudaFuncAttributeMaxDynamicSharedMemorySize, 83968);
    cudaFuncSetAttribute(k_fold, cudaFuncAttributeMaxDynamicSharedMemorySize, 82944);
    cudaFuncSetAttribute(k_attn_mma, cudaFuncAttributeMaxDynamicSharedMemorySize, SMEM_ASK);

    k_transpose_w<<<528, 512>>>(srw);
    k_prep<<<dim3(16, 8), 512, 83968>>>(x, srb, lng, lnb, Wkv);
    k_fold<<<dim3(8, 2, 4), 512, 82944>>>(Wq, Wp);
    k_attn_mma<<<dim3(128, 8), 512, SMEM_ASK>>>(x, bp, out);
}

// round 8
// speedup vs baseline: 2.3712x; 1.1019x over previous
#include <cuda_runtime.h>
#include <cuda_bf16.h>
#include <cstdint>

#define BATCH 8
#define NTOK  16384
#define NK    256
#define SCALE 0.125f

// ---------------- scratch (allocation-free rule) ----------------
__device__ float    g_w3[32 * 8448];
__device__ float    g_k[BATCH * 64 * NK];    // [b][d][p] fp32
__device__ float    g_v[BATCH * NK * 64];    // [b][p][c] fp32
__device__ uint32_t g_mh[BATCH * 8192];      // M bf16 pairs: [c][p/2]
__device__ uint32_t g_vh[BATCH * 8192];      // V' bf16 pairs: [p][e/2]
__device__ float    g_vsum[BATCH * 64];      // fp32 column sums of V'

// ---------------- helpers ----------------
__device__ __forceinline__ uint32_t smem_u32(const void* p) {
    uint32_t a;
    asm("{ .reg .u64 t; cvta.to.shared.u64 t, %1; cvt.u32.u64 %0, t; }" : "=r"(a) : "l"(p));
    return a;
}
__device__ __forceinline__ void split_pair(float a, float b, uint32_t& hp, uint32_t& lp) {
    __nv_bfloat16 ah = __float2bfloat16(a);
    __nv_bfloat16 bh = __float2bfloat16(b);
    __nv_bfloat16 al = __float2bfloat16(a - __bfloat162float(ah));
    __nv_bfloat16 bl = __float2bfloat16(b - __bfloat162float(bh));
    hp = ((uint32_t)__bfloat16_as_ushort(bh) << 16) | (uint32_t)__bfloat16_as_ushort(ah);
    lp = ((uint32_t)__bfloat16_as_ushort(bl) << 16) | (uint32_t)__bfloat16_as_ushort(al);
}
__device__ __forceinline__ uint32_t pack_bf16(float a, float b) {
    __nv_bfloat16 ah = __float2bfloat16(a);
    __nv_bfloat16 bh = __float2bfloat16(b);
    return ((uint32_t)__bfloat16_as_ushort(bh) << 16) | (uint32_t)__bfloat16_as_ushort(ah);
}

#define LDSM4(r, addr) \
    asm volatile("ldmatrix.sync.aligned.m8n8.x4.shared.b16 {%0,%1,%2,%3}, [%4];" \
        : "=r"((r)[0]), "=r"((r)[1]), "=r"((r)[2]), "=r"((r)[3]) : "r"(addr))
#define LDSM4T(r, addr) \
    asm volatile("ldmatrix.sync.aligned.m8n8.x4.trans.shared.b16 {%0,%1,%2,%3}, [%4];" \
        : "=r"((r)[0]), "=r"((r)[1]), "=r"((r)[2]), "=r"((r)[3]) : "r"(addr))
#define MMA_BF16(d, a, b0, b1) \
    asm volatile("mma.sync.aligned.m16n8k16.row.col.f32.bf16.bf16.f32 " \
        "{%0,%1,%2,%3}, {%4,%5,%6,%7}, {%8,%9}, {%0,%1,%2,%3};" \
        : "+f"((d)[0]), "+f"((d)[1]), "+f"((d)[2]), "+f"((d)[3]) \
        : "r"((a)[0]), "r"((a)[1]), "r"((a)[2]), "r"((a)[3]), "r"(b0), "r"(b1))

__device__ __forceinline__ void cp16(uint32_t s, const void* g) {
    asm volatile("cp.async.cg.shared.global [%0], [%1], 16;" :: "r"(s), "l"(g));
}
#define CP_COMMIT() asm volatile("cp.async.commit_group;" ::: "memory")
#define CP_WAIT1()  asm volatile("cp.async.wait_group 1;" ::: "memory")
#define CP_WAIT0()  asm volatile("cp.async.wait_group 0;" ::: "memory")

// ---------------------------------------------------------------------------
// Kernel 0: weight reshuffle for prep; also zero g_vsum
// ---------------------------------------------------------------------------
__global__ void k_transpose_w(const float* __restrict__ srw) {
    int d = blockIdx.x * 512 + threadIdx.x;
    if (d < BATCH * 64) g_vsum[d] = 0.f;
    int stage = d / 8448;
    int r = d - stage * 8448;
    int o = r / 132;
    int r2 = r - o * 132;
    float v = 0.f;
    if (r2 < 128) {
        int kw = r2 >> 4, ii = r2 & 15;
        int ic = stage >> 3, kh = stage & 7;
        v = srw[o * 4096 + (ic * 16 + ii) * 64 + kh * 8 + kw];
    }
    g_w3[d] = v;
}

// ---------------------------------------------------------------------------
// Kernel 1: sr-conv + LayerNorm + KV projection. cp.async double-buffered.
// ---------------------------------------------------------------------------
__global__ void __launch_bounds__(512) k_prep(
    const float* __restrict__ x, const float* __restrict__ srb,
    const float* __restrict__ lng, const float* __restrict__ lnb,
    const float* __restrict__ Wkv)
{
    extern __shared__ float dsm[];
    int ph = blockIdx.x, b = blockIdx.y;
    int t = threadIdx.x;
    int o = t & 63, pwg = t >> 6;
    uint32_t sb = smem_u32(dsm);

    auto issue = [&](int stage, int bi) {
        int ic = stage >> 3, kh = stage & 7;
        uint32_t wsdst = sb + bi * 33792;
        const float4* wsrc = (const float4*)g_w3 + stage * 2112;
        for (int i = t; i < 2112; i += 512)
            cp16(wsdst + i * 16, wsrc + i);
        uint32_t xsdst = sb + 67584 + bi * 8192;
        int w = t >> 2, j = t & 3;
        int row = (ph * 8 + kh) * 128 + w;
        cp16(xsdst + t * 16, (const float4*)x + (size_t)(b * NTOK + row) * 16 + ic * 4 + j);
    };

    float a0 = 0.f, a1 = 0.f;
    issue(0, 0);
    CP_COMMIT();
    for (int s = 0; s < 32; s++) {
        if (s + 1 < 32) { issue(s + 1, (s + 1) & 1); CP_COMMIT(); CP_WAIT1(); }
        else CP_WAIT0();
        __syncthreads();
        const float4* wsb  = (const float4*)(dsm + (s & 1) * 8448) + o * 33;
        const float4* xs4s = (const float4*)(dsm + 16896 + (s & 1) * 2048);
        #pragma unroll
        for (int kw = 0; kw < 8; kw++) {
            #pragma unroll
            for (int ii4 = 0; ii4 < 4; ii4++) {
                float4 w  = wsb[kw * 4 + ii4];
                float4 xa = xs4s[(pwg * 8 + kw) * 4 + ii4];
                float4 xb = xs4s[((pwg + 8) * 8 + kw) * 4 + ii4];
                a0 = fmaf(w.x, xa.x, a0); a0 = fmaf(w.y, xa.y, a0);
                a0 = fmaf(w.z, xa.z, a0); a0 = fmaf(w.w, xa.w, a0);
                a1 = fmaf(w.x, xb.x, a1); a1 = fmaf(w.y, xb.y, a1);
                a1 = fmaf(w.z, xb.z, a1); a1 = fmaf(w.w, xb.w, a1);
            }
        }
        __syncthreads();
    }

    float* co = dsm;
    float* ln = dsm + 1024;
    float bo = srb[o];
    co[pwg * 64 + o]       = a0 + bo;
    co[(pwg + 8) * 64 + o] = a1 + bo;
    __syncthreads();

    int warp = t >> 5, lane = t & 31;
    {
        float v0 = co[warp * 64 + lane];
        float v1 = co[warp * 64 + lane + 32];
        float s = v0 + v1, sq = v0 * v0 + v1 * v1;
        #pragma unroll
        for (int off = 16; off; off >>= 1) {
            s  += __shfl_xor_sync(0xffffffffu, s, off);
            sq += __shfl_xor_sync(0xffffffffu, sq, off);
        }
        float mean = s * (1.f / 64.f);
        float var  = sq * (1.f / 64.f) - mean * mean;
        float rs = rsqrtf(var + 1e-5f);
        ln[warp * 64 + lane]      = (v0 - mean) * rs * lng[lane]      + lnb[lane];
        ln[warp * 64 + lane + 32] = (v1 - mean) * rs * lng[lane + 32] + lnb[lane + 32];
    }
    __syncthreads();

    int c = t & 127, pg = t >> 7;
    float acc[4] = {0.f, 0.f, 0.f, 0.f};
    for (int i = 0; i < 64; i++) {
        float wv = Wkv[i * 128 + c];
        #pragma unroll
        for (int m = 0; m < 4; m++)
            acc[m] = fmaf(ln[(pg * 4 + m) * 64 + i], wv, acc[m]);
    }
    #pragma unroll
    for (int m = 0; m < 4; m++) {
        int p = ph * 16 + pg * 4 + m;
        if (c < 64) g_k[(b * 64 + c) * NK + p]        = acc[m];
        else        g_v[(b * NK + p) * 64 + (c - 64)] = acc[m];
    }
}

// ---------------------------------------------------------------------------
// Kernel 1.5: fold projections -> bf16 operands (single bf16 each);
// V' colsum fp32 atomics. grid (8 b, 2 z, 4 slices), 512 threads.
// ---------------------------------------------------------------------------
__global__ void __launch_bounds__(512) k_fold(
    const float* __restrict__ Wq, const float* __restrict__ Wp)
{
    extern __shared__ float fs[];
    int b = blockIdx.x, z = blockIdx.y, sl = blockIdx.z;
    int t = threadIdx.x;

    if (z == 0) {
        float* wq = fs;           // [64 c][64 d]
        float* ks = fs + 4096;    // [64 d][256 p]
        for (int i = t; i < 1024; i += 512) ((float4*)wq)[i] = ((const float4*)Wq)[i];
        const float4* gk4 = (const float4*)g_k + b * 4096;
        for (int i = t; i < 4096; i += 512) ((float4*)ks)[i] = gk4[i];
        __syncthreads();
        uint32_t* mh = g_mh + b * 8192;
        for (int idx = sl * 2048 + t; idx < (sl + 1) * 2048; idx += 512) {
            int c = idx >> 7, pp = idx & 127;
            float m0 = 0.f, m1 = 0.f;
            for (int d = 0; d < 64; d++) {
                float w = wq[c * 64 + d];
                m0 = fmaf(w, ks[d * 256 + 2 * pp],     m0);
                m1 = fmaf(w, ks[d * 256 + 2 * pp + 1], m1);
            }
            mh[idx] = pack_bf16(m0 * SCALE, m1 * SCALE);
        }
    } else {
        float* wp = fs;           // [64 c][64 e]
        float* vs = fs + 4096;    // [256 p][65]
        for (int i = t; i < 1024; i += 512) ((float4*)wp)[i] = ((const float4*)Wp)[i];
        const float* gv = g_v + b * 16384;
        for (int i = t; i < 16384; i += 512) { int p = i >> 6, c = i & 63; vs[p * 65 + c] = gv[i]; }
        __syncthreads();
        uint32_t* vh = g_vh + b * 8192;
        for (int idx = sl * 2048 + t; idx < (sl + 1) * 2048; idx += 512) {
            int p = idx >> 5, ee = idx & 31;
            float a0 = 0.f, a1 = 0.f;
            for (int c = 0; c < 64; c++) {
                float v = vs[p * 65 + c];
                a0 = fmaf(v, wp[c * 64 + 2 * ee],     a0);
                a1 = fmaf(v, wp[c * 64 + 2 * ee + 1], a1);
            }
            vh[idx] = pack_bf16(a0, a1);
            atomicAdd(&g_vsum[b * 64 + 2 * ee],     a0);
            atomicAdd(&g_vsum[b * 64 + 2 * ee + 1], a1);
        }
    }
}

// ---------------------------------------------------------------------------
// Kernel 2: HMMA attention, 2-term GEMM1 + centered 1-term GEMM2.
// 512 threads, grid (128, 8). SMEM map (no aliasing):
//   A1h@0(18432,144) A1l@18432(18432,144) B1h@36864(33792,528)
//   E@70656(67584,528) B2h@138240(36864,144) PSUM@175104(2048)
// ---------------------------------------------------------------------------
#define SA1 144
#define SB1 528
#define SE  528
#define SB2 144
#define A1H_ 0
#define A1L_ 18432
#define B1H_ 36864
#define E_   70656
#define B2H_ 138240
#define PSUM_ 175104
#define SMEM_ASK 177152

__global__ void __launch_bounds__(512, 1) k_attn_mma(
    const float* __restrict__ x, const float* __restrict__ bp,
    float* __restrict__ out)
{
    extern __shared__ char sm[];
    uint32_t sb = smem_u32(sm);
    int t = threadIdx.x;
    int L = t & 31, w = t >> 5;
    int qt = blockIdx.x, b = blockIdx.y;
    int q0 = qt * 128;

    // ---- async copy B1h (group 0) then B2h (group 1) ----
    {
        const char* mh = (const char*)(g_mh + b * 8192);
        for (int i = t; i < 2048; i += 512) {
            int r1 = i >> 5, c1 = i & 31;
            cp16(sb + B1H_ + r1 * SB1 + c1 * 16, mh + i * 16);
        }
        CP_COMMIT();
        const char* vh = (const char*)(g_vh + b * 8192);
        for (int i = t; i < 2048; i += 512) {
            int r2 = i >> 3, c2 = i & 7;
            cp16(sb + B2H_ + r2 * SB2 + c2 * 16, vh + i * 16);
        }
        CP_COMMIT();
    }
    // ---- A1: x tile fp32 -> bf16 hi/lo, rows stride 144B (overlaps copies) ----
    {
        int q = t >> 2, seg = t & 3;
        const float4* xg = (const float4*)(x + ((size_t)b * NTOK + q0 + q) * 64 + seg * 16);
        uint32_t* ah = (uint32_t*)(sm + A1H_);
        uint32_t* al = (uint32_t*)(sm + A1L_);
        int wb = q * 36 + seg * 8;
        #pragma unroll
        for (int j = 0; j < 4; j++) {
            float4 v = xg[j];
            uint32_t hp, lp;
            split_pair(v.x, v.y, hp, lp);
            ah[wb + 2 * j] = hp; al[wb + 2 * j] = lp;
            split_pair(v.z, v.w, hp, lp);
            ah[wb + 2 * j + 1] = hp; al[wb + 2 * j + 1] = lp;
        }
    }
    CP_WAIT1();       // B1h landed (B2h may still be in flight)
    __syncthreads();

    int wr = w >> 2, wc = w & 3;
    int m0 = wr * 32;

    // ================= GEMM1: S[128,256] = x @ M (2-term bf16) =================
    float acc[2][8][4];
    #pragma unroll
    for (int i = 0; i < 2; i++)
        #pragma unroll
        for (int j = 0; j < 8; j++)
            #pragma unroll
            for (int k = 0; k < 4; k++) acc[i][j][k] = 0.f;

    {
        int n0 = wc * 64;
        uint32_t a_lane = (uint32_t)((L & 15) * SA1 + (L >> 4) * 16);
        uint32_t b_lane = (uint32_t)(((L & 7) + 8 * ((L >> 3) & 1)) * SB1 + (L >> 4) * 16);
        const int aoffs[2] = {A1H_, A1L_};
        uint32_t bbase = sb + B1H_ + n0 * 2 + b_lane;
        #pragma unroll
        for (int term = 0; term < 2; term++) {
            uint32_t abase = sb + aoffs[term] + m0 * SA1 + a_lane;
            #pragma unroll
            for (int kc = 0; kc < 4; kc++) {
                uint32_t af[2][4];
                LDSM4(af[0], abase + kc * 32);
                LDSM4(af[1], abase + 16 * SA1 + kc * 32);
                uint32_t bf[4][4];
                #pragma unroll
                for (int j = 0; j < 4; j++)
                    LDSM4T(bf[j], bbase + kc * 16 * SB1 + j * 32);
                #pragma unroll
                for (int i = 0; i < 2; i++)
                    #pragma unroll
                    for (int j = 0; j < 4; j++) {
                        MMA_BF16(acc[i][2 * j],     af[i], bf[j][0], bf[j][1]);
                        MMA_BF16(acc[i][2 * j + 1], af[i], bf[j][2], bf[j][3]);
                    }
            }
        }
    }
    // no barrier: E has its own region

    // ============ exp + row sums + store (E-1) as single bf16 ============
    {
        int n0 = wc * 64;
        float rs[4] = {0.f, 0.f, 0.f, 0.f};
        #pragma unroll
        for (int i = 0; i < 2; i++) {
            int r0 = m0 + i * 16 + (L >> 2);
            #pragma unroll
            for (int j = 0; j < 8; j++) {
                float e0 = __expf(acc[i][j][0]);
                float e1 = __expf(acc[i][j][1]);
                float e2 = __expf(acc[i][j][2]);
                float e3 = __expf(acc[i][j][3]);
                rs[i * 2]     += e0 + e1;
                rs[i * 2 + 1] += e2 + e3;
                int cb = (n0 + j * 8 + 2 * (L & 3)) * 2;
                *(uint32_t*)(sm + E_ + r0 * SE + cb)       = pack_bf16(e0 - 1.f, e1 - 1.f);
                *(uint32_t*)(sm + E_ + (r0 + 8) * SE + cb) = pack_bf16(e2 - 1.f, e3 - 1.f);
            }
        }
        #pragma unroll
        for (int k = 0; k < 4; k++) {
            rs[k] += __shfl_xor_sync(0xffffffffu, rs[k], 1);
            rs[k] += __shfl_xor_sync(0xffffffffu, rs[k], 2);
        }
        if ((L & 3) == 0) {
            float* ps = (float*)(sm + PSUM_);
            #pragma unroll
            for (int i = 0; i < 2; i++)
                #pragma unroll
                for (int h = 0; h < 2; h++) {
                    int row = m0 + i * 16 + 8 * h + (L >> 2);
                    ps[row * 4 + wc] = rs[i * 2 + h];
                }
        }
    }
    CP_WAIT0();       // B2h landed
    __syncthreads();

    // ========= GEMM2: D2[128,64] = (E-1) @ V'hi (single term) =========
    float acc2[2][2][4];
    #pragma unroll
    for (int i = 0; i < 2; i++)
        #pragma unroll
        for (int j = 0; j < 2; j++)
            #pragma unroll
            for (int k = 0; k < 4; k++) acc2[i][j][k] = 0.f;

    {
        int n2 = wc * 16;
        uint32_t a_lane = (uint32_t)((L & 15) * SE + (L >> 4) * 16);
        uint32_t b_lane = (uint32_t)(((L & 7) + 8 * ((L >> 3) & 1)) * SB2 + (L >> 4) * 16);
        uint32_t abase = sb + E_ + m0 * SE + a_lane;
        uint32_t bbase = sb + B2H_ + n2 * 2 + b_lane;
        #pragma unroll
        for (int kc = 0; kc < 16; kc++) {
            uint32_t af[2][4];
            LDSM4(af[0], abase + kc * 32);
            LDSM4(af[1], abase + 16 * SE + kc * 32);
            uint32_t bf[4];
            LDSM4T(bf, bbase + kc * 16 * SB2);
            MMA_BF16(acc2[0][0], af[0], bf[0], bf[1]);
            MMA_BF16(acc2[0][1], af[0], bf[2], bf[3]);
            MMA_BF16(acc2[1][0], af[1], bf[0], bf[1]);
            MMA_BF16(acc2[1][1], af[1], bf[2], bf[3]);
        }
    }

    // ===== epilogue: out = (D2 + Svsum)/rowsum + bias =====
    {
        int n2 = wc * 16;
        const float* ps = (const float*)(sm + PSUM_);
        const float* sv = g_vsum + b * 64;
        #pragma unroll
        for (int i = 0; i < 2; i++)
            #pragma unroll
            for (int h = 0; h < 2; h++) {
                int row = m0 + i * 16 + 8 * h + (L >> 2);
                float4 p4 = *(const float4*)(ps + row * 4);
                float inv = 1.f / (p4.x + p4.y + p4.z + p4.w);
                float* og = out + ((size_t)(b * NTOK) + q0 + row) * 64;
                #pragma unroll
                for (int jj = 0; jj < 2; jj++) {
                    int c = n2 + jj * 8 + 2 * (L & 3);
                    float2 bb = *(const float2*)(bp + c);
                    float2 ss = *(const float2*)(sv + c);
                    float2 o;
                    o.x = (acc2[i][jj][2 * h]     + ss.x) * inv + bb.x;
                    o.y = (acc2[i][jj][2 * h + 1] + ss.y) * inv + bb.y;
                    *(float2*)(og + c) = o;
                }
            }
    }
}

// ---------------------------------------------------------------------------
extern "C" void kernel_launch(void* const* d_in, const int* in_sizes, int n_in,
                              void* d_out, int out_size) {
    const float* x   = (const float*)d_in[0];
    const float* Wq  = (const float*)d_in[1];
    const float* Wkv = (const float*)d_in[2];
    const float* Wp  = (const float*)d_in[3];
    const float* bp  = (const float*)d_in[4];
    const float* srw = (const float*)d_in[5];
    const float* srb = (const float*)d_in[6];
    const float* lng = (const float*)d_in[7];
    const float* lnb = (const float*)d_in[8];
    float* out = (float*)d_out;

    cudaFuncSetAttribute(k_prep, cudaFuncAttributeMaxDynamicSharedMemorySize, 83968);
    cudaFuncSetAttribute(k_fold, cudaFuncAttributeMaxDynamicSharedMemorySize, 82944);
    cudaFuncSetAttribute(k_attn_mma, cudaFuncAttributeMaxDynamicSharedMemorySize, SMEM_ASK);

    k_transpose_w<<<528, 512>>>(srw);
    k_prep<<<dim3(16, 8), 512, 83968>>>(x, srb, lng, lnb, Wkv);
    k_fold<<<dim3(8, 2, 4), 512, 82944>>>(Wq, Wp);
    k_attn_mma<<<dim3(128, 8), 512, SMEM_ASK>>>(x, bp, out);
}

// round 9
// speedup vs baseline: 2.6835x; 1.1317x over previous
#include <cuda_runtime.h>
#include <cuda_bf16.h>
#include <cstdint>

#define BATCH 8
#define NTOK  16384
#define NK    256
#define SCALE 0.125f

// ---------------- scratch (allocation-free rule) ----------------
__device__ float    g_w3[32 * 8448];
__device__ float    g_k[BATCH * 64 * NK];    // [b][d][p] fp32
__device__ float    g_v[BATCH * NK * 64];    // [b][p][c] fp32
__device__ uint32_t g_mh[BATCH * 8192];      // M bf16 pairs: [c][p/2]
__device__ uint32_t g_vh[BATCH * 8192];      // V' bf16 pairs: [p][e/2]
__device__ float    g_vsum[BATCH * 64];      // fp32 column sums of V'

// ---------------- helpers ----------------
__device__ __forceinline__ uint32_t smem_u32(const void* p) {
    uint32_t a;
    asm("{ .reg .u64 t; cvta.to.shared.u64 t, %1; cvt.u32.u64 %0, t; }" : "=r"(a) : "l"(p));
    return a;
}
__device__ __forceinline__ uint32_t pack_bf16(float a, float b) {
    __nv_bfloat16 ah = __float2bfloat16(a);
    __nv_bfloat16 bh = __float2bfloat16(b);
    return ((uint32_t)__bfloat16_as_ushort(bh) << 16) | (uint32_t)__bfloat16_as_ushort(ah);
}

#define LDSM4(r, addr) \
    asm volatile("ldmatrix.sync.aligned.m8n8.x4.shared.b16 {%0,%1,%2,%3}, [%4];" \
        : "=r"((r)[0]), "=r"((r)[1]), "=r"((r)[2]), "=r"((r)[3]) : "r"(addr))
#define LDSM4T(r, addr) \
    asm volatile("ldmatrix.sync.aligned.m8n8.x4.trans.shared.b16 {%0,%1,%2,%3}, [%4];" \
        : "=r"((r)[0]), "=r"((r)[1]), "=r"((r)[2]), "=r"((r)[3]) : "r"(addr))
#define MMA_BF16(d, a, b0, b1) \
    asm volatile("mma.sync.aligned.m16n8k16.row.col.f32.bf16.bf16.f32 " \
        "{%0,%1,%2,%3}, {%4,%5,%6,%7}, {%8,%9}, {%0,%1,%2,%3};" \
        : "+f"((d)[0]), "+f"((d)[1]), "+f"((d)[2]), "+f"((d)[3]) \
        : "r"((a)[0]), "r"((a)[1]), "r"((a)[2]), "r"((a)[3]), "r"(b0), "r"(b1))

__device__ __forceinline__ void cp16(uint32_t s, const void* g) {
    asm volatile("cp.async.cg.shared.global [%0], [%1], 16;" :: "r"(s), "l"(g));
}
#define CP_COMMIT() asm volatile("cp.async.commit_group;" ::: "memory")
#define CP_WAIT1()  asm volatile("cp.async.wait_group 1;" ::: "memory")
#define CP_WAIT0()  asm volatile("cp.async.wait_group 0;" ::: "memory")

// ---------------------------------------------------------------------------
// Kernel 0: weight reshuffle for prep; also zero g_vsum
// ---------------------------------------------------------------------------
__global__ void k_transpose_w(const float* __restrict__ srw) {
    int d = blockIdx.x * 512 + threadIdx.x;
    if (d < BATCH * 64) g_vsum[d] = 0.f;
    int stage = d / 8448;
    int r = d - stage * 8448;
    int o = r / 132;
    int r2 = r - o * 132;
    float v = 0.f;
    if (r2 < 128) {
        int kw = r2 >> 4, ii = r2 & 15;
        int ic = stage >> 3, kh = stage & 7;
        v = srw[o * 4096 + (ic * 16 + ii) * 64 + kh * 8 + kw];
    }
    g_w3[d] = v;
}

// ---------------------------------------------------------------------------
// Kernel 1: sr-conv + LayerNorm + KV projection. cp.async double-buffered.
// ---------------------------------------------------------------------------
__global__ void __launch_bounds__(512) k_prep(
    const float* __restrict__ x, const float* __restrict__ srb,
    const float* __restrict__ lng, const float* __restrict__ lnb,
    const float* __restrict__ Wkv)
{
    extern __shared__ float dsm[];
    int ph = blockIdx.x, b = blockIdx.y;
    int t = threadIdx.x;
    int o = t & 63, pwg = t >> 6;
    uint32_t sb = smem_u32(dsm);

    auto issue = [&](int stage, int bi) {
        int ic = stage >> 3, kh = stage & 7;
        uint32_t wsdst = sb + bi * 33792;
        const float4* wsrc = (const float4*)g_w3 + stage * 2112;
        for (int i = t; i < 2112; i += 512)
            cp16(wsdst + i * 16, wsrc + i);
        uint32_t xsdst = sb + 67584 + bi * 8192;
        int w = t >> 2, j = t & 3;
        int row = (ph * 8 + kh) * 128 + w;
        cp16(xsdst + t * 16, (const float4*)x + (size_t)(b * NTOK + row) * 16 + ic * 4 + j);
    };

    float a0 = 0.f, a1 = 0.f;
    issue(0, 0);
    CP_COMMIT();
    for (int s = 0; s < 32; s++) {
        if (s + 1 < 32) { issue(s + 1, (s + 1) & 1); CP_COMMIT(); CP_WAIT1(); }
        else CP_WAIT0();
        __syncthreads();
        const float4* wsb  = (const float4*)(dsm + (s & 1) * 8448) + o * 33;
        const float4* xs4s = (const float4*)(dsm + 16896 + (s & 1) * 2048);
        #pragma unroll
        for (int kw = 0; kw < 8; kw++) {
            #pragma unroll
            for (int ii4 = 0; ii4 < 4; ii4++) {
                float4 w  = wsb[kw * 4 + ii4];
                float4 xa = xs4s[(pwg * 8 + kw) * 4 + ii4];
                float4 xb = xs4s[((pwg + 8) * 8 + kw) * 4 + ii4];
                a0 = fmaf(w.x, xa.x, a0); a0 = fmaf(w.y, xa.y, a0);
                a0 = fmaf(w.z, xa.z, a0); a0 = fmaf(w.w, xa.w, a0);
                a1 = fmaf(w.x, xb.x, a1); a1 = fmaf(w.y, xb.y, a1);
                a1 = fmaf(w.z, xb.z, a1); a1 = fmaf(w.w, xb.w, a1);
            }
        }
        __syncthreads();
    }

    float* co = dsm;
    float* ln = dsm + 1024;
    float bo = srb[o];
    co[pwg * 64 + o]       = a0 + bo;
    co[(pwg + 8) * 64 + o] = a1 + bo;
    __syncthreads();

    int warp = t >> 5, lane = t & 31;
    {
        float v0 = co[warp * 64 + lane];
        float v1 = co[warp * 64 + lane + 32];
        float s = v0 + v1, sq = v0 * v0 + v1 * v1;
        #pragma unroll
        for (int off = 16; off; off >>= 1) {
            s  += __shfl_xor_sync(0xffffffffu, s, off);
            sq += __shfl_xor_sync(0xffffffffu, sq, off);
        }
        float mean = s * (1.f / 64.f);
        float var  = sq * (1.f / 64.f) - mean * mean;
        float rs = rsqrtf(var + 1e-5f);
        ln[warp * 64 + lane]      = (v0 - mean) * rs * lng[lane]      + lnb[lane];
        ln[warp * 64 + lane + 32] = (v1 - mean) * rs * lng[lane + 32] + lnb[lane + 32];
    }
    __syncthreads();

    int c = t & 127, pg = t >> 7;
    float acc[4] = {0.f, 0.f, 0.f, 0.f};
    for (int i = 0; i < 64; i++) {
        float wv = Wkv[i * 128 + c];
        #pragma unroll
        for (int m = 0; m < 4; m++)
            acc[m] = fmaf(ln[(pg * 4 + m) * 64 + i], wv, acc[m]);
    }
    #pragma unroll
    for (int m = 0; m < 4; m++) {
        int p = ph * 16 + pg * 4 + m;
        if (c < 64) g_k[(b * 64 + c) * NK + p]        = acc[m];
        else        g_v[(b * NK + p) * 64 + (c - 64)] = acc[m];
    }
}

// ---------------------------------------------------------------------------
// Kernel 1.5: fold projections -> bf16 operands; V' colsum fp32 atomics.
// grid (8 b, 2 z, 4 slices), 512 threads.
// ---------------------------------------------------------------------------
__global__ void __launch_bounds__(512) k_fold(
    const float* __restrict__ Wq, const float* __restrict__ Wp)
{
    extern __shared__ float fs[];
    int b = blockIdx.x, z = blockIdx.y, sl = blockIdx.z;
    int t = threadIdx.x;

    if (z == 0) {
        float* wq = fs;           // [64 c][64 d]
        float* ks = fs + 4096;    // [64 d][256 p]
        for (int i = t; i < 1024; i += 512) ((float4*)wq)[i] = ((const float4*)Wq)[i];
        const float4* gk4 = (const float4*)g_k + b * 4096;
        for (int i = t; i < 4096; i += 512) ((float4*)ks)[i] = gk4[i];
        __syncthreads();
        uint32_t* mh = g_mh + b * 8192;
        for (int idx = sl * 2048 + t; idx < (sl + 1) * 2048; idx += 512) {
            int c = idx >> 7, pp = idx & 127;
            float m0 = 0.f, m1 = 0.f;
            for (int d = 0; d < 64; d++) {
                float w = wq[c * 64 + d];
                m0 = fmaf(w, ks[d * 256 + 2 * pp],     m0);
                m1 = fmaf(w, ks[d * 256 + 2 * pp + 1], m1);
            }
            mh[idx] = pack_bf16(m0 * SCALE, m1 * SCALE);
        }
    } else {
        float* wp = fs;           // [64 c][64 e]
        float* vs = fs + 4096;    // [256 p][65]
        for (int i = t; i < 1024; i += 512) ((float4*)wp)[i] = ((const float4*)Wp)[i];
        const float* gv = g_v + b * 16384;
        for (int i = t; i < 16384; i += 512) { int p = i >> 6, c = i & 63; vs[p * 65 + c] = gv[i]; }
        __syncthreads();
        uint32_t* vh = g_vh + b * 8192;
        for (int idx = sl * 2048 + t; idx < (sl + 1) * 2048; idx += 512) {
            int p = idx >> 5, ee = idx & 31;
            float a0 = 0.f, a1 = 0.f;
            for (int c = 0; c < 64; c++) {
                float v = vs[p * 65 + c];
                a0 = fmaf(v, wp[c * 64 + 2 * ee],     a0);
                a1 = fmaf(v, wp[c * 64 + 2 * ee + 1], a1);
            }
            vh[idx] = pack_bf16(a0, a1);
            atomicAdd(&g_vsum[b * 64 + 2 * ee],     a0);
            atomicAdd(&g_vsum[b * 64 + 2 * ee + 1], a1);
        }
    }
}

// ---------------------------------------------------------------------------
// Kernel 2: persistent HMMA attention. grid (16, 8), 512 threads,
// 8 q-tiles per CTA with resident B operands + cp.async x prefetch.
// SMEM: XS0@0(32768) XS1@32768(32768) A1h@65536(18432,144)
//       B1h@83968(33792,528) E@117760(67584,528) B2h@185344(36864,144)
//       PSUM@222208(2048) -> 224256
// ---------------------------------------------------------------------------
#define SA1 144
#define SB1 528
#define SE  528
#define SB2 144
#define XS0_ 0
#define A1H_ 65536
#define B1H_ 83968
#define E_   117760
#define B2H_ 185344
#define PSUM_ 222208
#define SMEM_ASK 224256

__global__ void __launch_bounds__(512, 1) k_attn_mma(
    const float* __restrict__ x, const float* __restrict__ bp,
    float* __restrict__ out)
{
    extern __shared__ char sm[];
    uint32_t sb = smem_u32(sm);
    int t = threadIdx.x;
    int L = t & 31, w = t >> 5;
    int bx = blockIdx.x, b = blockIdx.y;
    int wr = w >> 2, wc = w & 3;
    int m0 = wr * 32;

    // ---- prologue: async copy B1h, B2h, x tile 0 (one group) ----
    {
        const char* mh = (const char*)(g_mh + b * 8192);
        for (int i = t; i < 2048; i += 512) {
            int r1 = i >> 5, c1 = i & 31;
            cp16(sb + B1H_ + r1 * SB1 + c1 * 16, mh + i * 16);
        }
        const char* vh = (const char*)(g_vh + b * 8192);
        for (int i = t; i < 2048; i += 512) {
            int r2 = i >> 3, c2 = i & 7;
            cp16(sb + B2H_ + r2 * SB2 + c2 * 16, vh + i * 16);
        }
        const char* xsrc = (const char*)(x + ((size_t)b * NTOK + (size_t)bx * 1024) * 64);
        for (int i = t; i < 2048; i += 512)
            cp16(sb + XS0_ + i * 16, xsrc + i * 16);
        CP_COMMIT();
    }

    for (int j = 0; j < 8; j++) {
        int q0 = bx * 1024 + j * 128;
        // prefetch next x tile; ensure current tile (and B ops on j=0) landed
        if (j < 7) {
            const char* xsrc = (const char*)(x + ((size_t)b * NTOK + q0 + 128) * 64);
            uint32_t dst = sb + XS0_ + ((j + 1) & 1) * 32768;
            for (int i = t; i < 2048; i += 512)
                cp16(dst + i * 16, xsrc + i * 16);
            CP_COMMIT();
            CP_WAIT1();
        } else {
            CP_WAIT0();
        }
        __syncthreads();   // XS[j&1] visible; all threads done with prev iteration

        // ---- convert x tile (smem fp32) -> A1h bf16, stride 144 ----
        {
            const float2* xs2 = (const float2*)(sm + XS0_ + (j & 1) * 32768);
            uint32_t* ah = (uint32_t*)(sm + A1H_);
            #pragma unroll
            for (int k = 0; k < 8; k++) {
                int f = t + k * 512;           // pair index 0..4095
                float2 v = xs2[f];
                int row = f >> 5, cp = f & 31;
                ah[row * 36 + cp] = pack_bf16(v.x, v.y);
            }
        }
        __syncthreads();   // A1h ready

        // ================= GEMM1: S[128,256] = x @ M (1-term bf16) =============
        float acc[2][8][4];
        #pragma unroll
        for (int i = 0; i < 2; i++)
            #pragma unroll
            for (int jj = 0; jj < 8; jj++)
                #pragma unroll
                for (int k = 0; k < 4; k++) acc[i][jj][k] = 0.f;

        {
            int n0 = wc * 64;
            uint32_t a_lane = (uint32_t)((L & 15) * SA1 + (L >> 4) * 16);
            uint32_t b_lane = (uint32_t)(((L & 7) + 8 * ((L >> 3) & 1)) * SB1 + (L >> 4) * 16);
            uint32_t abase = sb + A1H_ + m0 * SA1 + a_lane;
            uint32_t bbase = sb + B1H_ + n0 * 2 + b_lane;
            #pragma unroll
            for (int kc = 0; kc < 4; kc++) {
                uint32_t af[2][4];
                LDSM4(af[0], abase + kc * 32);
                LDSM4(af[1], abase + 16 * SA1 + kc * 32);
                uint32_t bf[4][4];
                #pragma unroll
                for (int jj = 0; jj < 4; jj++)
                    LDSM4T(bf[jj], bbase + kc * 16 * SB1 + jj * 32);
                #pragma unroll
                for (int i = 0; i < 2; i++)
                    #pragma unroll
                    for (int jj = 0; jj < 4; jj++) {
                        MMA_BF16(acc[i][2 * jj],     af[i], bf[jj][0], bf[jj][1]);
                        MMA_BF16(acc[i][2 * jj + 1], af[i], bf[jj][2], bf[jj][3]);
                    }
            }
        }

        // ============ exp + row sums + store (E-1) as single bf16 ============
        {
            int n0 = wc * 64;
            float rs[4] = {0.f, 0.f, 0.f, 0.f};
            #pragma unroll
            for (int i = 0; i < 2; i++) {
                int r0 = m0 + i * 16 + (L >> 2);
                #pragma unroll
                for (int jj = 0; jj < 8; jj++) {
                    float e0 = __expf(acc[i][jj][0]);
                    float e1 = __expf(acc[i][jj][1]);
                    float e2 = __expf(acc[i][jj][2]);
                    float e3 = __expf(acc[i][jj][3]);
                    rs[i * 2]     += e0 + e1;
                    rs[i * 2 + 1] += e2 + e3;
                    int cb = (n0 + jj * 8 + 2 * (L & 3)) * 2;
                    *(uint32_t*)(sm + E_ + r0 * SE + cb)       = pack_bf16(e0 - 1.f, e1 - 1.f);
                    *(uint32_t*)(sm + E_ + (r0 + 8) * SE + cb) = pack_bf16(e2 - 1.f, e3 - 1.f);
                }
            }
            #pragma unroll
            for (int k = 0; k < 4; k++) {
                rs[k] += __shfl_xor_sync(0xffffffffu, rs[k], 1);
                rs[k] += __shfl_xor_sync(0xffffffffu, rs[k], 2);
            }
            if ((L & 3) == 0) {
                float* ps = (float*)(sm + PSUM_);
                #pragma unroll
                for (int i = 0; i < 2; i++)
                    #pragma unroll
                    for (int h = 0; h < 2; h++) {
                        int row = m0 + i * 16 + 8 * h + (L >> 2);
                        ps[row * 4 + wc] = rs[i * 2 + h];
                    }
            }
        }
        __syncthreads();   // E + PSUM ready

        // ========= GEMM2: D2[128,64] = (E-1) @ V'hi (single term) =========
        float acc2[2][2][4];
        #pragma unroll
        for (int i = 0; i < 2; i++)
            #pragma unroll
            for (int jj = 0; jj < 2; jj++)
                #pragma unroll
                for (int k = 0; k < 4; k++) acc2[i][jj][k] = 0.f;

        {
            int n2 = wc * 16;
            uint32_t a_lane = (uint32_t)((L & 15) * SE + (L >> 4) * 16);
            uint32_t b_lane = (uint32_t)(((L & 7) + 8 * ((L >> 3) & 1)) * SB2 + (L >> 4) * 16);
            uint32_t abase = sb + E_ + m0 * SE + a_lane;
            uint32_t bbase = sb + B2H_ + n2 * 2 + b_lane;
            #pragma unroll
            for (int kc = 0; kc < 16; kc++) {
                uint32_t af[2][4];
                LDSM4(af[0], abase + kc * 32);
                LDSM4(af[1], abase + 16 * SE + kc * 32);
                uint32_t bf[4];
                LDSM4T(bf, bbase + kc * 16 * SB2);
                MMA_BF16(acc2[0][0], af[0], bf[0], bf[1]);
                MMA_BF16(acc2[0][1], af[0], bf[2], bf[3]);
                MMA_BF16(acc2[1][0], af[1], bf[0], bf[1]);
                MMA_BF16(acc2[1][1], af[1], bf[2], bf[3]);
            }
        }

        // ===== epilogue: out = (D2 + Svsum)/rowsum + bias =====
        {
            int n2 = wc * 16;
            const float* ps = (const float*)(sm + PSUM_);
            const float* sv = g_vsum + b * 64;
            #pragma unroll
            for (int i = 0; i < 2; i++)
                #pragma unroll
                for (int h = 0; h < 2; h++) {
                    int row = m0 + i * 16 + 8 * h + (L >> 2);
                    float4 p4 = *(const float4*)(ps + row * 4);
                    float inv = 1.f / (p4.x + p4.y + p4.z + p4.w);
                    float* og = out + ((size_t)(b * NTOK) + q0 + row) * 64;
                    #pragma unroll
                    for (int jj = 0; jj < 2; jj++) {
                        int c = n2 + jj * 8 + 2 * (L & 3);
                        float2 bb = *(const float2*)(bp + c);
                        float2 ss = *(const float2*)(sv + c);
                        float2 o;
                        o.x = (acc2[i][jj][2 * h]     + ss.x) * inv + bb.x;
                        o.y = (acc2[i][jj][2 * h + 1] + ss.y) * inv + bb.y;
                        *(float2*)(og + c) = o;
                    }
                }
        }
    }
}

// ---------------------------------------------------------------------------
extern "C" void kernel_launch(void* const* d_in, const int* in_sizes, int n_in,
                              void* d_out, int out_size) {
    const float* x   = (const float*)d_in[0];
    const float* Wq  = (const float*)d_in[1];
    const float* Wkv = (const float*)d_in[2];
    const float* Wp  = (const float*)d_in[3];
    const float* bp  = (const float*)d_in[4];
    const float* srw = (const float*)d_in[5];
    const float* srb = (const float*)d_in[6];
    const float* lng = (const float*)d_in[7];
    const float* lnb = (const float*)d_in[8];
    float* out = (float*)d_out;

    cudaFuncSetAttribute(k_prep, cudaFuncAttributeMaxDynamicSharedMemorySize, 83968);
    cudaFuncSetAttribute(k_fold, cudaFuncAttributeMaxDynamicSharedMemorySize, 82944);
    cudaFuncSetAttribute(k_attn_mma, cudaFuncAttributeMaxDynamicSharedMemorySize, SMEM_ASK);

    k_transpose_w<<<528, 512>>>(srw);
    k_prep<<<dim3(16, 8), 512, 83968>>>(x, srb, lng, lnb, Wkv);
    k_fold<<<dim3(8, 2, 4), 512, 82944>>>(Wq, Wp);
    k_attn_mma<<<dim3(16, 8), 512, SMEM_ASK>>>(x, bp, out);
}

// round 10
// speedup vs baseline: 3.9320x; 1.4653x over previous
#include <cuda_runtime.h>
#include <cuda_bf16.h>
#include <cstdint>

#define BATCH 8
#define NTOK  16384
#define NK    256
#define SCALE 0.125f

// ---------------- scratch (allocation-free rule) ----------------
__device__ uint32_t g_wbh[32 * 4608];        // conv W bf16-hi, padded slabs [s][128][36 words]
__device__ uint32_t g_wbl[32 * 4608];        // conv W bf16-lo
__device__ float    g_cacc[8 * 2048 * 64];   // conv partials per kh
__device__ float    g_k[BATCH * 64 * NK];    // [b][d][p] fp32
__device__ float    g_v[BATCH * NK * 64];    // [b][p][c] fp32
__device__ uint32_t g_mh[BATCH * 8192];      // M bf16 pairs: [c][p/2]
__device__ uint32_t g_vh[BATCH * 8192];      // V' bf16 pairs: [p][e/2]
__device__ float    g_vsum[BATCH * 64];      // fp32 column sums of V'

// ---------------- helpers ----------------
__device__ __forceinline__ uint32_t smem_u32(const void* p) {
    uint32_t a;
    asm("{ .reg .u64 t; cvta.to.shared.u64 t, %1; cvt.u32.u64 %0, t; }" : "=r"(a) : "l"(p));
    return a;
}
__device__ __forceinline__ uint32_t pack_bf16(float a, float b) {
    __nv_bfloat16 ah = __float2bfloat16(a);
    __nv_bfloat16 bh = __float2bfloat16(b);
    return ((uint32_t)__bfloat16_as_ushort(bh) << 16) | (uint32_t)__bfloat16_as_ushort(ah);
}
__device__ __forceinline__ void split_pair(float a, float b, uint32_t& hp, uint32_t& lp) {
    __nv_bfloat16 ah = __float2bfloat16(a);
    __nv_bfloat16 bh = __float2bfloat16(b);
    __nv_bfloat16 al = __float2bfloat16(a - __bfloat162float(ah));
    __nv_bfloat16 bl = __float2bfloat16(b - __bfloat162float(bh));
    hp = ((uint32_t)__bfloat16_as_ushort(bh) << 16) | (uint32_t)__bfloat16_as_ushort(ah);
    lp = ((uint32_t)__bfloat16_as_ushort(bl) << 16) | (uint32_t)__bfloat16_as_ushort(al);
}

#define LDSM4(r, addr) \
    asm volatile("ldmatrix.sync.aligned.m8n8.x4.shared.b16 {%0,%1,%2,%3}, [%4];" \
        : "=r"((r)[0]), "=r"((r)[1]), "=r"((r)[2]), "=r"((r)[3]) : "r"(addr))
#define LDSM4T(r, addr) \
    asm volatile("ldmatrix.sync.aligned.m8n8.x4.trans.shared.b16 {%0,%1,%2,%3}, [%4];" \
        : "=r"((r)[0]), "=r"((r)[1]), "=r"((r)[2]), "=r"((r)[3]) : "r"(addr))
#define MMA_BF16(d, a, b0, b1) \
    asm volatile("mma.sync.aligned.m16n8k16.row.col.f32.bf16.bf16.f32 " \
        "{%0,%1,%2,%3}, {%4,%5,%6,%7}, {%8,%9}, {%0,%1,%2,%3};" \
        : "+f"((d)[0]), "+f"((d)[1]), "+f"((d)[2]), "+f"((d)[3]) \
        : "r"((a)[0]), "r"((a)[1]), "r"((a)[2]), "r"((a)[3]), "r"(b0), "r"(b1))

__device__ __forceinline__ void cp16(uint32_t s, const void* g) {
    asm volatile("cp.async.cg.shared.global [%0], [%1], 16;" :: "r"(s), "l"(g));
}
#define CP_COMMIT() asm volatile("cp.async.commit_group;" ::: "memory")
#define CP_WAIT1()  asm volatile("cp.async.wait_group 1;" ::: "memory")
#define CP_WAIT0()  asm volatile("cp.async.wait_group 0;" ::: "memory")

// ---------------------------------------------------------------------------
// Kernel 0: split conv weights into padded bf16 hi/lo slabs; zero g_vsum.
// slab layout: [s = kh*4+ic][k = kw*16+ii][36 words of o-pairs (32 data + 4 pad)]
// ---------------------------------------------------------------------------
__global__ void k_transpose_w(const float* __restrict__ srw) {
    int d = blockIdx.x * 512 + threadIdx.x;    // 288*512 = 147456 = 32*4608
    if (d < BATCH * 64) g_vsum[d] = 0.f;
    int s = d / 4608;
    int r = d - s * 4608;
    int k = r / 36;
    int ow = r - k * 36;
    uint32_t hi = 0, lo = 0;
    if (ow < 32) {
        int kh = s >> 2, ic = s & 3;
        int kw = k >> 4, ii = k & 15;
        int i = ic * 16 + ii;
        float v0 = srw[(2 * ow) * 4096 + i * 64 + kh * 8 + kw];
        float v1 = srw[(2 * ow + 1) * 4096 + i * 64 + kh * 8 + kw];
        split_pair(v0, v1, hi, lo);
    }
    g_wbh[d] = hi;
    g_wbl[d] = lo;
}

// ---------------------------------------------------------------------------
// Kernel 1: conv-as-GEMM on tensor cores (3-term bf16 hi/lo).
// grid (16 pt, 8 kh), 512 threads. CTA: 128 patches (b = pt>>1, half = pt&1),
// K-slice = this kh (4 ic stages of K=128). Partials -> g_cacc[kh].
// SMEM: W[2 buf][hi 18432 | lo 18432] @0 (73728), AH@73728(34816), AL@108544
// ---------------------------------------------------------------------------
#define CW_BUF 36864
#define CW_LO  18432
#define CA_H   73728
#define CA_L   108544
#define CONV_SMEM 143360

__global__ void __launch_bounds__(512, 1) k_conv(const float* __restrict__ x) {
    extern __shared__ char sm[];
    uint32_t sb = smem_u32(sm);
    int t = threadIdx.x;
    int L = t & 31, w = t >> 5;
    int pt = blockIdx.x, kh = blockIdx.y;
    int b = pt >> 1, half = pt & 1;
    int wr = w >> 2, wc = w & 3;
    int m0 = wr * 32, n0 = wc * 16;

    auto issueW = [&](int st, int buf) {
        int s = kh * 4 + st;
        const char* srch = (const char*)g_wbh + (size_t)s * 18432;
        const char* srcl = (const char*)g_wbl + (size_t)s * 18432;
        uint32_t dst = sb + buf * CW_BUF;
        for (int i = t; i < 1152; i += 512) {
            cp16(dst + i * 16, srch + i * 16);
            cp16(dst + CW_LO + i * 16, srcl + i * 16);
        }
    };

    float acc[2][2][4];
    #pragma unroll
    for (int i = 0; i < 2; i++)
        #pragma unroll
        for (int j = 0; j < 2; j++)
            #pragma unroll
            for (int k = 0; k < 4; k++) acc[i][j][k] = 0.f;

    issueW(0, 0);
    CP_COMMIT();

    const float* xb = x + (size_t)b * NTOK * 64;
    for (int st = 0; st < 4; st++) {
        if (st < 4 - 1) { issueW(st + 1, (st + 1) & 1); CP_COMMIT(); }
        // ---- convert A: x -> bf16 hi/lo [128 m][128 k], stride 272B ----
        {
            uint32_t* ah = (uint32_t*)(sm + CA_H);
            uint32_t* al = (uint32_t*)(sm + CA_L);
            #pragma unroll
            for (int it = 0; it < 16; it++) {
                int idx = it * 512 + t;          // 8192 pair-cells
                int m = idx >> 6, pr = idx & 63;
                int kw = pr >> 3, ip = pr & 7;
                int ph = half * 8 + (m >> 4);
                int grow = (ph * 8 + kh) * 128 + (m & 15) * 8 + kw;
                float2 v = *(const float2*)(xb + (size_t)grow * 64 + st * 16 + ip * 2);
                uint32_t hp, lp;
                split_pair(v.x, v.y, hp, lp);
                int wo = m * 68 + kw * 8 + ip;
                ah[wo] = hp; al[wo] = lp;
            }
        }
        if (st < 4 - 1) CP_WAIT1(); else CP_WAIT0();
        __syncthreads();     // A + W(st) visible

        // ---- MMA: 3 terms (AhWh, AlWh, AhWl), K=128 ----
        {
            uint32_t a_lane = (uint32_t)((L & 15) * 272 + (L >> 4) * 16);
            uint32_t b_lane = (uint32_t)(((L & 7) + 8 * ((L >> 3) & 1)) * 144 + (L >> 4) * 16);
            uint32_t wbase = sb + (st & 1) * CW_BUF;
            const int aoffs[3] = {CA_H, CA_L, CA_H};
            const int boffs[3] = {0, 0, CW_LO};
            #pragma unroll
            for (int term = 0; term < 3; term++) {
                uint32_t abase = sb + aoffs[term] + m0 * 272 + a_lane;
                uint32_t bbase = wbase + boffs[term] + n0 * 2 + b_lane;
                #pragma unroll
                for (int kc = 0; kc < 8; kc++) {
                    uint32_t af[2][4];
                    LDSM4(af[0], abase + kc * 32);
                    LDSM4(af[1], abase + 16 * 272 + kc * 32);
                    uint32_t bf[4];
                    LDSM4T(bf, bbase + kc * 16 * 144);
                    MMA_BF16(acc[0][0], af[0], bf[0], bf[1]);
                    MMA_BF16(acc[0][1], af[0], bf[2], bf[3]);
                    MMA_BF16(acc[1][0], af[1], bf[0], bf[1]);
                    MMA_BF16(acc[1][1], af[1], bf[2], bf[3]);
                }
            }
        }
        __syncthreads();     // A free for next stage
    }

    // ---- write fp32 partials ----
    {
        float* gc = g_cacc + ((size_t)kh * 2048 + pt * 128) * 64;
        #pragma unroll
        for (int i = 0; i < 2; i++)
            #pragma unroll
            for (int h = 0; h < 2; h++) {
                int row = m0 + i * 16 + 8 * h + (L >> 2);
                #pragma unroll
                for (int jj = 0; jj < 2; jj++) {
                    int col = n0 + jj * 8 + 2 * (L & 3);
                    float2 o = make_float2(acc[i][jj][2 * h], acc[i][jj][2 * h + 1]);
                    *(float2*)(gc + row * 64 + col) = o;
                }
            }
    }
}

// ---------------------------------------------------------------------------
// Kernel 1.25: reduce conv partials + bias, LayerNorm, KV projection.
// grid (16 ph, 8 b), 512 threads.
// ---------------------------------------------------------------------------
__global__ void __launch_bounds__(512) k_lnkv(
    const float* __restrict__ srb, const float* __restrict__ lng,
    const float* __restrict__ lnb, const float* __restrict__ Wkv)
{
    __shared__ float co[1024];
    __shared__ float ln[1024];
    int ph = blockIdx.x, b = blockIdx.y;
    int t = threadIdx.x;
    int gbase = (b * 2 + (ph >> 3)) * 128 + (ph & 7) * 16;

    if (t < 256) {
        int pw = t >> 4, c4 = t & 15;
        float4 s = make_float4(0.f, 0.f, 0.f, 0.f);
        #pragma unroll
        for (int kh = 0; kh < 8; kh++) {
            float4 v = *(const float4*)(g_cacc + ((size_t)kh * 2048 + gbase + pw) * 64 + c4 * 4);
            s.x += v.x; s.y += v.y; s.z += v.z; s.w += v.w;
        }
        float4 bb = *(const float4*)(srb + c4 * 4);
        s.x += bb.x; s.y += bb.y; s.z += bb.z; s.w += bb.w;
        *(float4*)(co + pw * 64 + c4 * 4) = s;
    }
    __syncthreads();

    int warp = t >> 5, lane = t & 31;
    {
        float v0 = co[warp * 64 + lane];
        float v1 = co[warp * 64 + lane + 32];
        float s = v0 + v1, sq = v0 * v0 + v1 * v1;
        #pragma unroll
        for (int off = 16; off; off >>= 1) {
            s  += __shfl_xor_sync(0xffffffffu, s, off);
            sq += __shfl_xor_sync(0xffffffffu, sq, off);
        }
        float mean = s * (1.f / 64.f);
        float var  = sq * (1.f / 64.f) - mean * mean;
        float rs = rsqrtf(var + 1e-5f);
        ln[warp * 64 + lane]      = (v0 - mean) * rs * lng[lane]      + lnb[lane];
        ln[warp * 64 + lane + 32] = (v1 - mean) * rs * lng[lane + 32] + lnb[lane + 32];
    }
    __syncthreads();

    int c = t & 127, pg = t >> 7;
    float acc[4] = {0.f, 0.f, 0.f, 0.f};
    for (int i = 0; i < 64; i++) {
        float wv = Wkv[i * 128 + c];
        #pragma unroll
        for (int m = 0; m < 4; m++)
            acc[m] = fmaf(ln[(pg * 4 + m) * 64 + i], wv, acc[m]);
    }
    #pragma unroll
    for (int m = 0; m < 4; m++) {
        int p = ph * 16 + pg * 4 + m;
        if (c < 64) g_k[(b * 64 + c) * NK + p]        = acc[m];
        else        g_v[(b * NK + p) * 64 + (c - 64)] = acc[m];
    }
}

// ---------------------------------------------------------------------------
// Kernel 1.5: fold projections -> bf16 operands; V' colsum fp32 atomics.
// grid (8 b, 2 z, 4 slices), 512 threads.
// ---------------------------------------------------------------------------
__global__ void __launch_bounds__(512) k_fold(
    const float* __restrict__ Wq, const float* __restrict__ Wp)
{
    extern __shared__ float fs[];
    int b = blockIdx.x, z = blockIdx.y, sl = blockIdx.z;
    int t = threadIdx.x;

    if (z == 0) {
        float* wq = fs;           // [64 c][64 d]
        float* ks = fs + 4096;    // [64 d][256 p]
        for (int i = t; i < 1024; i += 512) ((float4*)wq)[i] = ((const float4*)Wq)[i];
        const float4* gk4 = (const float4*)g_k + b * 4096;
        for (int i = t; i < 4096; i += 512) ((float4*)ks)[i] = gk4[i];
        __syncthreads();
        uint32_t* mh = g_mh + b * 8192;
        for (int idx = sl * 2048 + t; idx < (sl + 1) * 2048; idx += 512) {
            int c = idx >> 7, pp = idx & 127;
            float m0 = 0.f, m1 = 0.f;
            for (int d = 0; d < 64; d++) {
                float w = wq[c * 64 + d];
                m0 = fmaf(w, ks[d * 256 + 2 * pp],     m0);
                m1 = fmaf(w, ks[d * 256 + 2 * pp + 1], m1);
            }
            mh[idx] = pack_bf16(m0 * SCALE, m1 * SCALE);
        }
    } else {
        float* wp = fs;           // [64 c][64 e]
        float* vs = fs + 4096;    // [256 p][65]
        for (int i = t; i < 1024; i += 512) ((float4*)wp)[i] = ((const float4*)Wp)[i];
        const float* gv = g_v + b * 16384;
        for (int i = t; i < 16384; i += 512) { int p = i >> 6, c = i & 63; vs[p * 65 + c] = gv[i]; }
        __syncthreads();
        uint32_t* vh = g_vh + b * 8192;
        for (int idx = sl * 2048 + t; idx < (sl + 1) * 2048; idx += 512) {
            int p = idx >> 5, ee = idx & 31;
            float a0 = 0.f, a1 = 0.f;
            for (int c = 0; c < 64; c++) {
                float v = vs[p * 65 + c];
                a0 = fmaf(v, wp[c * 64 + 2 * ee],     a0);
                a1 = fmaf(v, wp[c * 64 + 2 * ee + 1], a1);
            }
            vh[idx] = pack_bf16(a0, a1);
            atomicAdd(&g_vsum[b * 64 + 2 * ee],     a0);
            atomicAdd(&g_vsum[b * 64 + 2 * ee + 1], a1);
        }
    }
}

// ---------------------------------------------------------------------------
// Kernel 2: persistent HMMA attention (unchanged from R9).
// ---------------------------------------------------------------------------
#define SA1 144
#define SB1 528
#define SE  528
#define SB2 144
#define XS0_ 0
#define A1H_ 65536
#define B1H_ 83968
#define E_   117760
#define B2H_ 185344
#define PSUM_ 222208
#define SMEM_ASK 224256

__global__ void __launch_bounds__(512, 1) k_attn_mma(
    const float* __restrict__ x, const float* __restrict__ bp,
    float* __restrict__ out)
{
    extern __shared__ char sm[];
    uint32_t sb = smem_u32(sm);
    int t = threadIdx.x;
    int L = t & 31, w = t >> 5;
    int bx = blockIdx.x, b = blockIdx.y;
    int wr = w >> 2, wc = w & 3;
    int m0 = wr * 32;

    {
        const char* mh = (const char*)(g_mh + b * 8192);
        for (int i = t; i < 2048; i += 512) {
            int r1 = i >> 5, c1 = i & 31;
            cp16(sb + B1H_ + r1 * SB1 + c1 * 16, mh + i * 16);
        }
        const char* vh = (const char*)(g_vh + b * 8192);
        for (int i = t; i < 2048; i += 512) {
            int r2 = i >> 3, c2 = i & 7;
            cp16(sb + B2H_ + r2 * SB2 + c2 * 16, vh + i * 16);
        }
        const char* xsrc = (const char*)(x + ((size_t)b * NTOK + (size_t)bx * 1024) * 64);
        for (int i = t; i < 2048; i += 512)
            cp16(sb + XS0_ + i * 16, xsrc + i * 16);
        CP_COMMIT();
    }

    for (int j = 0; j < 8; j++) {
        int q0 = bx * 1024 + j * 128;
        if (j < 7) {
            const char* xsrc = (const char*)(x + ((size_t)b * NTOK + q0 + 128) * 64);
            uint32_t dst = sb + XS0_ + ((j + 1) & 1) * 32768;
            for (int i = t; i < 2048; i += 512)
                cp16(dst + i * 16, xsrc + i * 16);
            CP_COMMIT();
            CP_WAIT1();
        } else {
            CP_WAIT0();
        }
        __syncthreads();

        {
            const float2* xs2 = (const float2*)(sm + XS0_ + (j & 1) * 32768);
            uint32_t* ah = (uint32_t*)(sm + A1H_);
            #pragma unroll
            for (int k = 0; k < 8; k++) {
                int f = t + k * 512;
                float2 v = xs2[f];
                int row = f >> 5, cp = f & 31;
                ah[row * 36 + cp] = pack_bf16(v.x, v.y);
            }
        }
        __syncthreads();

        float acc[2][8][4];
        #pragma unroll
        for (int i = 0; i < 2; i++)
            #pragma unroll
            for (int jj = 0; jj < 8; jj++)
                #pragma unroll
                for (int k = 0; k < 4; k++) acc[i][jj][k] = 0.f;

        {
            int n0 = wc * 64;
            uint32_t a_lane = (uint32_t)((L & 15) * SA1 + (L >> 4) * 16);
            uint32_t b_lane = (uint32_t)(((L & 7) + 8 * ((L >> 3) & 1)) * SB1 + (L >> 4) * 16);
            uint32_t abase = sb + A1H_ + m0 * SA1 + a_lane;
            uint32_t bbase = sb + B1H_ + n0 * 2 + b_lane;
            #pragma unroll
            for (int kc = 0; kc < 4; kc++) {
                uint32_t af[2][4];
                LDSM4(af[0], abase + kc * 32);
                LDSM4(af[1], abase + 16 * SA1 + kc * 32);
                uint32_t bf[4][4];
                #pragma unroll
                for (int jj = 0; jj < 4; jj++)
                    LDSM4T(bf[jj], bbase + kc * 16 * SB1 + jj * 32);
                #pragma unroll
                for (int i = 0; i < 2; i++)
                    #pragma unroll
                    for (int jj = 0; jj < 4; jj++) {
                        MMA_BF16(acc[i][2 * jj],     af[i], bf[jj][0], bf[jj][1]);
                        MMA_BF16(acc[i][2 * jj + 1], af[i], bf[jj][2], bf[jj][3]);
                    }
            }
        }

        {
            int n0 = wc * 64;
            float rs[4] = {0.f, 0.f, 0.f, 0.f};
            #pragma unroll
            for (int i = 0; i < 2; i++) {
                int r0 = m0 + i * 16 + (L >> 2);
                #pragma unroll
                for (int jj = 0; jj < 8; jj++) {
                    float e0 = __expf(acc[i][jj][0]);
                    float e1 = __expf(acc[i][jj][1]);
                    float e2 = __expf(acc[i][jj][2]);
                    float e3 = __expf(acc[i][jj][3]);
                    rs[i * 2]     += e0 + e1;
                    rs[i * 2 + 1] += e2 + e3;
                    int cb = (n0 + jj * 8 + 2 * (L & 3)) * 2;
                    *(uint32_t*)(sm + E_ + r0 * SE + cb)       = pack_bf16(e0 - 1.f, e1 - 1.f);
                    *(uint32_t*)(sm + E_ + (r0 + 8) * SE + cb) = pack_bf16(e2 - 1.f, e3 - 1.f);
                }
            }
            #pragma unroll
            for (int k = 0; k < 4; k++) {
                rs[k] += __shfl_xor_sync(0xffffffffu, rs[k], 1);
                rs[k] += __shfl_xor_sync(0xffffffffu, rs[k], 2);
            }
            if ((L & 3) == 0) {
                float* ps = (float*)(sm + PSUM_);
                #pragma unroll
                for (int i = 0; i < 2; i++)
                    #pragma unroll
                    for (int h = 0; h < 2; h++) {
                        int row = m0 + i * 16 + 8 * h + (L >> 2);
                        ps[row * 4 + wc] = rs[i * 2 + h];
                    }
            }
        }
        __syncthreads();

        float acc2[2][2][4];
        #pragma unroll
        for (int i = 0; i < 2; i++)
            #pragma unroll
            for (int jj = 0; jj < 2; jj++)
                #pragma unroll
                for (int k = 0; k < 4; k++) acc2[i][jj][k] = 0.f;

        {
            int n2 = wc * 16;
            uint32_t a_lane = (uint32_t)((L & 15) * SE + (L >> 4) * 16);
            uint32_t b_lane = (uint32_t)(((L & 7) + 8 * ((L >> 3) & 1)) * SB2 + (L >> 4) * 16);
            uint32_t abase = sb + E_ + m0 * SE + a_lane;
            uint32_t bbase = sb + B2H_ + n2 * 2 + b_lane;
            #pragma unroll
            for (int kc = 0; kc < 16; kc++) {
                uint32_t af[2][4];
                LDSM4(af[0], abase + kc * 32);
                LDSM4(af[1], abase + 16 * SE + kc * 32);
                uint32_t bf[4];
                LDSM4T(bf, bbase + kc * 16 * SB2);
                MMA_BF16(acc2[0][0], af[0], bf[0], bf[1]);
                MMA_BF16(acc2[0][1], af[0], bf[2], bf[3]);
                MMA_BF16(acc2[1][0], af[1], bf[0], bf[1]);
                MMA_BF16(acc2[1][1], af[1], bf[2], bf[3]);
            }
        }

        {
            int n2 = wc * 16;
            const float* ps = (const float*)(sm + PSUM_);
            const float* sv = g_vsum + b * 64;
            #pragma unroll
            for (int i = 0; i < 2; i++)
                #pragma unroll
                for (int h = 0; h < 2; h++) {
                    int row = m0 + i * 16 + 8 * h + (L >> 2);
                    float4 p4 = *(const float4*)(ps + row * 4);
                    float inv = 1.f / (p4.x + p4.y + p4.z + p4.w);
                    float* og = out + ((size_t)(b * NTOK) + q0 + row) * 64;
                    #pragma unroll
                    for (int jj = 0; jj < 2; jj++) {
                        int c = n2 + jj * 8 + 2 * (L & 3);
                        float2 bb = *(const float2*)(bp + c);
                        float2 ss = *(const float2*)(sv + c);
                        float2 o;
                        o.x = (acc2[i][jj][2 * h]     + ss.x) * inv + bb.x;
                        o.y = (acc2[i][jj][2 * h + 1] + ss.y) * inv + bb.y;
                        *(float2*)(og + c) = o;
                    }
                }
        }
    }
}

// ---------------------------------------------------------------------------
extern "C" void kernel_launch(void* const* d_in, const int* in_sizes, int n_in,
                              void* d_out, int out_size) {
    const float* x   = (const float*)d_in[0];
    const float* Wq  = (const float*)d_in[1];
    const float* Wkv = (const float*)d_in[2];
    const float* Wp  = (const float*)d_in[3];
    const float* bp  = (const float*)d_in[4];
    const float* srw = (const float*)d_in[5];
    const float* srb = (const float*)d_in[6];
    const float* lng = (const float*)d_in[7];
    const float* lnb = (const float*)d_in[8];
    float* out = (float*)d_out;

    cudaFuncSetAttribute(k_conv, cudaFuncAttributeMaxDynamicSharedMemorySize, CONV_SMEM);
    cudaFuncSetAttribute(k_fold, cudaFuncAttributeMaxDynamicSharedMemorySize, 82944);
    cudaFuncSetAttribute(k_attn_mma, cudaFuncAttributeMaxDynamicSharedMemorySize, SMEM_ASK);

    k_transpose_w<<<288, 512>>>(srw);
    k_conv<<<dim3(16, 8), 512, CONV_SMEM>>>(x);
    k_lnkv<<<dim3(16, 8), 512>>>(srb, lng, lnb, Wkv);
    k_fold<<<dim3(8, 2, 4), 512, 82944>>>(Wq, Wp);
    k_attn_mma<<<dim3(16, 8), 512, SMEM_ASK>>>(x, bp, out);
}

// round 11
// speedup vs baseline: 4.1371x; 1.0522x over previous
#include <cuda_runtime.h>
#include <cuda_bf16.h>
#include <cstdint>

#define BATCH 8
#define NTOK  16384
#define NK    256
#define SCALE 0.125f

// ---------------- scratch (allocation-free rule) ----------------
__device__ uint32_t g_wbh[32 * 4608];        // conv W bf16-hi, padded slabs [s][128][36 words]
__device__ uint32_t g_wbl[32 * 4608];        // conv W bf16-lo
__device__ float    g_cacc[8 * 2048 * 64];   // conv partials per kh
__device__ float    g_k[BATCH * 64 * NK];    // [b][d][p] fp32
__device__ float    g_v[BATCH * NK * 64];    // [b][p][c] fp32
__device__ uint32_t g_mh[BATCH * 8192];      // M bf16 pairs: [c][p/2]
__device__ uint32_t g_vh[BATCH * 8192];      // V' bf16 pairs: [p][e/2]
__device__ float    g_vsum[BATCH * 64];      // fp32 column sums of V'

// ---------------- helpers ----------------
__device__ __forceinline__ uint32_t smem_u32(const void* p) {
    uint32_t a;
    asm("{ .reg .u64 t; cvta.to.shared.u64 t, %1; cvt.u32.u64 %0, t; }" : "=r"(a) : "l"(p));
    return a;
}
__device__ __forceinline__ uint32_t pack_bf16(float a, float b) {
    __nv_bfloat16 ah = __float2bfloat16(a);
    __nv_bfloat16 bh = __float2bfloat16(b);
    return ((uint32_t)__bfloat16_as_ushort(bh) << 16) | (uint32_t)__bfloat16_as_ushort(ah);
}
__device__ __forceinline__ void split_pair(float a, float b, uint32_t& hp, uint32_t& lp) {
    __nv_bfloat16 ah = __float2bfloat16(a);
    __nv_bfloat16 bh = __float2bfloat16(b);
    __nv_bfloat16 al = __float2bfloat16(a - __bfloat162float(ah));
    __nv_bfloat16 bl = __float2bfloat16(b - __bfloat162float(bh));
    hp = ((uint32_t)__bfloat16_as_ushort(bh) << 16) | (uint32_t)__bfloat16_as_ushort(ah);
    lp = ((uint32_t)__bfloat16_as_ushort(bl) << 16) | (uint32_t)__bfloat16_as_ushort(al);
}

#define LDSM4(r, addr) \
    asm volatile("ldmatrix.sync.aligned.m8n8.x4.shared.b16 {%0,%1,%2,%3}, [%4];" \
        : "=r"((r)[0]), "=r"((r)[1]), "=r"((r)[2]), "=r"((r)[3]) : "r"(addr))
#define LDSM4T(r, addr) \
    asm volatile("ldmatrix.sync.aligned.m8n8.x4.trans.shared.b16 {%0,%1,%2,%3}, [%4];" \
        : "=r"((r)[0]), "=r"((r)[1]), "=r"((r)[2]), "=r"((r)[3]) : "r"(addr))
#define MMA_BF16(d, a, b0, b1) \
    asm volatile("mma.sync.aligned.m16n8k16.row.col.f32.bf16.bf16.f32 " \
        "{%0,%1,%2,%3}, {%4,%5,%6,%7}, {%8,%9}, {%0,%1,%2,%3};" \
        : "+f"((d)[0]), "+f"((d)[1]), "+f"((d)[2]), "+f"((d)[3]) \
        : "r"((a)[0]), "r"((a)[1]), "r"((a)[2]), "r"((a)[3]), "r"(b0), "r"(b1))

__device__ __forceinline__ void cp16(uint32_t s, const void* g) {
    asm volatile("cp.async.cg.shared.global [%0], [%1], 16;" :: "r"(s), "l"(g));
}
#define CP_COMMIT() asm volatile("cp.async.commit_group;" ::: "memory")
#define CP_WAIT1()  asm volatile("cp.async.wait_group 1;" ::: "memory")
#define CP_WAIT0()  asm volatile("cp.async.wait_group 0;" ::: "memory")
#define NBAR(id)    asm volatile("bar.sync %0, 128;" :: "r"(id) : "memory")

// ---------------------------------------------------------------------------
// Kernel 0: split conv weights into padded bf16 hi/lo slabs; zero g_vsum.
// ---------------------------------------------------------------------------
__global__ void k_transpose_w(const float* __restrict__ srw) {
    int d = blockIdx.x * 512 + threadIdx.x;    // 288*512 = 147456 = 32*4608
    if (d < BATCH * 64) g_vsum[d] = 0.f;
    int s = d / 4608;
    int r = d - s * 4608;
    int k = r / 36;
    int ow = r - k * 36;
    uint32_t hi = 0, lo = 0;
    if (ow < 32) {
        int kh = s >> 2, ic = s & 3;
        int kw = k >> 4, ii = k & 15;
        int i = ic * 16 + ii;
        float v0 = srw[(2 * ow) * 4096 + i * 64 + kh * 8 + kw];
        float v1 = srw[(2 * ow + 1) * 4096 + i * 64 + kh * 8 + kw];
        split_pair(v0, v1, hi, lo);
    }
    g_wbh[d] = hi;
    g_wbl[d] = lo;
}

// ---------------------------------------------------------------------------
// Kernel 1: conv-as-GEMM on tensor cores (3-term bf16 hi/lo). (unchanged)
// ---------------------------------------------------------------------------
#define CW_BUF 36864
#define CW_LO  18432
#define CA_H   73728
#define CA_L   108544
#define CONV_SMEM 143360

__global__ void __launch_bounds__(512, 1) k_conv(const float* __restrict__ x) {
    extern __shared__ char sm[];
    uint32_t sb = smem_u32(sm);
    int t = threadIdx.x;
    int L = t & 31, w = t >> 5;
    int pt = blockIdx.x, kh = blockIdx.y;
    int b = pt >> 1, half = pt & 1;
    int wr = w >> 2, wc = w & 3;
    int m0 = wr * 32, n0 = wc * 16;

    auto issueW = [&](int st, int buf) {
        int s = kh * 4 + st;
        const char* srch = (const char*)g_wbh + (size_t)s * 18432;
        const char* srcl = (const char*)g_wbl + (size_t)s * 18432;
        uint32_t dst = sb + buf * CW_BUF;
        for (int i = t; i < 1152; i += 512) {
            cp16(dst + i * 16, srch + i * 16);
            cp16(dst + CW_LO + i * 16, srcl + i * 16);
        }
    };

    float acc[2][2][4];
    #pragma unroll
    for (int i = 0; i < 2; i++)
        #pragma unroll
        for (int j = 0; j < 2; j++)
            #pragma unroll
            for (int k = 0; k < 4; k++) acc[i][j][k] = 0.f;

    issueW(0, 0);
    CP_COMMIT();

    const float* xb = x + (size_t)b * NTOK * 64;
    for (int st = 0; st < 4; st++) {
        if (st < 3) { issueW(st + 1, (st + 1) & 1); CP_COMMIT(); }
        {
            uint32_t* ah = (uint32_t*)(sm + CA_H);
            uint32_t* al = (uint32_t*)(sm + CA_L);
            #pragma unroll
            for (int it = 0; it < 16; it++) {
                int idx = it * 512 + t;
                int m = idx >> 6, pr = idx & 63;
                int kw = pr >> 3, ip = pr & 7;
                int ph = half * 8 + (m >> 4);
                int grow = (ph * 8 + kh) * 128 + (m & 15) * 8 + kw;
                float2 v = *(const float2*)(xb + (size_t)grow * 64 + st * 16 + ip * 2);
                uint32_t hp, lp;
                split_pair(v.x, v.y, hp, lp);
                int wo = m * 68 + kw * 8 + ip;
                ah[wo] = hp; al[wo] = lp;
            }
        }
        if (st < 3) CP_WAIT1(); else CP_WAIT0();
        __syncthreads();

        {
            uint32_t a_lane = (uint32_t)((L & 15) * 272 + (L >> 4) * 16);
            uint32_t b_lane = (uint32_t)(((L & 7) + 8 * ((L >> 3) & 1)) * 144 + (L >> 4) * 16);
            uint32_t wbase = sb + (st & 1) * CW_BUF;
            const int aoffs[3] = {CA_H, CA_L, CA_H};
            const int boffs[3] = {0, 0, CW_LO};
            #pragma unroll
            for (int term = 0; term < 3; term++) {
                uint32_t abase = sb + aoffs[term] + m0 * 272 + a_lane;
                uint32_t bbase = wbase + boffs[term] + n0 * 2 + b_lane;
                #pragma unroll
                for (int kc = 0; kc < 8; kc++) {
                    uint32_t af[2][4];
                    LDSM4(af[0], abase + kc * 32);
                    LDSM4(af[1], abase + 16 * 272 + kc * 32);
                    uint32_t bf[4];
                    LDSM4T(bf, bbase + kc * 16 * 144);
                    MMA_BF16(acc[0][0], af[0], bf[0], bf[1]);
                    MMA_BF16(acc[0][1], af[0], bf[2], bf[3]);
                    MMA_BF16(acc[1][0], af[1], bf[0], bf[1]);
                    MMA_BF16(acc[1][1], af[1], bf[2], bf[3]);
                }
            }
        }
        __syncthreads();
    }

    {
        float* gc = g_cacc + ((size_t)kh * 2048 + pt * 128) * 64;
        #pragma unroll
        for (int i = 0; i < 2; i++)
            #pragma unroll
            for (int h = 0; h < 2; h++) {
                int row = m0 + i * 16 + 8 * h + (L >> 2);
                #pragma unroll
                for (int jj = 0; jj < 2; jj++) {
                    int col = n0 + jj * 8 + 2 * (L & 3);
                    float2 o = make_float2(acc[i][jj][2 * h], acc[i][jj][2 * h + 1]);
                    *(float2*)(gc + row * 64 + col) = o;
                }
            }
    }
}

// ---------------------------------------------------------------------------
// Kernel 1.25: reduce conv partials + bias, LayerNorm, KV projection. (unchanged)
// ---------------------------------------------------------------------------
__global__ void __launch_bounds__(512) k_lnkv(
    const float* __restrict__ srb, const float* __restrict__ lng,
    const float* __restrict__ lnb, const float* __restrict__ Wkv)
{
    __shared__ float co[1024];
    __shared__ float ln[1024];
    int ph = blockIdx.x, b = blockIdx.y;
    int t = threadIdx.x;
    int gbase = (b * 2 + (ph >> 3)) * 128 + (ph & 7) * 16;

    if (t < 256) {
        int pw = t >> 4, c4 = t & 15;
        float4 s = make_float4(0.f, 0.f, 0.f, 0.f);
        #pragma unroll
        for (int kh = 0; kh < 8; kh++) {
            float4 v = *(const float4*)(g_cacc + ((size_t)kh * 2048 + gbase + pw) * 64 + c4 * 4);
            s.x += v.x; s.y += v.y; s.z += v.z; s.w += v.w;
        }
        float4 bb = *(const float4*)(srb + c4 * 4);
        s.x += bb.x; s.y += bb.y; s.z += bb.z; s.w += bb.w;
        *(float4*)(co + pw * 64 + c4 * 4) = s;
    }
    __syncthreads();

    int warp = t >> 5, lane = t & 31;
    {
        float v0 = co[warp * 64 + lane];
        float v1 = co[warp * 64 + lane + 32];
        float s = v0 + v1, sq = v0 * v0 + v1 * v1;
        #pragma unroll
        for (int off = 16; off; off >>= 1) {
            s  += __shfl_xor_sync(0xffffffffu, s, off);
            sq += __shfl_xor_sync(0xffffffffu, sq, off);
        }
        float mean = s * (1.f / 64.f);
        float var  = sq * (1.f / 64.f) - mean * mean;
        float rs = rsqrtf(var + 1e-5f);
        ln[warp * 64 + lane]      = (v0 - mean) * rs * lng[lane]      + lnb[lane];
        ln[warp * 64 + lane + 32] = (v1 - mean) * rs * lng[lane + 32] + lnb[lane + 32];
    }
    __syncthreads();

    int c = t & 127, pg = t >> 7;
    float acc[4] = {0.f, 0.f, 0.f, 0.f};
    for (int i = 0; i < 64; i++) {
        float wv = Wkv[i * 128 + c];
        #pragma unroll
        for (int m = 0; m < 4; m++)
            acc[m] = fmaf(ln[(pg * 4 + m) * 64 + i], wv, acc[m]);
    }
    #pragma unroll
    for (int m = 0; m < 4; m++) {
        int p = ph * 16 + pg * 4 + m;
        if (c < 64) g_k[(b * 64 + c) * NK + p]        = acc[m];
        else        g_v[(b * NK + p) * 64 + (c - 64)] = acc[m];
    }
}

// ---------------------------------------------------------------------------
// Kernel 1.5: fold projections -> bf16 operands. cp.async staging, 8 slices.
// grid (8 b, 2 z, 8 sl), 512 threads. smem: max(512+16384, 4096+2176) floats.
// ---------------------------------------------------------------------------
#define FOLD_SMEM 67584

__global__ void __launch_bounds__(512) k_fold(
    const float* __restrict__ Wq, const float* __restrict__ Wp)
{
    extern __shared__ float fs[];
    uint32_t sb = smem_u32(fs);
    int b = blockIdx.x, z = blockIdx.y, sl = blockIdx.z;
    int t = threadIdx.x;

    if (z == 0) {
        int c0 = sl * 8;                       // 8 Wq rows for this slice
        if (t < 128) cp16(sb + t * 16, (const float4*)Wq + c0 * 16 + t);
        const float4* gk4 = (const float4*)g_k + b * 4096;
        for (int i = t; i < 4096; i += 512)
            cp16(sb + 2048 + i * 16, gk4 + i);
        CP_COMMIT(); CP_WAIT0();
        __syncthreads();
        const float* wq = fs;                  // [8 c][64 d]
        const float* ks = fs + 512;            // [64 d][256 p]
        uint32_t* mh = g_mh + b * 8192;
        #pragma unroll
        for (int u = 0; u < 2; u++) {
            int idx = sl * 1024 + u * 512 + t;
            int c = idx >> 7, pp = idx & 127;
            int cl = c - c0;
            float m0 = 0.f, m1 = 0.f;
            for (int d = 0; d < 64; d++) {
                float w = wq[cl * 64 + d];
                m0 = fmaf(w, ks[d * 256 + 2 * pp],     m0);
                m1 = fmaf(w, ks[d * 256 + 2 * pp + 1], m1);
            }
            mh[idx] = pack_bf16(m0 * SCALE, m1 * SCALE);
        }
    } else {
        int p0 = sl * 32;                      // 32 v rows for this slice
        for (int i = t; i < 1024; i += 512)
            cp16(sb + i * 16, (const float4*)Wp + i);
        if (t < 512) {
            int r = t >> 4, c4 = t & 15;
            cp16(sb + 16384 + (r * 68 + c4 * 4) * 4,
                 (const float4*)g_v + b * 4096 + p0 * 16 + t);
        }
        CP_COMMIT(); CP_WAIT0();
        __syncthreads();
        const float* wp = fs;                  // [64 c][64 e]
        const float* vs = fs + 4096;           // [32 p][68]
        uint32_t* vh = g_vh + b * 8192;
        #pragma unroll
        for (int u = 0; u < 2; u++) {
            int idx = sl * 1024 + u * 512 + t;
            int p = idx >> 5, ee = idx & 31;
            int pl = p - p0;
            float a0 = 0.f, a1 = 0.f;
            for (int c = 0; c < 64; c++) {
                float v = vs[pl * 68 + c];
                a0 = fmaf(v, wp[c * 64 + 2 * ee],     a0);
                a1 = fmaf(v, wp[c * 64 + 2 * ee + 1], a1);
            }
            vh[idx] = pack_bf16(a0, a1);
            atomicAdd(&g_vsum[b * 64 + 2 * ee],     a0);
            atomicAdd(&g_vsum[b * 64 + 2 * ee + 1], a1);
        }
    }
}

// ---------------------------------------------------------------------------
// Kernel 2: persistent HMMA attention, 4 decoupled 128-thread pipelines
// (named barriers). grid (16, 8), 512 threads.
// ---------------------------------------------------------------------------
#define SA1 144
#define SB1 528
#define SE  528
#define SB2 144
#define XS0_ 0
#define A1H_ 65536
#define B1H_ 83968
#define E_   117760
#define B2H_ 185344
#define PSUM_ 222208
#define SMEM_ASK 224256

__global__ void __launch_bounds__(512, 1) k_attn_mma(
    const float* __restrict__ x, const float* __restrict__ bp,
    float* __restrict__ out)
{
    extern __shared__ char sm[];
    uint32_t sb = smem_u32(sm);
    int t = threadIdx.x;
    int L = t & 31, w = t >> 5;
    int bx = blockIdx.x, b = blockIdx.y;
    int wr = w >> 2, wc = w & 3;
    int m0 = wr * 32;
    int tg = t & 127;                  // index within 128-thread group (grp == wr)
    int bar = 8 + wr;

    // ---- prologue: B1h/B2h by all threads; XS0 rows by owning group ----
    {
        const char* mh = (const char*)(g_mh + b * 8192);
        for (int i = t; i < 2048; i += 512) {
            int r1 = i >> 5, c1 = i & 31;
            cp16(sb + B1H_ + r1 * SB1 + c1 * 16, mh + i * 16);
        }
        const char* vh = (const char*)(g_vh + b * 8192);
        for (int i = t; i < 2048; i += 512) {
            int r2 = i >> 3, c2 = i & 7;
            cp16(sb + B2H_ + r2 * SB2 + c2 * 16, vh + i * 16);
        }
        const char* xsrc = (const char*)(x + ((size_t)b * NTOK + (size_t)bx * 1024 + m0) * 64);
        for (int i = tg; i < 512; i += 128)
            cp16(sb + XS0_ + m0 * 256 + i * 16, xsrc + i * 16);
        CP_COMMIT();
    }

    for (int j = 0; j < 8; j++) {
        int q0 = bx * 1024 + j * 128;
        if (j < 7) {
            const char* xsrc = (const char*)(x + ((size_t)b * NTOK + q0 + 128 + m0) * 64);
            uint32_t dst = sb + XS0_ + ((j + 1) & 1) * 32768 + m0 * 256;
            for (int i = tg; i < 512; i += 128)
                cp16(dst + i * 16, xsrc + i * 16);
            CP_COMMIT();
            CP_WAIT1();
        } else {
            CP_WAIT0();
        }
        if (j == 0) __syncthreads();       // B operands + XS0 visible CTA-wide
        else        NBAR(bar);             // group's XS rows visible

        // ---- convert own 32 x rows -> A1h bf16 (stride 144) ----
        {
            const float2* xs2 = (const float2*)(sm + XS0_ + (j & 1) * 32768);
            uint32_t* ah = (uint32_t*)(sm + A1H_);
            #pragma unroll
            for (int k = 0; k < 8; k++) {
                int f = tg + k * 128;            // 0..1023 pair cells for this group
                int row = m0 + (f >> 5), cp = f & 31;
                float2 v = xs2[row * 32 + cp];
                ah[row * 36 + cp] = pack_bf16(v.x, v.y);
            }
        }
        NBAR(bar);                         // A rows ready for this group

        // ================= GEMM1: S = x @ M (1-term bf16) =================
        float acc[2][8][4];
        #pragma unroll
        for (int i = 0; i < 2; i++)
            #pragma unroll
            for (int jj = 0; jj < 8; jj++)
                #pragma unroll
                for (int k = 0; k < 4; k++) acc[i][jj][k] = 0.f;

        {
            int n0 = wc * 64;
            uint32_t a_lane = (uint32_t)((L & 15) * SA1 + (L >> 4) * 16);
            uint32_t b_lane = (uint32_t)(((L & 7) + 8 * ((L >> 3) & 1)) * SB1 + (L >> 4) * 16);
            uint32_t abase = sb + A1H_ + m0 * SA1 + a_lane;
            uint32_t bbase = sb + B1H_ + n0 * 2 + b_lane;
            #pragma unroll
            for (int kc = 0; kc < 4; kc++) {
                uint32_t af[2][4];
                LDSM4(af[0], abase + kc * 32);
                LDSM4(af[1], abase + 16 * SA1 + kc * 32);
                uint32_t bf[4][4];
                #pragma unroll
                for (int jj = 0; jj < 4; jj++)
                    LDSM4T(bf[jj], bbase + kc * 16 * SB1 + jj * 32);
                #pragma unroll
                for (int i = 0; i < 2; i++)
                    #pragma unroll
                    for (int jj = 0; jj < 4; jj++) {
                        MMA_BF16(acc[i][2 * jj],     af[i], bf[jj][0], bf[jj][1]);
                        MMA_BF16(acc[i][2 * jj + 1], af[i], bf[jj][2], bf[jj][3]);
                    }
            }
        }

        // ============ exp + row sums + store (E-1) as single bf16 ============
        {
            int n0 = wc * 64;
            float rs[4] = {0.f, 0.f, 0.f, 0.f};
            #pragma unroll
            for (int i = 0; i < 2; i++) {
                int r0 = m0 + i * 16 + (L >> 2);
                #pragma unroll
                for (int jj = 0; jj < 8; jj++) {
                    float e0 = __expf(acc[i][jj][0]);
                    float e1 = __expf(acc[i][jj][1]);
                    float e2 = __expf(acc[i][jj][2]);
                    float e3 = __expf(acc[i][jj][3]);
                    rs[i * 2]     += e0 + e1;
                    rs[i * 2 + 1] += e2 + e3;
                    int cb = (n0 + jj * 8 + 2 * (L & 3)) * 2;
                    *(uint32_t*)(sm + E_ + r0 * SE + cb)       = pack_bf16(e0 - 1.f, e1 - 1.f);
                    *(uint32_t*)(sm + E_ + (r0 + 8) * SE + cb) = pack_bf16(e2 - 1.f, e3 - 1.f);
                }
            }
            #pragma unroll
            for (int k = 0; k < 4; k++) {
                rs[k] += __shfl_xor_sync(0xffffffffu, rs[k], 1);
                rs[k] += __shfl_xor_sync(0xffffffffu, rs[k], 2);
            }
            if ((L & 3) == 0) {
                float* ps = (float*)(sm + PSUM_);
                #pragma unroll
                for (int i = 0; i < 2; i++)
                    #pragma unroll
                    for (int h = 0; h < 2; h++) {
                        int row = m0 + i * 16 + 8 * h + (L >> 2);
                        ps[row * 4 + wc] = rs[i * 2 + h];
                    }
            }
        }
        NBAR(bar);                         // E + PSUM ready for this group

        // ========= GEMM2: D2 = (E-1) @ V'hi (single term) =========
        float acc2[2][2][4];
        #pragma unroll
        for (int i = 0; i < 2; i++)
            #pragma unroll
            for (int jj = 0; jj < 2; jj++)
                #pragma unroll
                for (int k = 0; k < 4; k++) acc2[i][jj][k] = 0.f;

        {
            int n2 = wc * 16;
            uint32_t a_lane = (uint32_t)((L & 15) * SE + (L >> 4) * 16);
            uint32_t b_lane = (uint32_t)(((L & 7) + 8 * ((L >> 3) & 1)) * SB2 + (L >> 4) * 16);
            uint32_t abase = sb + E_ + m0 * SE + a_lane;
            uint32_t bbase = sb + B2H_ + n2 * 2 + b_lane;
            #pragma unroll
            for (int kc = 0; kc < 16; kc++) {
                uint32_t af[2][4];
                LDSM4(af[0], abase + kc * 32);
                LDSM4(af[1], abase + 16 * SE + kc * 32);
                uint32_t bf[4];
                LDSM4T(bf, bbase + kc * 16 * SB2);
                MMA_BF16(acc2[0][0], af[0], bf[0], bf[1]);
                MMA_BF16(acc2[0][1], af[0], bf[2], bf[3]);
                MMA_BF16(acc2[1][0], af[1], bf[0], bf[1]);
                MMA_BF16(acc2[1][1], af[1], bf[2], bf[3]);
            }
        }

        // ===== epilogue: out = (D2 + Svsum)/rowsum + bias =====
        {
            int n2 = wc * 16;
            const float* ps = (const float*)(sm + PSUM_);
            const float* sv = g_vsum + b * 64;
            #pragma unroll
            for (int i = 0; i < 2; i++)
                #pragma unroll
                for (int h = 0; h < 2; h++) {
                    int row = m0 + i * 16 + 8 * h + (L >> 2);
                    float4 p4 = *(const float4*)(ps + row * 4);
                    float inv = 1.f / (p4.x + p4.y + p4.z + p4.w);
                    float* og = out + ((size_t)(b * NTOK) + q0 + row) * 64;
                    #pragma unroll
                    for (int jj = 0; jj < 2; jj++) {
                        int c = n2 + jj * 8 + 2 * (L & 3);
                        float2 bb = *(const float2*)(bp + c);
                        float2 ss = *(const float2*)(sv + c);
                        float2 o;
                        o.x = (acc2[i][jj][2 * h]     + ss.x) * inv + bb.x;
                        o.y = (acc2[i][jj][2 * h + 1] + ss.y) * inv + bb.y;
                        *(float2*)(og + c) = o;
                    }
                }
        }
    }
}

// ---------------------------------------------------------------------------
extern "C" void kernel_launch(void* const* d_in, const int* in_sizes, int n_in,
                              void* d_out, int out_size) {
    const float* x   = (const float*)d_in[0];
    const float* Wq  = (const float*)d_in[1];
    const float* Wkv = (const float*)d_in[2];
    const float* Wp  = (const float*)d_in[3];
    const float* bp  = (const float*)d_in[4];
    const float* srw = (const float*)d_in[5];
    const float* srb = (const float*)d_in[6];
    const float* lng = (const float*)d_in[7];
    const float* lnb = (const float*)d_in[8];
    float* out = (float*)d_out;

    cudaFuncSetAttribute(k_conv, cudaFuncAttributeMaxDynamicSharedMemorySize, CONV_SMEM);
    cudaFuncSetAttribute(k_fold, cudaFuncAttributeMaxDynamicSharedMemorySize, FOLD_SMEM);
    cudaFuncSetAttribute(k_attn_mma, cudaFuncAttributeMaxDynamicSharedMemorySize, SMEM_ASK);

    k_transpose_w<<<288, 512>>>(srw);
    k_conv<<<dim3(16, 8), 512, CONV_SMEM>>>(x);
    k_lnkv<<<dim3(16, 8), 512>>>(srb, lng, lnb, Wkv);
    k_fold<<<dim3(8, 2, 8), 512, FOLD_SMEM>>>(Wq, Wp);
    k_attn_mma<<<dim3(16, 8), 512, SMEM_ASK>>>(x, bp, out);
}

// round 13
// speedup vs baseline: 4.5983x; 1.1115x over previous
#include <cuda_runtime.h>
#include <cuda_bf16.h>
#include <cstdint>

#define BATCH 8
#define NTOK  16384
#define NK    256
#define SCALE 0.125f
#define SCALE_L2E 0.18033688f   // SCALE * log2(e)

// ---------------- scratch (allocation-free rule) ----------------
__device__ uint32_t g_wbh[32 * 4608];        // conv W bf16-hi, padded slabs [s][128][36 words]
__device__ uint32_t g_wbl[32 * 4608];        // conv W bf16-lo
__device__ float    g_cacc[8 * 2048 * 64];   // conv partials per kh
__device__ float    g_k[BATCH * 64 * NK];    // [b][d][p] fp32
__device__ float    g_v[BATCH * NK * 64];    // [b][p][c] fp32
__device__ uint32_t g_mh[BATCH * 8192];      // M bf16 pairs (pre-scaled by SCALE*log2e)
__device__ uint32_t g_vh[BATCH * 8192];      // V' bf16 pairs: [p][e/2]
__device__ float    g_vsum[BATCH * 64];      // fp32 column sums of V'

// ---------------- helpers ----------------
__device__ __forceinline__ uint32_t smem_u32(const void* p) {
    uint32_t a;
    asm("{ .reg .u64 t; cvta.to.shared.u64 t, %1; cvt.u32.u64 %0, t; }" : "=r"(a) : "l"(p));
    return a;
}
__device__ __forceinline__ uint32_t pack_bf16(float a, float b) {
    uint32_t r;   // r = {hi: bf16(b), lo: bf16(a)}
    asm("cvt.rn.bf16x2.f32 %0, %1, %2;" : "=r"(r) : "f"(b), "f"(a));
    return r;
}
__device__ __forceinline__ void split_pair(float a, float b, uint32_t& hp, uint32_t& lp) {
    uint32_t h;
    asm("cvt.rn.bf16x2.f32 %0, %1, %2;" : "=r"(h) : "f"(b), "f"(a));
    float ah = __uint_as_float(h << 16);
    float bh = __uint_as_float(h & 0xffff0000u);
    uint32_t l;
    float la = a - ah, lb = b - bh;
    asm("cvt.rn.bf16x2.f32 %0, %1, %2;" : "=r"(l) : "f"(lb), "f"(la));
    hp = h; lp = l;
}
__device__ __forceinline__ float ex2(float x) {
    float r; asm("ex2.approx.f32 %0, %1;" : "=f"(r) : "f"(x)); return r;
}

#define LDSM4(r, addr) \
    asm volatile("ldmatrix.sync.aligned.m8n8.x4.shared.b16 {%0,%1,%2,%3}, [%4];" \
        : "=r"((r)[0]), "=r"((r)[1]), "=r"((r)[2]), "=r"((r)[3]) : "r"(addr))
#define LDSM4T(r, addr) \
    asm volatile("ldmatrix.sync.aligned.m8n8.x4.trans.shared.b16 {%0,%1,%2,%3}, [%4];" \
        : "=r"((r)[0]), "=r"((r)[1]), "=r"((r)[2]), "=r"((r)[3]) : "r"(addr))
#define MMA_BF16(d, a, b0, b1) \
    asm volatile("mma.sync.aligned.m16n8k16.row.col.f32.bf16.bf16.f32 " \
        "{%0,%1,%2,%3}, {%4,%5,%6,%7}, {%8,%9}, {%0,%1,%2,%3};" \
        : "+f"((d)[0]), "+f"((d)[1]), "+f"((d)[2]), "+f"((d)[3]) \
        : "r"((a)[0]), "r"((a)[1]), "r"((a)[2]), "r"((a)[3]), "r"(b0), "r"(b1))

__device__ __forceinline__ void cp16(uint32_t s, const void* g) {
    asm volatile("cp.async.cg.shared.global [%0], [%1], 16;" :: "r"(s), "l"(g));
}
#define CP_COMMIT() asm volatile("cp.async.commit_group;" ::: "memory")
#define CP_WAIT1()  asm volatile("cp.async.wait_group 1;" ::: "memory")
#define CP_WAIT0()  asm volatile("cp.async.wait_group 0;" ::: "memory")
#define NBAR(id)    asm volatile("bar.sync %0, 128;" :: "r"(id) : "memory")

// ---------------------------------------------------------------------------
// Kernel 0: conv weights -> bf16 hi/lo padded slabs; zero g_vsum.
// ---------------------------------------------------------------------------
__global__ void k_transpose_w(const float* __restrict__ srw) {
    int d = blockIdx.x * 512 + threadIdx.x;    // 288*512 = 147456 = 32*4608
    if (d < BATCH * 64) g_vsum[d] = 0.f;
    int s = d / 4608;
    int r = d - s * 4608;
    int k = r / 36;
    int ow = r - k * 36;
    uint32_t hi = 0, lo = 0;
    if (ow < 32) {
        int kh = s >> 2, ic = s & 3;
        int kw = k >> 4, ii = k & 15;
        int i = ic * 16 + ii;
        float v0 = srw[(2 * ow) * 4096 + i * 64 + kh * 8 + kw];
        float v1 = srw[(2 * ow + 1) * 4096 + i * 64 + kh * 8 + kw];
        split_pair(v0, v1, hi, lo);
    }
    g_wbh[d] = hi;
    g_wbl[d] = lo;
}

// ---------------------------------------------------------------------------
// Kernel 1: conv-as-GEMM, 3-term bf16 (AhWh + AlWh + AhWl). grid (16,8).
// SMEM: W[2 buf][hi 18432 | lo 18432] @0 (73728), AH@73728, AL@108544
// ---------------------------------------------------------------------------
#define CW_BUF 36864
#define CW_LO  18432
#define CA_H   73728
#define CA_L   108544
#define CONV_SMEM 143360

__global__ void __launch_bounds__(512, 1) k_conv(const float* __restrict__ x) {
    extern __shared__ char sm[];
    uint32_t sb = smem_u32(sm);
    int t = threadIdx.x;
    int L = t & 31, w = t >> 5;
    int pt = blockIdx.x, kh = blockIdx.y;
    int b = pt >> 1, half = pt & 1;
    int wr = w >> 2, wc = w & 3;
    int m0 = wr * 32, n0 = wc * 16;

    auto issueW = [&](int st, int buf) {
        int s = kh * 4 + st;
        const char* srch = (const char*)g_wbh + (size_t)s * 18432;
        const char* srcl = (const char*)g_wbl + (size_t)s * 18432;
        uint32_t dst = sb + buf * CW_BUF;
        for (int i = t; i < 1152; i += 512) {
            cp16(dst + i * 16, srch + i * 16);
            cp16(dst + CW_LO + i * 16, srcl + i * 16);
        }
    };

    float acc[2][2][4];
    #pragma unroll
    for (int i = 0; i < 2; i++)
        #pragma unroll
        for (int j = 0; j < 2; j++)
            #pragma unroll
            for (int k = 0; k < 4; k++) acc[i][j][k] = 0.f;

    issueW(0, 0);
    CP_COMMIT();

    const float* xb = x + (size_t)b * NTOK * 64;
    for (int st = 0; st < 4; st++) {
        if (st < 3) { issueW(st + 1, (st + 1) & 1); CP_COMMIT(); }
        {
            uint32_t* ah = (uint32_t*)(sm + CA_H);
            uint32_t* al = (uint32_t*)(sm + CA_L);
            #pragma unroll
            for (int it = 0; it < 16; it++) {
                int idx = it * 512 + t;
                int m = idx >> 6, pr = idx & 63;
                int kw = pr >> 3, ip = pr & 7;
                int ph = half * 8 + (m >> 4);
                int grow = (ph * 8 + kh) * 128 + (m & 15) * 8 + kw;
                float2 v = *(const float2*)(xb + (size_t)grow * 64 + st * 16 + ip * 2);
                uint32_t hp, lp;
                split_pair(v.x, v.y, hp, lp);
                int wo = m * 68 + kw * 8 + ip;
                ah[wo] = hp; al[wo] = lp;
            }
        }
        if (st < 3) CP_WAIT1(); else CP_WAIT0();
        __syncthreads();

        {
            uint32_t a_lane = (uint32_t)((L & 15) * 272 + (L >> 4) * 16);
            uint32_t b_lane = (uint32_t)(((L & 7) + 8 * ((L >> 3) & 1)) * 144 + (L >> 4) * 16);
            uint32_t wbase = sb + (st & 1) * CW_BUF;
            const int aoffs[3] = {CA_H, CA_L, CA_H};
            const int boffs[3] = {0, 0, CW_LO};
            #pragma unroll
            for (int term = 0; term < 3; term++) {
                uint32_t abase = sb + aoffs[term] + m0 * 272 + a_lane;
                uint32_t bbase = wbase + boffs[term] + n0 * 2 + b_lane;
                #pragma unroll
                for (int kc = 0; kc < 8; kc++) {
                    uint32_t af[2][4];
                    LDSM4(af[0], abase + kc * 32);
                    LDSM4(af[1], abase + 16 * 272 + kc * 32);
                    uint32_t bf[4];
                    LDSM4T(bf, bbase + kc * 16 * 144);
                    MMA_BF16(acc[0][0], af[0], bf[0], bf[1]);
                    MMA_BF16(acc[0][1], af[0], bf[2], bf[3]);
                    MMA_BF16(acc[1][0], af[1], bf[0], bf[1]);
                    MMA_BF16(acc[1][1], af[1], bf[2], bf[3]);
                }
            }
        }
        __syncthreads();
    }

    {
        float* gc = g_cacc + ((size_t)kh * 2048 + pt * 128) * 64;
        #pragma unroll
        for (int i = 0; i < 2; i++)
            #pragma unroll
            for (int h = 0; h < 2; h++) {
                int row = m0 + i * 16 + 8 * h + (L >> 2);
                #pragma unroll
                for (int jj = 0; jj < 2; jj++) {
                    int col = n0 + jj * 8 + 2 * (L & 3);
                    float2 o = make_float2(acc[i][jj][2 * h], acc[i][jj][2 * h + 1]);
                    *(float2*)(gc + row * 64 + col) = o;
                }
            }
    }
}

// ---------------------------------------------------------------------------
// Kernel 1.25: reduce conv partials + bias, LayerNorm, KV projection.
// ---------------------------------------------------------------------------
__global__ void __launch_bounds__(512) k_lnkv(
    const float* __restrict__ srb, const float* __restrict__ lng,
    const float* __restrict__ lnb, const float* __restrict__ Wkv)
{
    __shared__ float co[1024];
    __shared__ float ln[1024];
    int ph = blockIdx.x, b = blockIdx.y;
    int t = threadIdx.x;
    int gbase = (b * 2 + (ph >> 3)) * 128 + (ph & 7) * 16;

    if (t < 256) {
        int pw = t >> 4, c4 = t & 15;
        float4 s = make_float4(0.f, 0.f, 0.f, 0.f);
        #pragma unroll
        for (int kh = 0; kh < 8; kh++) {
            float4 v = *(const float4*)(g_cacc + ((size_t)kh * 2048 + gbase + pw) * 64 + c4 * 4);
            s.x += v.x; s.y += v.y; s.z += v.z; s.w += v.w;
        }
        float4 bb = *(const float4*)(srb + c4 * 4);
        s.x += bb.x; s.y += bb.y; s.z += bb.z; s.w += bb.w;
        *(float4*)(co + pw * 64 + c4 * 4) = s;
    }
    __syncthreads();

    int warp = t >> 5, lane = t & 31;
    {
        float v0 = co[warp * 64 + lane];
        float v1 = co[warp * 64 + lane + 32];
        float s = v0 + v1, sq = v0 * v0 + v1 * v1;
        #pragma unroll
        for (int off = 16; off; off >>= 1) {
            s  += __shfl_xor_sync(0xffffffffu, s, off);
            sq += __shfl_xor_sync(0xffffffffu, sq, off);
        }
        float mean = s * (1.f / 64.f);
        float var  = sq * (1.f / 64.f) - mean * mean;
        float rs = rsqrtf(var + 1e-5f);
        ln[warp * 64 + lane]      = (v0 - mean) * rs * lng[lane]      + lnb[lane];
        ln[warp * 64 + lane + 32] = (v1 - mean) * rs * lng[lane + 32] + lnb[lane + 32];
    }
    __syncthreads();

    int c = t & 127, pg = t >> 7;
    float acc[4] = {0.f, 0.f, 0.f, 0.f};
    #pragma unroll 8
    for (int i = 0; i < 64; i++) {
        float wv = Wkv[i * 128 + c];
        #pragma unroll
        for (int m = 0; m < 4; m++)
            acc[m] = fmaf(ln[(pg * 4 + m) * 64 + i], wv, acc[m]);
    }
    #pragma unroll
    for (int m = 0; m < 4; m++) {
        int p = ph * 16 + pg * 4 + m;
        if (c < 64) g_k[(b * 64 + c) * NK + p]        = acc[m];
        else        g_v[(b * NK + p) * 64 + (c - 64)] = acc[m];
    }
}

// ---------------------------------------------------------------------------
// Kernel 1.5: fold projections -> bf16 operands. M pre-scaled by SCALE*log2e.
// grid (8 b, 2 z, 8 sl), 512 threads.
// ---------------------------------------------------------------------------
#define FOLD_SMEM 67584

__global__ void __launch_bounds__(512) k_fold(
    const float* __restrict__ Wq, const float* __restrict__ Wp)
{
    extern __shared__ float fs[];
    uint32_t sb = smem_u32(fs);
    int b = blockIdx.x, z = blockIdx.y, sl = blockIdx.z;
    int t = threadIdx.x;

    if (z == 0) {
        int c0 = sl * 8;
        if (t < 128) cp16(sb + t * 16, (const float4*)Wq + c0 * 16 + t);
        const float4* gk4 = (const float4*)g_k + b * 4096;
        for (int i = t; i < 4096; i += 512)
            cp16(sb + 2048 + i * 16, gk4 + i);
        CP_COMMIT(); CP_WAIT0();
        __syncthreads();
        const float* wq = fs;
        const float* ks = fs + 512;
        uint32_t* mh = g_mh + b * 8192;
        #pragma unroll
        for (int u = 0; u < 2; u++) {
            int idx = sl * 1024 + u * 512 + t;
            int c = idx >> 7, pp = idx & 127;
            int cl = c - c0;
            float m0 = 0.f, m1 = 0.f;
            #pragma unroll 8
            for (int d = 0; d < 64; d++) {
                float w = wq[cl * 64 + d];
                m0 = fmaf(w, ks[d * 256 + 2 * pp],     m0);
                m1 = fmaf(w, ks[d * 256 + 2 * pp + 1], m1);
            }
            mh[idx] = pack_bf16(m0 * SCALE_L2E, m1 * SCALE_L2E);
        }
    } else {
        int p0 = sl * 32;
        for (int i = t; i < 1024; i += 512)
            cp16(sb + i * 16, (const float4*)Wp + i);
        if (t < 512) {
            int r = t >> 4, c4 = t & 15;
            cp16(sb + 16384 + (r * 68 + c4 * 4) * 4,
                 (const float4*)g_v + b * 4096 + p0 * 16 + t);
        }
        CP_COMMIT(); CP_WAIT0();
        __syncthreads();
        const float* wp = fs;
        const float* vs = fs + 4096;
        uint32_t* vh = g_vh + b * 8192;
        #pragma unroll
        for (int u = 0; u < 2; u++) {
            int idx = sl * 1024 + u * 512 + t;
            int p = idx >> 5, ee = idx & 31;
            int pl = p - p0;
            float a0 = 0.f, a1 = 0.f;
            #pragma unroll 8
            for (int c = 0; c < 64; c++) {
                float v = vs[pl * 68 + c];
                a0 = fmaf(v, wp[c * 64 + 2 * ee],     a0);
                a1 = fmaf(v, wp[c * 64 + 2 * ee + 1], a1);
            }
            vh[idx] = pack_bf16(a0, a1);
            atomicAdd(&g_vsum[b * 64 + 2 * ee],     a0);
            atomicAdd(&g_vsum[b * 64 + 2 * ee + 1], a1);
        }
    }
}

// ---------------------------------------------------------------------------
// Kernel 2: persistent HMMA attention, 4 decoupled 128-thread pipelines.
// E = 2^s (M pre-scaled) via ex2.approx. grid (16, 8), 512 threads.
// ---------------------------------------------------------------------------
#define SA1 144
#define SB1 528
#define SE  528
#define SB2 144
#define XS0_ 0
#define A1H_ 65536
#define B1H_ 83968
#define E_   117760
#define B2H_ 185344
#define PSUM_ 222208
#define SMEM_ASK 224256

__global__ void __launch_bounds__(512, 1) k_attn_mma(
    const float* __restrict__ x, const float* __restrict__ bp,
    float* __restrict__ out)
{
    extern __shared__ char sm[];
    uint32_t sb = smem_u32(sm);
    int t = threadIdx.x;
    int L = t & 31, w = t >> 5;
    int bx = blockIdx.x, b = blockIdx.y;
    int wr = w >> 2, wc = w & 3;
    int m0 = wr * 32;
    int tg = t & 127;
    int bar = 8 + wr;

    {
        const char* mh = (const char*)(g_mh + b * 8192);
        for (int i = t; i < 2048; i += 512) {
            int r1 = i >> 5, c1 = i & 31;
            cp16(sb + B1H_ + r1 * SB1 + c1 * 16, mh + i * 16);
        }
        const char* vh = (const char*)(g_vh + b * 8192);
        for (int i = t; i < 2048; i += 512) {
            int r2 = i >> 3, c2 = i & 7;
            cp16(sb + B2H_ + r2 * SB2 + c2 * 16, vh + i * 16);
        }
        const char* xsrc = (const char*)(x + ((size_t)b * NTOK + (size_t)bx * 1024 + m0) * 64);
        for (int i = tg; i < 512; i += 128)
            cp16(sb + XS0_ + m0 * 256 + i * 16, xsrc + i * 16);
        CP_COMMIT();
    }

    for (int j = 0; j < 8; j++) {
        int q0 = bx * 1024 + j * 128;
        if (j < 7) {
            const char* xsrc = (const char*)(x + ((size_t)b * NTOK + q0 + 128 + m0) * 64);
            uint32_t dst = sb + XS0_ + ((j + 1) & 1) * 32768 + m0 * 256;
            for (int i = tg; i < 512; i += 128)
                cp16(dst + i * 16, xsrc + i * 16);
            CP_COMMIT();
            CP_WAIT1();
        } else {
            CP_WAIT0();
        }
        if (j == 0) __syncthreads();
        else        NBAR(bar);

        {
            const float2* xs2 = (const float2*)(sm + XS0_ + (j & 1) * 32768);
            uint32_t* ah = (uint32_t*)(sm + A1H_);
            #pragma unroll
            for (int k = 0; k < 8; k++) {
                int f = tg + k * 128;
                int row = m0 + (f >> 5), cp = f & 31;
                float2 v = xs2[row * 32 + cp];
                ah[row * 36 + cp] = pack_bf16(v.x, v.y);
            }
        }
        NBAR(bar);

        // ================= GEMM1: S = x @ M (1-term bf16) =================
        float acc[2][8][4];
        #pragma unroll
        for (int i = 0; i < 2; i++)
            #pragma unroll
            for (int jj = 0; jj < 8; jj++)
                #pragma unroll
                for (int k = 0; k < 4; k++) acc[i][jj][k] = 0.f;

        {
            int n0 = wc * 64;
            uint32_t a_lane = (uint32_t)((L & 15) * SA1 + (L >> 4) * 16);
            uint32_t b_lane = (uint32_t)(((L & 7) + 8 * ((L >> 3) & 1)) * SB1 + (L >> 4) * 16);
            uint32_t abase = sb + A1H_ + m0 * SA1 + a_lane;
            uint32_t bbase = sb + B1H_ + n0 * 2 + b_lane;
            #pragma unroll
            for (int kc = 0; kc < 4; kc++) {
                uint32_t af[2][4];
                LDSM4(af[0], abase + kc * 32);
                LDSM4(af[1], abase + 16 * SA1 + kc * 32);
                uint32_t bf[4][4];
                #pragma unroll
                for (int jj = 0; jj < 4; jj++)
                    LDSM4T(bf[jj], bbase + kc * 16 * SB1 + jj * 32);
                #pragma unroll
                for (int i = 0; i < 2; i++)
                    #pragma unroll
                    for (int jj = 0; jj < 4; jj++) {
                        MMA_BF16(acc[i][2 * jj],     af[i], bf[jj][0], bf[jj][1]);
                        MMA_BF16(acc[i][2 * jj + 1], af[i], bf[jj][2], bf[jj][3]);
                    }
            }
        }

        // ============ E = 2^s ; row sums ; store (E-1) bf16 ============
        {
            int n0 = wc * 64;
            float rs[4] = {0.f, 0.f, 0.f, 0.f};
            #pragma unroll
            for (int i = 0; i < 2; i++) {
                int r0 = m0 + i * 16 + (L >> 2);
                #pragma unroll
                for (int jj = 0; jj < 8; jj++) {
                    float e0 = ex2(acc[i][jj][0]);
                    float e1 = ex2(acc[i][jj][1]);
                    float e2 = ex2(acc[i][jj][2]);
                    float e3 = ex2(acc[i][jj][3]);
                    rs[i * 2]     += e0 + e1;
                    rs[i * 2 + 1] += e2 + e3;
                    int cb = (n0 + jj * 8 + 2 * (L & 3)) * 2;
                    *(uint32_t*)(sm + E_ + r0 * SE + cb)       = pack_bf16(e0 - 1.f, e1 - 1.f);
                    *(uint32_t*)(sm + E_ + (r0 + 8) * SE + cb) = pack_bf16(e2 - 1.f, e3 - 1.f);
                }
            }
            #pragma unroll
            for (int k = 0; k < 4; k++) {
                rs[k] += __shfl_xor_sync(0xffffffffu, rs[k], 1);
                rs[k] += __shfl_xor_sync(0xffffffffu, rs[k], 2);
            }
            if ((L & 3) == 0) {
                float* ps = (float*)(sm + PSUM_);
                #pragma unroll
                for (int i = 0; i < 2; i++)
                    #pragma unroll
                    for (int h = 0; h < 2; h++) {
                        int row = m0 + i * 16 + 8 * h + (L >> 2);
                        ps[row * 4 + wc] = rs[i * 2 + h];
                    }
            }
        }
        NBAR(bar);

        // ========= GEMM2: D2 = (E-1) @ V'hi =========
        float acc2[2][2][4];
        #pragma unroll
        for (int i = 0; i < 2; i++)
            #pragma unroll
            for (int jj = 0; jj < 2; jj++)
                #pragma unroll
                for (int k = 0; k < 4; k++) acc2[i][jj][k] = 0.f;

        {
            int n2 = wc * 16;
            uint32_t a_lane = (uint32_t)((L & 15) * SE + (L >> 4) * 16);
            uint32_t b_lane = (uint32_t)(((L & 7) + 8 * ((L >> 3) & 1)) * SB2 + (L >> 4) * 16);
            uint32_t abase = sb + E_ + m0 * SE + a_lane;
            uint32_t bbase = sb + B2H_ + n2 * 2 + b_lane;
            #pragma unroll
            for (int kc = 0; kc < 16; kc++) {
                uint32_t af[2][4];
                LDSM4(af[0], abase + kc * 32);
                LDSM4(af[1], abase + 16 * SE + kc * 32);
                uint32_t bf[4];
                LDSM4T(bf, bbase + kc * 16 * SB2);
                MMA_BF16(acc2[0][0], af[0], bf[0], bf[1]);
                MMA_BF16(acc2[0][1], af[0], bf[2], bf[3]);
                MMA_BF16(acc2[1][0], af[1], bf[0], bf[1]);
                MMA_BF16(acc2[1][1], af[1], bf[2], bf[3]);
            }
        }

        // ===== epilogue: out = (D2 + Svsum)/rowsum + bias =====
        {
            int n2 = wc * 16;
            const float* ps = (const float*)(sm + PSUM_);
            const float* sv = g_vsum + b * 64;
            #pragma unroll
            for (int i = 0; i < 2; i++)
                #pragma unroll
                for (int h = 0; h < 2; h++) {
                    int row = m0 + i * 16 + 8 * h + (L >> 2);
                    float4 p4 = *(const float4*)(ps + row * 4);
                    float inv = 1.f / (p4.x + p4.y + p4.z + p4.w);
                    float* og = out + ((size_t)(b * NTOK) + q0 + row) * 64;
                    #pragma unroll
                    for (int jj = 0; jj < 2; jj++) {
                        int c = n2 + jj * 8 + 2 * (L & 3);
                        float2 bb = *(const float2*)(bp + c);
                        float2 ss = *(const float2*)(sv + c);
                        float2 o;
                        o.x = (acc2[i][jj][2 * h]     + ss.x) * inv + bb.x;
                        o.y = (acc2[i][jj][2 * h + 1] + ss.y) * inv + bb.y;
                        *(float2*)(og + c) = o;
                    }
                }
        }
    }
}

// ---------------------------------------------------------------------------
extern "C" void kernel_launch(void* const* d_in, const int* in_sizes, int n_in,
                              void* d_out, int out_size) {
    const float* x   = (const float*)d_in[0];
    const float* Wq  = (const float*)d_in[1];
    const float* Wkv = (const float*)d_in[2];
    const float* Wp  = (const float*)d_in[3];
    const float* bp  = (const float*)d_in[4];
    const float* srw = (const float*)d_in[5];
    const float* srb = (const float*)d_in[6];
    const float* lng = (const float*)d_in[7];
    const float* lnb = (const float*)d_in[8];
    float* out = (float*)d_out;

    cudaFuncSetAttribute(k_conv, cudaFuncAttributeMaxDynamicSharedMemorySize, CONV_SMEM);
    cudaFuncSetAttribute(k_fold, cudaFuncAttributeMaxDynamicSharedMemorySize, FOLD_SMEM);
    cudaFuncSetAttribute(k_attn_mma, cudaFuncAttributeMaxDynamicSharedMemorySize, SMEM_ASK);

    k_transpose_w<<<288, 512>>>(srw);
    k_conv<<<dim3(16, 8), 512, CONV_SMEM>>>(x);
    k_lnkv<<<dim3(16, 8), 512>>>(srb, lng, lnb, Wkv);
    k_fold<<<dim3(8, 2, 8), 512, FOLD_SMEM>>>(Wq, Wp);
    k_attn_mma<<<dim3(16, 8), 512, SMEM_ASK>>>(x, bp, out);
}

// round 14
// speedup vs baseline: 4.6928x; 1.0206x over previous
#include <cuda_runtime.h>
#include <cuda_bf16.h>
#include <cstdint>

#define BATCH 8
#define NTOK  16384
#define NK    256
#define SCALE 0.125f
#define SCALE_L2E 0.18033688f   // SCALE * log2(e)

// ---------------- scratch (allocation-free rule) ----------------
__device__ uint32_t g_wbh[32 * 4608];        // conv W bf16-hi, padded slabs [s][128][36 words]
__device__ uint32_t g_wbl[32 * 4608];        // conv W bf16-lo
__device__ float    g_cacc[8 * 2048 * 64];   // conv partials per kh
__device__ uint32_t g_mh[BATCH * 8192];      // M bf16 pairs (pre-scaled by SCALE*log2e)
__device__ uint32_t g_vh[BATCH * 8192];      // V' bf16 pairs: [p][e/2]
__device__ float    g_vsum[BATCH * 64];      // fp32 column sums of V'

// ---------------- helpers ----------------
__device__ __forceinline__ uint32_t smem_u32(const void* p) {
    uint32_t a;
    asm("{ .reg .u64 t; cvta.to.shared.u64 t, %1; cvt.u32.u64 %0, t; }" : "=r"(a) : "l"(p));
    return a;
}
__device__ __forceinline__ uint32_t pack_bf16(float a, float b) {
    uint32_t r;   // r = {hi: bf16(b), lo: bf16(a)}
    asm("cvt.rn.bf16x2.f32 %0, %1, %2;" : "=r"(r) : "f"(b), "f"(a));
    return r;
}
__device__ __forceinline__ void split_pair(float a, float b, uint32_t& hp, uint32_t& lp) {
    uint32_t h;
    asm("cvt.rn.bf16x2.f32 %0, %1, %2;" : "=r"(h) : "f"(b), "f"(a));
    float ah = __uint_as_float(h << 16);
    float bh = __uint_as_float(h & 0xffff0000u);
    uint32_t l;
    float la = a - ah, lb = b - bh;
    asm("cvt.rn.bf16x2.f32 %0, %1, %2;" : "=r"(l) : "f"(lb), "f"(la));
    hp = h; lp = l;
}
__device__ __forceinline__ float ex2(float x) {
    float r; asm("ex2.approx.f32 %0, %1;" : "=f"(r) : "f"(x)); return r;
}

#define LDSM4(r, addr) \
    asm volatile("ldmatrix.sync.aligned.m8n8.x4.shared.b16 {%0,%1,%2,%3}, [%4];" \
        : "=r"((r)[0]), "=r"((r)[1]), "=r"((r)[2]), "=r"((r)[3]) : "r"(addr))
#define LDSM4T(r, addr) \
    asm volatile("ldmatrix.sync.aligned.m8n8.x4.trans.shared.b16 {%0,%1,%2,%3}, [%4];" \
        : "=r"((r)[0]), "=r"((r)[1]), "=r"((r)[2]), "=r"((r)[3]) : "r"(addr))
#define MMA_BF16(d, a, b0, b1) \
    asm volatile("mma.sync.aligned.m16n8k16.row.col.f32.bf16.bf16.f32 " \
        "{%0,%1,%2,%3}, {%4,%5,%6,%7}, {%8,%9}, {%0,%1,%2,%3};" \
        : "+f"((d)[0]), "+f"((d)[1]), "+f"((d)[2]), "+f"((d)[3]) \
        : "r"((a)[0]), "r"((a)[1]), "r"((a)[2]), "r"((a)[3]), "r"(b0), "r"(b1))

__device__ __forceinline__ void cp16(uint32_t s, const void* g) {
    asm volatile("cp.async.cg.shared.global [%0], [%1], 16;" :: "r"(s), "l"(g));
}
#define CP_COMMIT() asm volatile("cp.async.commit_group;" ::: "memory")
#define CP_WAIT1()  asm volatile("cp.async.wait_group 1;" ::: "memory")
#define CP_WAIT0()  asm volatile("cp.async.wait_group 0;" ::: "memory")
#define NBAR(id)    asm volatile("bar.sync %0, 128;" :: "r"(id) : "memory")

// ---------------------------------------------------------------------------
// Kernel 0: conv weights -> bf16 hi/lo padded slabs; zero g_vsum.
// ---------------------------------------------------------------------------
__global__ void k_transpose_w(const float* __restrict__ srw) {
    int d = blockIdx.x * 512 + threadIdx.x;    // 288*512 = 147456 = 32*4608
    if (d < BATCH * 64) g_vsum[d] = 0.f;
    int s = d / 4608;
    int r = d - s * 4608;
    int k = r / 36;
    int ow = r - k * 36;
    uint32_t hi = 0, lo = 0;
    if (ow < 32) {
        int kh = s >> 2, ic = s & 3;
        int kw = k >> 4, ii = k & 15;
        int i = ic * 16 + ii;
        float v0 = srw[(2 * ow) * 4096 + i * 64 + kh * 8 + kw];
        float v1 = srw[(2 * ow + 1) * 4096 + i * 64 + kh * 8 + kw];
        split_pair(v0, v1, hi, lo);
    }
    g_wbh[d] = hi;
    g_wbl[d] = lo;
}

// ---------------------------------------------------------------------------
// Kernel 1: conv-as-GEMM, 3-term bf16 (AhWh + AlWh + AhWl). grid (16,8).
// ---------------------------------------------------------------------------
#define CW_BUF 36864
#define CW_LO  18432
#define CA_H   73728
#define CA_L   108544
#define CONV_SMEM 143360

__global__ void __launch_bounds__(512, 1) k_conv(const float* __restrict__ x) {
    extern __shared__ char sm[];
    uint32_t sb = smem_u32(sm);
    int t = threadIdx.x;
    int L = t & 31, w = t >> 5;
    int pt = blockIdx.x, kh = blockIdx.y;
    int b = pt >> 1, half = pt & 1;
    int wr = w >> 2, wc = w & 3;
    int m0 = wr * 32, n0 = wc * 16;

    auto issueW = [&](int st, int buf) {
        int s = kh * 4 + st;
        const char* srch = (const char*)g_wbh + (size_t)s * 18432;
        const char* srcl = (const char*)g_wbl + (size_t)s * 18432;
        uint32_t dst = sb + buf * CW_BUF;
        for (int i = t; i < 1152; i += 512) {
            cp16(dst + i * 16, srch + i * 16);
            cp16(dst + CW_LO + i * 16, srcl + i * 16);
        }
    };

    float acc[2][2][4];
    #pragma unroll
    for (int i = 0; i < 2; i++)
        #pragma unroll
        for (int j = 0; j < 2; j++)
            #pragma unroll
            for (int k = 0; k < 4; k++) acc[i][j][k] = 0.f;

    issueW(0, 0);
    CP_COMMIT();

    const float* xb = x + (size_t)b * NTOK * 64;
    for (int st = 0; st < 4; st++) {
        if (st < 3) { issueW(st + 1, (st + 1) & 1); CP_COMMIT(); }
        {
            uint32_t* ah = (uint32_t*)(sm + CA_H);
            uint32_t* al = (uint32_t*)(sm + CA_L);
            #pragma unroll
            for (int it = 0; it < 16; it++) {
                int idx = it * 512 + t;
                int m = idx >> 6, pr = idx & 63;
                int kw = pr >> 3, ip = pr & 7;
                int ph = half * 8 + (m >> 4);
                int grow = (ph * 8 + kh) * 128 + (m & 15) * 8 + kw;
                float2 v = *(const float2*)(xb + (size_t)grow * 64 + st * 16 + ip * 2);
                uint32_t hp, lp;
                split_pair(v.x, v.y, hp, lp);
                int wo = m * 68 + kw * 8 + ip;
                ah[wo] = hp; al[wo] = lp;
            }
        }
        if (st < 3) CP_WAIT1(); else CP_WAIT0();
        __syncthreads();

        {
            uint32_t a_lane = (uint32_t)((L & 15) * 272 + (L >> 4) * 16);
            uint32_t b_lane = (uint32_t)(((L & 7) + 8 * ((L >> 3) & 1)) * 144 + (L >> 4) * 16);
            uint32_t wbase = sb + (st & 1) * CW_BUF;
            const int aoffs[3] = {CA_H, CA_L, CA_H};
            const int boffs[3] = {0, 0, CW_LO};
            #pragma unroll
            for (int term = 0; term < 3; term++) {
                uint32_t abase = sb + aoffs[term] + m0 * 272 + a_lane;
                uint32_t bbase = wbase + boffs[term] + n0 * 2 + b_lane;
                #pragma unroll
                for (int kc = 0; kc < 8; kc++) {
                    uint32_t af[2][4];
                    LDSM4(af[0], abase + kc * 32);
                    LDSM4(af[1], abase + 16 * 272 + kc * 32);
                    uint32_t bf[4];
                    LDSM4T(bf, bbase + kc * 16 * 144);
                    MMA_BF16(acc[0][0], af[0], bf[0], bf[1]);
                    MMA_BF16(acc[0][1], af[0], bf[2], bf[3]);
                    MMA_BF16(acc[1][0], af[1], bf[0], bf[1]);
                    MMA_BF16(acc[1][1], af[1], bf[2], bf[3]);
                }
            }
        }
        __syncthreads();
    }

    {
        float* gc = g_cacc + ((size_t)kh * 2048 + pt * 128) * 64;
        #pragma unroll
        for (int i = 0; i < 2; i++)
            #pragma unroll
            for (int h = 0; h < 2; h++) {
                int row = m0 + i * 16 + 8 * h + (L >> 2);
                #pragma unroll
                for (int jj = 0; jj < 2; jj++) {
                    int col = n0 + jj * 8 + 2 * (L & 3);
                    float2 o = make_float2(acc[i][jj][2 * h], acc[i][jj][2 * h + 1]);
                    *(float2*)(gc + row * 64 + col) = o;
                }
            }
    }
}

// ---------------------------------------------------------------------------
// Kernel 1.25: reduce conv partials + bias, LN, KV, AND folded M/V' emission.
// grid (16 ph, 8 b), 512 threads, dynamic smem 51456 B.
// smem floats: co@0(1024) ln@1024(1024) ks@2048(1024: [64 d][16 p])
//              vs@3072(1088: [16 p][68]) Wq@4160(4352: [64][68]) Wp@8512(4352)
// ---------------------------------------------------------------------------
#define LK_CO 0
#define LK_LN 1024
#define LK_KS 2048
#define LK_VS 3072
#define LK_WQ 4160
#define LK_WP 8512
#define LNKV_SMEM 51456

__global__ void __launch_bounds__(512) k_lnkv(
    const float* __restrict__ srb, const float* __restrict__ lng,
    const float* __restrict__ lnb, const float* __restrict__ Wkv,
    const float* __restrict__ Wq,  const float* __restrict__ Wp)
{
    extern __shared__ float dsm[];
    uint32_t sb = smem_u32(dsm);
    int ph = blockIdx.x, b = blockIdx.y;
    int t = threadIdx.x;
    int gbase = (b * 2 + (ph >> 3)) * 128 + (ph & 7) * 16;

    // stage Wq, Wp (padded stride-68 rows) — overlaps phases A-C
    {
        #pragma unroll
        for (int u = 0; u < 2; u++) {
            int i = u * 512 + t;                 // 1024 chunks each
            int r = i >> 4, j = i & 15;
            cp16(sb + (LK_WQ + r * 68 + j * 4) * 4, (const float4*)Wq + i);
            cp16(sb + (LK_WP + r * 68 + j * 4) * 4, (const float4*)Wp + i);
        }
        CP_COMMIT();
    }

    float* co = dsm + LK_CO;
    float* ln = dsm + LK_LN;

    // Phase A: reduce conv partials + bias
    if (t < 256) {
        int pw = t >> 4, c4 = t & 15;
        float4 s = make_float4(0.f, 0.f, 0.f, 0.f);
        #pragma unroll
        for (int kh = 0; kh < 8; kh++) {
            float4 v = *(const float4*)(g_cacc + ((size_t)kh * 2048 + gbase + pw) * 64 + c4 * 4);
            s.x += v.x; s.y += v.y; s.z += v.z; s.w += v.w;
        }
        float4 bb = *(const float4*)(srb + c4 * 4);
        s.x += bb.x; s.y += bb.y; s.z += bb.z; s.w += bb.w;
        *(float4*)(co + pw * 64 + c4 * 4) = s;
    }
    __syncthreads();

    // Phase B: LayerNorm
    int warp = t >> 5, lane = t & 31;
    {
        float v0 = co[warp * 64 + lane];
        float v1 = co[warp * 64 + lane + 32];
        float s = v0 + v1, sq = v0 * v0 + v1 * v1;
        #pragma unroll
        for (int off = 16; off; off >>= 1) {
            s  += __shfl_xor_sync(0xffffffffu, s, off);
            sq += __shfl_xor_sync(0xffffffffu, sq, off);
        }
        float mean = s * (1.f / 64.f);
        float var  = sq * (1.f / 64.f) - mean * mean;
        float rs = rsqrtf(var + 1e-5f);
        ln[warp * 64 + lane]      = (v0 - mean) * rs * lng[lane]      + lnb[lane];
        ln[warp * 64 + lane + 32] = (v1 - mean) * rs * lng[lane + 32] + lnb[lane + 32];
    }
    __syncthreads();

    // Phase C: KV projection -> smem ks [d][16], vs [16][68]
    {
        int c = t & 127, pg = t >> 7;
        float acc[4] = {0.f, 0.f, 0.f, 0.f};
        #pragma unroll 8
        for (int i = 0; i < 64; i++) {
            float wv = Wkv[i * 128 + c];
            #pragma unroll
            for (int m = 0; m < 4; m++)
                acc[m] = fmaf(ln[(pg * 4 + m) * 64 + i], wv, acc[m]);
        }
        float* ks = dsm + LK_KS;
        float* vs = dsm + LK_VS;
        #pragma unroll
        for (int m = 0; m < 4; m++) {
            int pl = pg * 4 + m;
            if (c < 64) ks[c * 16 + pl]        = acc[m];
            else        vs[pl * 68 + (c - 64)] = acc[m];
        }
    }
    CP_WAIT0();
    __syncthreads();

    // Phase D: M pairs. thread -> (c = t>>3, pw = t&7); global pp = ph*8+pw.
    {
        const float* wq = dsm + LK_WQ;
        const float* ks = dsm + LK_KS;
        int c = t >> 3, pw = t & 7;
        float m0 = 0.f, m1 = 0.f;
        #pragma unroll 8
        for (int d = 0; d < 64; d++) {
            float w = wq[c * 68 + d];
            m0 = fmaf(w, ks[d * 16 + 2 * pw],     m0);
            m1 = fmaf(w, ks[d * 16 + 2 * pw + 1], m1);
        }
        g_mh[b * 8192 + c * 128 + ph * 8 + pw] = pack_bf16(m0 * SCALE_L2E, m1 * SCALE_L2E);
    }

    // Phase E: V' pairs. thread -> (pl = t>>5, ee = t&31); Svsum atomics.
    {
        const float* wp = dsm + LK_WP;
        const float* vs = dsm + LK_VS;
        int pl = t >> 5, ee = t & 31;
        float a0 = 0.f, a1 = 0.f;
        #pragma unroll 8
        for (int c = 0; c < 64; c++) {
            float v = vs[pl * 68 + c];
            a0 = fmaf(v, wp[c * 68 + 2 * ee],     a0);
            a1 = fmaf(v, wp[c * 68 + 2 * ee + 1], a1);
        }
        g_vh[b * 8192 + (ph * 16 + pl) * 32 + ee] = pack_bf16(a0, a1);
        atomicAdd(&g_vsum[b * 64 + 2 * ee],     a0);
        atomicAdd(&g_vsum[b * 64 + 2 * ee + 1], a1);
    }
}

// ---------------------------------------------------------------------------
// Kernel 2: persistent HMMA attention (unchanged from R13).
// ---------------------------------------------------------------------------
#define SA1 144
#define SB1 528
#define SE  528
#define SB2 144
#define XS0_ 0
#define A1H_ 65536
#define B1H_ 83968
#define E_   117760
#define B2H_ 185344
#define PSUM_ 222208
#define SMEM_ASK 224256

__global__ void __launch_bounds__(512, 1) k_attn_mma(
    const float* __restrict__ x, const float* __restrict__ bp,
    float* __restrict__ out)
{
    extern __shared__ char sm[];
    uint32_t sb = smem_u32(sm);
    int t = threadIdx.x;
    int L = t & 31, w = t >> 5;
    int bx = blockIdx.x, b = blockIdx.y;
    int wr = w >> 2, wc = w & 3;
    int m0 = wr * 32;
    int tg = t & 127;
    int bar = 8 + wr;

    {
        const char* mh = (const char*)(g_mh + b * 8192);
        for (int i = t; i < 2048; i += 512) {
            int r1 = i >> 5, c1 = i & 31;
            cp16(sb + B1H_ + r1 * SB1 + c1 * 16, mh + i * 16);
        }
        const char* vh = (const char*)(g_vh + b * 8192);
        for (int i = t; i < 2048; i += 512) {
            int r2 = i >> 3, c2 = i & 7;
            cp16(sb + B2H_ + r2 * SB2 + c2 * 16, vh + i * 16);
        }
        const char* xsrc = (const char*)(x + ((size_t)b * NTOK + (size_t)bx * 1024 + m0) * 64);
        for (int i = tg; i < 512; i += 128)
            cp16(sb + XS0_ + m0 * 256 + i * 16, xsrc + i * 16);
        CP_COMMIT();
    }

    for (int j = 0; j < 8; j++) {
        int q0 = bx * 1024 + j * 128;
        if (j < 7) {
            const char* xsrc = (const char*)(x + ((size_t)b * NTOK + q0 + 128 + m0) * 64);
            uint32_t dst = sb + XS0_ + ((j + 1) & 1) * 32768 + m0 * 256;
            for (int i = tg; i < 512; i += 128)
                cp16(dst + i * 16, xsrc + i * 16);
            CP_COMMIT();
            CP_WAIT1();
        } else {
            CP_WAIT0();
        }
        if (j == 0) __syncthreads();
        else        NBAR(bar);

        {
            const float2* xs2 = (const float2*)(sm + XS0_ + (j & 1) * 32768);
            uint32_t* ah = (uint32_t*)(sm + A1H_);
            #pragma unroll
            for (int k = 0; k < 8; k++) {
                int f = tg + k * 128;
                int row = m0 + (f >> 5), cp = f & 31;
                float2 v = xs2[row * 32 + cp];
                ah[row * 36 + cp] = pack_bf16(v.x, v.y);
            }
        }
        NBAR(bar);

        // ================= GEMM1: S = x @ M (1-term bf16) =================
        float acc[2][8][4];
        #pragma unroll
        for (int i = 0; i < 2; i++)
            #pragma unroll
            for (int jj = 0; jj < 8; jj++)
                #pragma unroll
                for (int k = 0; k < 4; k++) acc[i][jj][k] = 0.f;

        {
            int n0 = wc * 64;
            uint32_t a_lane = (uint32_t)((L & 15) * SA1 + (L >> 4) * 16);
            uint32_t b_lane = (uint32_t)(((L & 7) + 8 * ((L >> 3) & 1)) * SB1 + (L >> 4) * 16);
            uint32_t abase = sb + A1H_ + m0 * SA1 + a_lane;
            uint32_t bbase = sb + B1H_ + n0 * 2 + b_lane;
            #pragma unroll
            for (int kc = 0; kc < 4; kc++) {
                uint32_t af[2][4];
                LDSM4(af[0], abase + kc * 32);
                LDSM4(af[1], abase + 16 * SA1 + kc * 32);
                uint32_t bf[4][4];
                #pragma unroll
                for (int jj = 0; jj < 4; jj++)
                    LDSM4T(bf[jj], bbase + kc * 16 * SB1 + jj * 32);
                #pragma unroll
                for (int i = 0; i < 2; i++)
                    #pragma unroll
                    for (int jj = 0; jj < 4; jj++) {
                        MMA_BF16(acc[i][2 * jj],     af[i], bf[jj][0], bf[jj][1]);
                        MMA_BF16(acc[i][2 * jj + 1], af[i], bf[jj][2], bf[jj][3]);
                    }
            }
        }

        // ============ E = 2^s ; row sums ; store (E-1) bf16 ============
        {
            int n0 = wc * 64;
            float rs[4] = {0.f, 0.f, 0.f, 0.f};
            #pragma unroll
            for (int i = 0; i < 2; i++) {
                int r0 = m0 + i * 16 + (L >> 2);
                #pragma unroll
                for (int jj = 0; jj < 8; jj++) {
                    float e0 = ex2(acc[i][jj][0]);
                    float e1 = ex2(acc[i][jj][1]);
                    float e2 = ex2(acc[i][jj][2]);
                    float e3 = ex2(acc[i][jj][3]);
                    rs[i * 2]     += e0 + e1;
                    rs[i * 2 + 1] += e2 + e3;
                    int cb = (n0 + jj * 8 + 2 * (L & 3)) * 2;
                    *(uint32_t*)(sm + E_ + r0 * SE + cb)       = pack_bf16(e0 - 1.f, e1 - 1.f);
                    *(uint32_t*)(sm + E_ + (r0 + 8) * SE + cb) = pack_bf16(e2 - 1.f, e3 - 1.f);
                }
            }
            #pragma unroll
            for (int k = 0; k < 4; k++) {
                rs[k] += __shfl_xor_sync(0xffffffffu, rs[k], 1);
                rs[k] += __shfl_xor_sync(0xffffffffu, rs[k], 2);
            }
            if ((L & 3) == 0) {
                float* ps = (float*)(sm + PSUM_);
                #pragma unroll
                for (int i = 0; i < 2; i++)
                    #pragma unroll
                    for (int h = 0; h < 2; h++) {
                        int row = m0 + i * 16 + 8 * h + (L >> 2);
                        ps[row * 4 + wc] = rs[i * 2 + h];
                    }
            }
        }
        NBAR(bar);

        // ========= GEMM2: D2 = (E-1) @ V'hi =========
        float acc2[2][2][4];
        #pragma unroll
        for (int i = 0; i < 2; i++)
            #pragma unroll
            for (int jj = 0; jj < 2; jj++)
                #pragma unroll
                for (int k = 0; k < 4; k++) acc2[i][jj][k] = 0.f;

        {
            int n2 = wc * 16;
            uint32_t a_lane = (uint32_t)((L & 15) * SE + (L >> 4) * 16);
            uint32_t b_lane = (uint32_t)(((L & 7) + 8 * ((L >> 3) & 1)) * SB2 + (L >> 4) * 16);
            uint32_t abase = sb + E_ + m0 * SE + a_lane;
            uint32_t bbase = sb + B2H_ + n2 * 2 + b_lane;
            #pragma unroll
            for (int kc = 0; kc < 16; kc++) {
                uint32_t af[2][4];
                LDSM4(af[0], abase + kc * 32);
                LDSM4(af[1], abase + 16 * SE + kc * 32);
                uint32_t bf[4];
                LDSM4T(bf, bbase + kc * 16 * SB2);
                MMA_BF16(acc2[0][0], af[0], bf[0], bf[1]);
                MMA_BF16(acc2[0][1], af[0], bf[2], bf[3]);
                MMA_BF16(acc2[1][0], af[1], bf[0], bf[1]);
                MMA_BF16(acc2[1][1], af[1], bf[2], bf[3]);
            }
        }

        // ===== epilogue: out = (D2 + Svsum)/rowsum + bias =====
        {
            int n2 = wc * 16;
            const float* ps = (const float*)(sm + PSUM_);
            const float* sv = g_vsum + b * 64;
            #pragma unroll
            for (int i = 0; i < 2; i++)
                #pragma unroll
                for (int h = 0; h < 2; h++) {
                    int row = m0 + i * 16 + 8 * h + (L >> 2);
                    float4 p4 = *(const float4*)(ps + row * 4);
                    float inv = 1.f / (p4.x + p4.y + p4.z + p4.w);
                    float* og = out + ((size_t)(b * NTOK) + q0 + row) * 64;
                    #pragma unroll
                    for (int jj = 0; jj < 2; jj++) {
                        int c = n2 + jj * 8 + 2 * (L & 3);
                        float2 bb = *(const float2*)(bp + c);
                        float2 ss = *(const float2*)(sv + c);
                        float2 o;
                        o.x = (acc2[i][jj][2 * h]     + ss.x) * inv + bb.x;
                        o.y = (acc2[i][jj][2 * h + 1] + ss.y) * inv + bb.y;
                        *(float2*)(og + c) = o;
                    }
                }
        }
    }
}

// ---------------------------------------------------------------------------
extern "C" void kernel_launch(void* const* d_in, const int* in_sizes, int n_in,
                              void* d_out, int out_size) {
    const float* x   = (const float*)d_in[0];
    const float* Wq  = (const float*)d_in[1];
    const float* Wkv = (const float*)d_in[2];
    const float* Wp  = (const float*)d_in[3];
    const float* bp  = (const float*)d_in[4];
    const float* srw = (const float*)d_in[5];
    const float* srb = (const float*)d_in[6];
    const float* lng = (const float*)d_in[7];
    const float* lnb = (const float*)d_in[8];
    float* out = (float*)d_out;

    cudaFuncSetAttribute(k_conv, cudaFuncAttributeMaxDynamicSharedMemorySize, CONV_SMEM);
    cudaFuncSetAttribute(k_lnkv, cudaFuncAttributeMaxDynamicSharedMemorySize, LNKV_SMEM);
    cudaFuncSetAttribute(k_attn_mma, cudaFuncAttributeMaxDynamicSharedMemorySize, SMEM_ASK);

    k_transpose_w<<<288, 512>>>(srw);
    k_conv<<<dim3(16, 8), 512, CONV_SMEM>>>(x);
    k_lnkv<<<dim3(16, 8), 512, LNKV_SMEM>>>(srb, lng, lnb, Wkv, Wq, Wp);
    k_attn_mma<<<dim3(16, 8), 512, SMEM_ASK>>>(x, bp, out);
}

// round 15
// speedup vs baseline: 4.8903x; 1.0421x over previous
#include <cuda_runtime.h>
#include <cuda_bf16.h>
#include <cstdint>

#define BATCH 8
#define NTOK  16384
#define NK    256
#define SCALE 0.125f

// ---------------- scratch (allocation-free rule) ----------------
__device__ uint32_t g_wbh[32 * 4608];        // conv W bf16-hi, padded slabs [s][128][36 words]
__device__ uint32_t g_wbl[32 * 4608];        // conv W bf16-lo
__device__ float    g_cacc[8 * 2048 * 64];   // conv partials per kh
__device__ uint32_t g_mh[BATCH * 8192];      // M bf16 pairs (pre-scaled by SCALE)
__device__ uint32_t g_vh[BATCH * 8192];      // V' bf16 pairs: [p][e/2]
__device__ float    g_vsum[BATCH * 64];      // fp32 column sums of V'

// ---------------- helpers ----------------
__device__ __forceinline__ uint32_t smem_u32(const void* p) {
    uint32_t a;
    asm("{ .reg .u64 t; cvta.to.shared.u64 t, %1; cvt.u32.u64 %0, t; }" : "=r"(a) : "l"(p));
    return a;
}
__device__ __forceinline__ uint32_t pack_bf16(float a, float b) {
    uint32_t r;   // r = {hi: bf16(b), lo: bf16(a)}
    asm("cvt.rn.bf16x2.f32 %0, %1, %2;" : "=r"(r) : "f"(b), "f"(a));
    return r;
}
__device__ __forceinline__ void split_pair(float a, float b, uint32_t& hp, uint32_t& lp) {
    uint32_t h;
    asm("cvt.rn.bf16x2.f32 %0, %1, %2;" : "=r"(h) : "f"(b), "f"(a));
    float ah = __uint_as_float(h << 16);
    float bh = __uint_as_float(h & 0xffff0000u);
    uint32_t l;
    float la = a - ah, lb = b - bh;
    asm("cvt.rn.bf16x2.f32 %0, %1, %2;" : "=r"(l) : "f"(lb), "f"(la));
    hp = h; lp = l;
}
// expm1 via 4-term Taylor (|s| << 1): e^s - 1 = s(1 + s(1/2 + s(1/6 + s/24)))
__device__ __forceinline__ float em1(float s) {
    float t = fmaf(s, 0.041666668f, 0.16666667f);
    t = fmaf(s, t, 0.5f);
    t = fmaf(s, t, 1.0f);
    return s * t;
}

#define LDSM4(r, addr) \
    asm volatile("ldmatrix.sync.aligned.m8n8.x4.shared.b16 {%0,%1,%2,%3}, [%4];" \
        : "=r"((r)[0]), "=r"((r)[1]), "=r"((r)[2]), "=r"((r)[3]) : "r"(addr))
#define LDSM4T(r, addr) \
    asm volatile("ldmatrix.sync.aligned.m8n8.x4.trans.shared.b16 {%0,%1,%2,%3}, [%4];" \
        : "=r"((r)[0]), "=r"((r)[1]), "=r"((r)[2]), "=r"((r)[3]) : "r"(addr))
#define MMA_BF16(d, a, b0, b1) \
    asm volatile("mma.sync.aligned.m16n8k16.row.col.f32.bf16.bf16.f32 " \
        "{%0,%1,%2,%3}, {%4,%5,%6,%7}, {%8,%9}, {%0,%1,%2,%3};" \
        : "+f"((d)[0]), "+f"((d)[1]), "+f"((d)[2]), "+f"((d)[3]) \
        : "r"((a)[0]), "r"((a)[1]), "r"((a)[2]), "r"((a)[3]), "r"(b0), "r"(b1))

__device__ __forceinline__ void cp16(uint32_t s, const void* g) {
    asm volatile("cp.async.cg.shared.global [%0], [%1], 16;" :: "r"(s), "l"(g));
}
#define CP_COMMIT() asm volatile("cp.async.commit_group;" ::: "memory")
#define CP_WAIT1()  asm volatile("cp.async.wait_group 1;" ::: "memory")
#define CP_WAIT0()  asm volatile("cp.async.wait_group 0;" ::: "memory")
#define NBAR(id)    asm volatile("bar.sync %0, 128;" :: "r"(id) : "memory")

// ---------------------------------------------------------------------------
// Kernel 0: conv weights -> bf16 hi/lo padded slabs; zero g_vsum.
// ---------------------------------------------------------------------------
__global__ void k_transpose_w(const float* __restrict__ srw) {
    int d = blockIdx.x * 512 + threadIdx.x;    // 288*512 = 147456 = 32*4608
    if (d < BATCH * 64) g_vsum[d] = 0.f;
    int s = d / 4608;
    int r = d - s * 4608;
    int k = r / 36;
    int ow = r - k * 36;
    uint32_t hi = 0, lo = 0;
    if (ow < 32) {
        int kh = s >> 2, ic = s & 3;
        int kw = k >> 4, ii = k & 15;
        int i = ic * 16 + ii;
        float v0 = srw[(2 * ow) * 4096 + i * 64 + kh * 8 + kw];
        float v1 = srw[(2 * ow + 1) * 4096 + i * 64 + kh * 8 + kw];
        split_pair(v0, v1, hi, lo);
    }
    g_wbh[d] = hi;
    g_wbl[d] = lo;
}

// ---------------------------------------------------------------------------
// Kernel 1: conv-as-GEMM, 3-term bf16 (AhWh + AlWh + AhWl). grid (16,8).
// ---------------------------------------------------------------------------
#define CW_BUF 36864
#define CW_LO  18432
#define CA_H   73728
#define CA_L   108544
#define CONV_SMEM 143360

__global__ void __launch_bounds__(512, 1) k_conv(const float* __restrict__ x) {
    extern __shared__ char sm[];
    uint32_t sb = smem_u32(sm);
    int t = threadIdx.x;
    int L = t & 31, w = t >> 5;
    int pt = blockIdx.x, kh = blockIdx.y;
    int b = pt >> 1, half = pt & 1;
    int wr = w >> 2, wc = w & 3;
    int m0 = wr * 32, n0 = wc * 16;

    auto issueW = [&](int st, int buf) {
        int s = kh * 4 + st;
        const char* srch = (const char*)g_wbh + (size_t)s * 18432;
        const char* srcl = (const char*)g_wbl + (size_t)s * 18432;
        uint32_t dst = sb + buf * CW_BUF;
        for (int i = t; i < 1152; i += 512) {
            cp16(dst + i * 16, srch + i * 16);
            cp16(dst + CW_LO + i * 16, srcl + i * 16);
        }
    };

    float acc[2][2][4];
    #pragma unroll
    for (int i = 0; i < 2; i++)
        #pragma unroll
        for (int j = 0; j < 2; j++)
            #pragma unroll
            for (int k = 0; k < 4; k++) acc[i][j][k] = 0.f;

    issueW(0, 0);
    CP_COMMIT();

    const float* xb = x + (size_t)b * NTOK * 64;
    for (int st = 0; st < 4; st++) {
        if (st < 3) { issueW(st + 1, (st + 1) & 1); CP_COMMIT(); }
        // ---- convert A: float4 LDG, paired stores ----
        {
            uint32_t* ah = (uint32_t*)(sm + CA_H);
            uint32_t* al = (uint32_t*)(sm + CA_L);
            #pragma unroll
            for (int it = 0; it < 8; it++) {
                int idx = it * 512 + t;          // 4096 float4-cells
                int m = idx >> 5, pr4 = idx & 31;
                int kw = pr4 >> 2, ip2 = pr4 & 3;
                int ph = half * 8 + (m >> 4);
                int grow = (ph * 8 + kh) * 128 + (m & 15) * 8 + kw;
                float4 v = *(const float4*)(xb + (size_t)grow * 64 + st * 16 + ip2 * 4);
                uint32_t h0, l0, h1, l1;
                split_pair(v.x, v.y, h0, l0);
                split_pair(v.z, v.w, h1, l1);
                int wo = m * 68 + kw * 8 + ip2 * 2;
                *(uint2*)(ah + wo) = make_uint2(h0, h1);
                *(uint2*)(al + wo) = make_uint2(l0, l1);
            }
        }
        if (st < 3) CP_WAIT1(); else CP_WAIT0();
        __syncthreads();

        {
            uint32_t a_lane = (uint32_t)((L & 15) * 272 + (L >> 4) * 16);
            uint32_t b_lane = (uint32_t)(((L & 7) + 8 * ((L >> 3) & 1)) * 144 + (L >> 4) * 16);
            uint32_t wbase = sb + (st & 1) * CW_BUF;
            const int aoffs[3] = {CA_H, CA_L, CA_H};
            const int boffs[3] = {0, 0, CW_LO};
            #pragma unroll
            for (int term = 0; term < 3; term++) {
                uint32_t abase = sb + aoffs[term] + m0 * 272 + a_lane;
                uint32_t bbase = wbase + boffs[term] + n0 * 2 + b_lane;
                #pragma unroll
                for (int kc = 0; kc < 8; kc++) {
                    uint32_t af[2][4];
                    LDSM4(af[0], abase + kc * 32);
                    LDSM4(af[1], abase + 16 * 272 + kc * 32);
                    uint32_t bf[4];
                    LDSM4T(bf, bbase + kc * 16 * 144);
                    MMA_BF16(acc[0][0], af[0], bf[0], bf[1]);
                    MMA_BF16(acc[0][1], af[0], bf[2], bf[3]);
                    MMA_BF16(acc[1][0], af[1], bf[0], bf[1]);
                    MMA_BF16(acc[1][1], af[1], bf[2], bf[3]);
                }
            }
        }
        __syncthreads();
    }

    {
        float* gc = g_cacc + ((size_t)kh * 2048 + pt * 128) * 64;
        #pragma unroll
        for (int i = 0; i < 2; i++)
            #pragma unroll
            for (int h = 0; h < 2; h++) {
                int row = m0 + i * 16 + 8 * h + (L >> 2);
                #pragma unroll
                for (int jj = 0; jj < 2; jj++) {
                    int col = n0 + jj * 8 + 2 * (L & 3);
                    float2 o = make_float2(acc[i][jj][2 * h], acc[i][jj][2 * h + 1]);
                    *(float2*)(gc + row * 64 + col) = o;
                }
            }
    }
}

// ---------------------------------------------------------------------------
// Kernel 1.25: reduce conv partials + bias, LN, KV, folded M/V' emission.
// grid (16 ph, 8 b), 512 threads, dynamic smem 51456 B.
// ---------------------------------------------------------------------------
#define LK_CO 0
#define LK_LN 1024
#define LK_KS 2048
#define LK_VS 3072
#define LK_WQ 4160
#define LK_WP 8512
#define LNKV_SMEM 51456

__global__ void __launch_bounds__(512) k_lnkv(
    const float* __restrict__ srb, const float* __restrict__ lng,
    const float* __restrict__ lnb, const float* __restrict__ Wkv,
    const float* __restrict__ Wq,  const float* __restrict__ Wp)
{
    extern __shared__ float dsm[];
    uint32_t sb = smem_u32(dsm);
    int ph = blockIdx.x, b = blockIdx.y;
    int t = threadIdx.x;
    int gbase = (b * 2 + (ph >> 3)) * 128 + (ph & 7) * 16;

    {
        #pragma unroll
        for (int u = 0; u < 2; u++) {
            int i = u * 512 + t;
            int r = i >> 4, j = i & 15;
            cp16(sb + (LK_WQ + r * 68 + j * 4) * 4, (const float4*)Wq + i);
            cp16(sb + (LK_WP + r * 68 + j * 4) * 4, (const float4*)Wp + i);
        }
        CP_COMMIT();
    }

    float* co = dsm + LK_CO;
    float* ln = dsm + LK_LN;

    if (t < 256) {
        int pw = t >> 4, c4 = t & 15;
        float4 s = make_float4(0.f, 0.f, 0.f, 0.f);
        #pragma unroll
        for (int kh = 0; kh < 8; kh++) {
            float4 v = *(const float4*)(g_cacc + ((size_t)kh * 2048 + gbase + pw) * 64 + c4 * 4);
            s.x += v.x; s.y += v.y; s.z += v.z; s.w += v.w;
        }
        float4 bb = *(const float4*)(srb + c4 * 4);
        s.x += bb.x; s.y += bb.y; s.z += bb.z; s.w += bb.w;
        *(float4*)(co + pw * 64 + c4 * 4) = s;
    }
    __syncthreads();

    int warp = t >> 5, lane = t & 31;
    {
        float v0 = co[warp * 64 + lane];
        float v1 = co[warp * 64 + lane + 32];
        float s = v0 + v1, sq = v0 * v0 + v1 * v1;
        #pragma unroll
        for (int off = 16; off; off >>= 1) {
            s  += __shfl_xor_sync(0xffffffffu, s, off);
            sq += __shfl_xor_sync(0xffffffffu, sq, off);
        }
        float mean = s * (1.f / 64.f);
        float var  = sq * (1.f / 64.f) - mean * mean;
        float rs = rsqrtf(var + 1e-5f);
        ln[warp * 64 + lane]      = (v0 - mean) * rs * lng[lane]      + lnb[lane];
        ln[warp * 64 + lane + 32] = (v1 - mean) * rs * lng[lane + 32] + lnb[lane + 32];
    }
    __syncthreads();

    {
        int c = t & 127, pg = t >> 7;
        float acc[4] = {0.f, 0.f, 0.f, 0.f};
        #pragma unroll 8
        for (int i = 0; i < 64; i++) {
            float wv = Wkv[i * 128 + c];
            #pragma unroll
            for (int m = 0; m < 4; m++)
                acc[m] = fmaf(ln[(pg * 4 + m) * 64 + i], wv, acc[m]);
        }
        float* ks = dsm + LK_KS;
        float* vs = dsm + LK_VS;
        #pragma unroll
        for (int m = 0; m < 4; m++) {
            int pl = pg * 4 + m;
            if (c < 64) ks[c * 16 + pl]        = acc[m];
            else        vs[pl * 68 + (c - 64)] = acc[m];
        }
    }
    CP_WAIT0();
    __syncthreads();

    // Phase D: M pairs (scaled by SCALE; attn computes e^s via poly)
    {
        const float* wq = dsm + LK_WQ;
        const float* ks = dsm + LK_KS;
        int c = t >> 3, pw = t & 7;
        float m0 = 0.f, m1 = 0.f;
        #pragma unroll 8
        for (int d = 0; d < 64; d++) {
            float w = wq[c * 68 + d];
            m0 = fmaf(w, ks[d * 16 + 2 * pw],     m0);
            m1 = fmaf(w, ks[d * 16 + 2 * pw + 1], m1);
        }
        g_mh[b * 8192 + c * 128 + ph * 8 + pw] = pack_bf16(m0 * SCALE, m1 * SCALE);
    }

    // Phase E: V' pairs + Svsum atomics
    {
        const float* wp = dsm + LK_WP;
        const float* vs = dsm + LK_VS;
        int pl = t >> 5, ee = t & 31;
        float a0 = 0.f, a1 = 0.f;
        #pragma unroll 8
        for (int c = 0; c < 64; c++) {
            float v = vs[pl * 68 + c];
            a0 = fmaf(v, wp[c * 68 + 2 * ee],     a0);
            a1 = fmaf(v, wp[c * 68 + 2 * ee + 1], a1);
        }
        g_vh[b * 8192 + (ph * 16 + pl) * 32 + ee] = pack_bf16(a0, a1);
        atomicAdd(&g_vsum[b * 64 + 2 * ee],     a0);
        atomicAdd(&g_vsum[b * 64 + 2 * ee + 1], a1);
    }
}

// ---------------------------------------------------------------------------
// Kernel 2: persistent HMMA attention, poly expm1, float4 convert.
// ---------------------------------------------------------------------------
#define SA1 144
#define SB1 528
#define SE  528
#define SB2 144
#define XS0_ 0
#define A1H_ 65536
#define B1H_ 83968
#define E_   117760
#define B2H_ 185344
#define PSUM_ 222208
#define SMEM_ASK 224256

__global__ void __launch_bounds__(512, 1) k_attn_mma(
    const float* __restrict__ x, const float* __restrict__ bp,
    float* __restrict__ out)
{
    extern __shared__ char sm[];
    uint32_t sb = smem_u32(sm);
    int t = threadIdx.x;
    int L = t & 31, w = t >> 5;
    int bx = blockIdx.x, b = blockIdx.y;
    int wr = w >> 2, wc = w & 3;
    int m0 = wr * 32;
    int tg = t & 127;
    int bar = 8 + wr;

    {
        const char* mh = (const char*)(g_mh + b * 8192);
        for (int i = t; i < 2048; i += 512) {
            int r1 = i >> 5, c1 = i & 31;
            cp16(sb + B1H_ + r1 * SB1 + c1 * 16, mh + i * 16);
        }
        const char* vh = (const char*)(g_vh + b * 8192);
        for (int i = t; i < 2048; i += 512) {
            int r2 = i >> 3, c2 = i & 7;
            cp16(sb + B2H_ + r2 * SB2 + c2 * 16, vh + i * 16);
        }
        const char* xsrc = (const char*)(x + ((size_t)b * NTOK + (size_t)bx * 1024 + m0) * 64);
        for (int i = tg; i < 512; i += 128)
            cp16(sb + XS0_ + m0 * 256 + i * 16, xsrc + i * 16);
        CP_COMMIT();
    }

    for (int j = 0; j < 8; j++) {
        int q0 = bx * 1024 + j * 128;
        if (j < 7) {
            const char* xsrc = (const char*)(x + ((size_t)b * NTOK + q0 + 128 + m0) * 64);
            uint32_t dst = sb + XS0_ + ((j + 1) & 1) * 32768 + m0 * 256;
            for (int i = tg; i < 512; i += 128)
                cp16(dst + i * 16, xsrc + i * 16);
            CP_COMMIT();
            CP_WAIT1();
        } else {
            CP_WAIT0();
        }
        if (j == 0) __syncthreads();
        else        NBAR(bar);

        // ---- convert own 32 x rows -> A1h bf16 (float4 path) ----
        {
            const float4* xs4 = (const float4*)(sm + XS0_ + (j & 1) * 32768);
            uint32_t* ah = (uint32_t*)(sm + A1H_);
            #pragma unroll
            for (int k = 0; k < 4; k++) {
                int g = tg + k * 128;            // 512 float4-cells for this group
                int row = m0 + (g >> 4), cp2 = g & 15;
                float4 v = xs4[row * 16 + cp2];
                *(uint2*)(ah + row * 36 + cp2 * 2) =
                    make_uint2(pack_bf16(v.x, v.y), pack_bf16(v.z, v.w));
            }
        }
        NBAR(bar);

        // ================= GEMM1: S = x @ M (1-term bf16) =================
        float acc[2][8][4];
        #pragma unroll
        for (int i = 0; i < 2; i++)
            #pragma unroll
            for (int jj = 0; jj < 8; jj++)
                #pragma unroll
                for (int k = 0; k < 4; k++) acc[i][jj][k] = 0.f;

        {
            int n0 = wc * 64;
            uint32_t a_lane = (uint32_t)((L & 15) * SA1 + (L >> 4) * 16);
            uint32_t b_lane = (uint32_t)(((L & 7) + 8 * ((L >> 3) & 1)) * SB1 + (L >> 4) * 16);
            uint32_t abase = sb + A1H_ + m0 * SA1 + a_lane;
            uint32_t bbase = sb + B1H_ + n0 * 2 + b_lane;
            #pragma unroll
            for (int kc = 0; kc < 4; kc++) {
                uint32_t af[2][4];
                LDSM4(af[0], abase + kc * 32);
                LDSM4(af[1], abase + 16 * SA1 + kc * 32);
                uint32_t bf[4][4];
                #pragma unroll
                for (int jj = 0; jj < 4; jj++)
                    LDSM4T(bf[jj], bbase + kc * 16 * SB1 + jj * 32);
                #pragma unroll
                for (int i = 0; i < 2; i++)
                    #pragma unroll
                    for (int jj = 0; jj < 4; jj++) {
                        MMA_BF16(acc[i][2 * jj],     af[i], bf[jj][0], bf[jj][1]);
                        MMA_BF16(acc[i][2 * jj + 1], af[i], bf[jj][2], bf[jj][3]);
                    }
            }
        }

        // ====== E-1 via poly ; partial row sums of (E-1) ; store bf16 ======
        {
            int n0 = wc * 64;
            float rs[4] = {0.f, 0.f, 0.f, 0.f};
            #pragma unroll
            for (int i = 0; i < 2; i++) {
                int r0 = m0 + i * 16 + (L >> 2);
                #pragma unroll
                for (int jj = 0; jj < 8; jj++) {
                    float e0 = em1(acc[i][jj][0]);
                    float e1 = em1(acc[i][jj][1]);
                    float e2 = em1(acc[i][jj][2]);
                    float e3 = em1(acc[i][jj][3]);
                    rs[i * 2]     += e0 + e1;
                    rs[i * 2 + 1] += e2 + e3;
                    int cb = (n0 + jj * 8 + 2 * (L & 3)) * 2;
                    *(uint32_t*)(sm + E_ + r0 * SE + cb)       = pack_bf16(e0, e1);
                    *(uint32_t*)(sm + E_ + (r0 + 8) * SE + cb) = pack_bf16(e2, e3);
                }
            }
            #pragma unroll
            for (int k = 0; k < 4; k++) {
                rs[k] += __shfl_xor_sync(0xffffffffu, rs[k], 1);
                rs[k] += __shfl_xor_sync(0xffffffffu, rs[k], 2);
            }
            if ((L & 3) == 0) {
                float* ps = (float*)(sm + PSUM_);
                #pragma unroll
                for (int i = 0; i < 2; i++)
                    #pragma unroll
                    for (int h = 0; h < 2; h++) {
                        int row = m0 + i * 16 + 8 * h + (L >> 2);
                        ps[row * 4 + wc] = rs[i * 2 + h];
                    }
            }
        }
        NBAR(bar);

        // ========= GEMM2: D2 = (E-1) @ V'hi =========
        float acc2[2][2][4];
        #pragma unroll
        for (int i = 0; i < 2; i++)
            #pragma unroll
            for (int jj = 0; jj < 2; jj++)
                #pragma unroll
                for (int k = 0; k < 4; k++) acc2[i][jj][k] = 0.f;

        {
            int n2 = wc * 16;
            uint32_t a_lane = (uint32_t)((L & 15) * SE + (L >> 4) * 16);
            uint32_t b_lane = (uint32_t)(((L & 7) + 8 * ((L >> 3) & 1)) * SB2 + (L >> 4) * 16);
            uint32_t abase = sb + E_ + m0 * SE + a_lane;
            uint32_t bbase = sb + B2H_ + n2 * 2 + b_lane;
            #pragma unroll
            for (int kc = 0; kc < 16; kc++) {
                uint32_t af[2][4];
                LDSM4(af[0], abase + kc * 32);
                LDSM4(af[1], abase + 16 * SE + kc * 32);
                uint32_t bf[4];
                LDSM4T(bf, bbase + kc * 16 * SB2);
                MMA_BF16(acc2[0][0], af[0], bf[0], bf[1]);
                MMA_BF16(acc2[0][1], af[0], bf[2], bf[3]);
                MMA_BF16(acc2[1][0], af[1], bf[0], bf[1]);
                MMA_BF16(acc2[1][1], af[1], bf[2], bf[3]);
            }
        }

        // ===== epilogue: out = (D2 + Svsum)/(256 + rowsum(E-1)) + bias =====
        {
            int n2 = wc * 16;
            const float* ps = (const float*)(sm + PSUM_);
            const float* sv = g_vsum + b * 64;
            #pragma unroll
            for (int i = 0; i < 2; i++)
                #pragma unroll
                for (int h = 0; h < 2; h++) {
                    int row = m0 + i * 16 + 8 * h + (L >> 2);
                    float4 p4 = *(const float4*)(ps + row * 4);
                    float inv = 1.f / (256.f + p4.x + p4.y + p4.z + p4.w);
                    float* og = out + ((size_t)(b * NTOK) + q0 + row) * 64;
                    #pragma unroll
                    for (int jj = 0; jj < 2; jj++) {
                        int c = n2 + jj * 8 + 2 * (L & 3);
                        float2 bb = *(const float2*)(bp + c);
                        float2 ss = *(const float2*)(sv + c);
                        float2 o;
                        o.x = (acc2[i][jj][2 * h]     + ss.x) * inv + bb.x;
                        o.y = (acc2[i][jj][2 * h + 1] + ss.y) * inv + bb.y;
                        *(float2*)(og + c) = o;
                    }
                }
        }
    }
}

// ---------------------------------------------------------------------------
extern "C" void kernel_launch(void* const* d_in, const int* in_sizes, int n_in,
                              void* d_out, int out_size) {
    const float* x   = (const float*)d_in[0];
    const float* Wq  = (const float*)d_in[1];
    const float* Wkv = (const float*)d_in[2];
    const float* Wp  = (const float*)d_in[3];
    const float* bp  = (const float*)d_in[4];
    const float* srw = (const float*)d_in[5];
    const float* srb = (const float*)d_in[6];
    const float* lng = (const float*)d_in[7];
    const float* lnb = (const float*)d_in[8];
    float* out = (float*)d_out;

    cudaFuncSetAttribute(k_conv, cudaFuncAttributeMaxDynamicSharedMemorySize, CONV_SMEM);
    cudaFuncSetAttribute(k_lnkv, cudaFuncAttributeMaxDynamicSharedMemorySize, LNKV_SMEM);
    cudaFuncSetAttribute(k_attn_mma, cudaFuncAttributeMaxDynamicSharedMemorySize, SMEM_ASK);

    k_transpose_w<<<288, 512>>>(srw);
    k_conv<<<dim3(16, 8), 512, CONV_SMEM>>>(x);
    k_lnkv<<<dim3(16, 8), 512, LNKV_SMEM>>>(srb, lng, lnb, Wkv, Wq, Wp);
    k_attn_mma<<<dim3(16, 8), 512, SMEM_ASK>>>(x, bp, out);
}